// round 4
// baseline (speedup 1.0000x reference)
#include <cuda_runtime.h>
#include <math.h>

// Problem constants
#define Bsz 32
#define Lsz 4096
#define Hsz 256
#define H2sz 512
#define NLs 4
#define N2s 32
#define Tc  128   // chunk length
#define Cc  32    // chunks per sequence (Tc*Cc == Lsz)

// ---------------------------------------------------------------------------
// Scratch (device globals; no runtime allocation allowed)
// ---------------------------------------------------------------------------
__device__ float  g_u [(size_t)Bsz*Hsz*Lsz];   // current hidden state h (B,H,L)
__device__ float  g_yg[(size_t)Bsz*Hsz*Lsz];   // post-gelu S4D output
__device__ float  g_z [(size_t)Bsz*Hsz*Lsz];   // GLU output + residual (pre-LN)
__device__ float2 g_Q [(size_t)NLs*Hsz*Tc*N2s]; // Q[il][h][j][n] = r^(T-1-j)
__device__ float2 g_E [(size_t)NLs*Hsz*Tc*N2s]; // E[il][h][j][n] = (2Re(Ck r^{j+1}), -2Im(Ck r^{j+1}))
__device__ float  g_kc[(size_t)NLs*Hsz*Tc];     // conv kernel k[il][h][d] = 2Re(sum_n Ck r^d)
__device__ float2 g_rT[(size_t)NLs*Hsz*N2s];    // r^T per mode

// ---------------------------------------------------------------------------
// Precompute tables per (layer, h).  grid = NL*H blocks, 128 threads.
// ---------------------------------------------------------------------------
__global__ void precompute_kernel(const float* __restrict__ log_dt,
                                  const float* __restrict__ log_A_real,
                                  const float* __restrict__ A_imag,
                                  const float* __restrict__ C_re,
                                  const float* __restrict__ C_im)
{
    int ilh = blockIdx.x;
    int il = ilh >> 8;
    int h  = ilh & 255;
    __shared__ float s_dre[N2s], s_dim[N2s], s_Ckr[N2s], s_Cki[N2s];

    int tid = threadIdx.x;
    if (tid < N2s) {
        int n = tid;
        float dt = expf(log_dt[il*Hsz + h]);
        size_t idx = ((size_t)il*Hsz + h)*N2s + n;
        float Are = -expf(log_A_real[idx]);
        float Aim = A_imag[idx];
        float dre = Are * dt, dim = Aim * dt;
        float er = expf(dre);
        float sr, cr0; sincosf(dim, &sr, &cr0);
        float rr = er * cr0, ri = er * sr;
        // Ck = C * (r - 1) / A
        float nr = rr - 1.0f, ni = ri;
        float den = Are*Are + Aim*Aim;
        float qr = (nr*Are + ni*Aim)/den;
        float qi = (ni*Are - nr*Aim)/den;
        float cre = C_re[idx], cim = C_im[idx];
        float Ckr = cre*qr - cim*qi;
        float Cki = cre*qi + cim*qr;
        s_dre[n] = dre; s_dim[n] = dim; s_Ckr[n] = Ckr; s_Cki[n] = Cki;
        // r^T
        float eT = expf(dre * (float)Tc);
        float sT, cT; sincosf(dim * (float)Tc, &sT, &cT);
        g_rT[((size_t)il*Hsz + h)*N2s + n] = make_float2(eT*cT, eT*sT);
    }
    __syncthreads();

    int j = tid;  // 0..127
    float2* Qh = g_Q + (((size_t)il*Hsz + h)*Tc + j)*N2s;
    float2* Eh = g_E + (((size_t)il*Hsz + h)*Tc + j)*N2s;
    float ksum = 0.f;
    #pragma unroll 4
    for (int n = 0; n < N2s; n++) {
        float dre = s_dre[n], dim = s_dim[n];
        float Ckr = s_Ckr[n], Cki = s_Cki[n];
        // Q[j][n] = exp(dtA * (T-1-j))
        float m1 = (float)(Tc - 1 - j);
        float e1 = expf(dre*m1);
        float s1, c1; sincosf(dim*m1, &s1, &c1);
        Qh[n] = make_float2(e1*c1, e1*s1);
        // w = Ck * exp(dtA*(j+1))
        float m2 = (float)(j + 1);
        float e2 = expf(dre*m2);
        float s2, c2; sincosf(dim*m2, &s2, &c2);
        float pr = e2*c2, pi = e2*s2;
        float wr = Ckr*pr - Cki*pi;
        float wi = Ckr*pi + Cki*pr;
        Eh[n] = make_float2(2.f*wr, -2.f*wi);
        // kconv[j] = 2*Re(Ck * exp(dtA*j))
        float m3 = (float)j;
        float e3 = expf(dre*m3);
        float s3, c3; sincosf(dim*m3, &s3, &c3);
        ksum += Ckr*(e3*c3) - Cki*(e3*s3);
    }
    g_kc[((size_t)il*Hsz + h)*Tc + j] = 2.f*ksum;
}

// ---------------------------------------------------------------------------
// Encoder: g_u[b][h][l] = x[b][l]*enc_w[h] + enc_b[h]
// ---------------------------------------------------------------------------
__global__ void encoder_kernel(const float* __restrict__ x,
                               const float* __restrict__ ew,
                               const float* __restrict__ eb)
{
    size_t i = (size_t)blockIdx.x * blockDim.x + threadIdx.x;
    int l = (int)(i & (Lsz - 1));
    size_t bh = i >> 12;
    int hh = (int)(bh & (Hsz - 1));
    int b  = (int)(bh >> 8);
    g_u[i] = x[(size_t)b*Lsz + l]*ew[hh] + eb[hh];
}

// ---------------------------------------------------------------------------
// S4D chunked scan + D-skip + GELU.  One block per (b,h), 256 threads.
// Dyn shared: u[32*129] + y[32*129] + Sre[32*33] + Sim[32*33] + kc[128]
// ---------------------------------------------------------------------------
#define U_PITCH 129
#define S_PITCH 33

__global__ __launch_bounds__(256) void s4d_scan_kernel(const float* __restrict__ Dvec, int il)
{
    extern __shared__ float sm[];
    float* u_sh  = sm;                       // 32*129
    float* y_sh  = u_sh + Cc*U_PITCH;        // 32*129
    float* Sre   = y_sh + Cc*U_PITCH;        // 32*33
    float* Sim   = Sre + Cc*S_PITCH;         // 32*33
    float* kc_sh = Sim + Cc*S_PITCH;         // 128

    int bh = blockIdx.x;            // b*H + h
    int h  = bh & (Hsz - 1);
    int tid = threadIdx.x;

    const float* ubase = g_u + (size_t)bh * Lsz;
    for (int i = tid; i < Lsz; i += 256) {
        u_sh[(i >> 7)*U_PITCH + (i & 127)] = ubase[i];
    }
    if (tid < Tc) kc_sh[tid] = g_kc[((size_t)il*Hsz + h)*Tc + tid];
    __syncthreads();

    // ---- Phase 1: chunk-end states S[c][n] = sum_j Q[j][n]*u[c*T+j]
    const float2* Qh = g_Q + ((size_t)il*Hsz + h)*Tc*N2s;
    int n  = tid & 31;
    int cs = tid >> 5;  // 0..7
    for (int cg = 0; cg < 4; cg++) {
        int c = cg*8 + cs;
        const float* uc = &u_sh[c*U_PITCH];
        float sr = 0.f, si = 0.f;
        #pragma unroll 4
        for (int j = 0; j < Tc; j++) {
            float2 q = Qh[(size_t)j*N2s + n];
            float uu = uc[j];
            sr = fmaf(q.x, uu, sr);
            si = fmaf(q.y, uu, si);
        }
        Sre[c*S_PITCH + n] = sr;
        Sim[c*S_PITCH + n] = si;
    }
    __syncthreads();

    // ---- Phase 2: inter-chunk scan (warp 0, lane = mode). Writes EXCLUSIVE carries.
    if (tid < 32) {
        float2 rt = g_rT[((size_t)il*Hsz + h)*N2s + n];
        float xr = 0.f, xi = 0.f;
        for (int c = 0; c < Cc; c++) {
            float sr = Sre[c*S_PITCH + n];
            float si = Sim[c*S_PITCH + n];
            Sre[c*S_PITCH + n] = xr;
            Sim[c*S_PITCH + n] = xi;
            float nxr = fmaf(rt.x, xr, fmaf(-rt.y, xi, sr));
            float nxi = fmaf(rt.x, xi, fmaf( rt.y, xr, si));
            xr = nxr; xi = nxi;
        }
    }
    __syncthreads();

    // ---- Phase 3: outputs. warp = j-group (j = w + 8*jj), lane = chunk c.
    const float2* Eh = g_E + ((size_t)il*Hsz + h)*Tc*N2s;
    float Dh = Dvec[il*Hsz + h];
    int w = tid >> 5;
    int c = tid & 31;
    const float* uc = &u_sh[c*U_PITCH];
    for (int jj = 0; jj < 16; jj++) {
        int j = w + (jj << 3);
        // triangular conv with k
        float acc = 0.f;
        #pragma unroll 4
        for (int s = 0; s <= j; s++) acc = fmaf(kc_sh[j - s], uc[s], acc);
        // carry contribution
        const float2* Ej = &Eh[(size_t)j*N2s];
        #pragma unroll 8
        for (int nn = 0; nn < N2s; nn++) {
            float2 e = __ldg(&Ej[nn]);
            acc = fmaf(e.x, Sre[c*S_PITCH + nn], acc);
            acc = fmaf(e.y, Sim[c*S_PITCH + nn], acc);
        }
        float yv = acc + Dh * uc[j];
        // exact GELU
        float gl = 0.5f * yv * (1.0f + erff(yv * 0.70710678118654752f));
        y_sh[c*U_PITCH + j] = gl;
    }
    __syncthreads();

    float* ygb = g_yg + (size_t)bh * Lsz;
    for (int i = tid; i < Lsz; i += 256) {
        ygb[i] = y_sh[(i >> 7)*U_PITCH + (i & 127)];
    }
}

// ---------------------------------------------------------------------------
// GLU 1x1-conv GEMM with fused sigmoid-gate + residual.
// Per b: Z[h,l] = A[h,l]*sigmoid(G[h,l]) + u[h,l],
//   A = W[0:256]   @ Yg + ba,  G = W[256:512] @ Yg + bg.
// Tile: BM=64 (h, dual accum), BN=128 (l), BK=16, 256 threads, TM=4, TN=8.
// ---------------------------------------------------------------------------
#define BM 64
#define BN 128
#define BK 16

__global__ __launch_bounds__(256) void glu_gemm_kernel(const float* __restrict__ glu_w,
                                                       const float* __restrict__ glu_b,
                                                       int il)
{
    __shared__ float sWa[BK][BM];
    __shared__ float sWg[BK][BM];
    __shared__ float sY [BK][BN];

    int b  = blockIdx.z;
    int h0 = blockIdx.y * BM;
    int l0 = blockIdx.x * BN;
    int tid = threadIdx.x;
    int tm = (tid & 15) * 4;   // 0..60
    int tn = (tid >> 4) * 8;   // 0..120

    const float* wbase = glu_w + (size_t)il * H2sz * Hsz;
    const float* ygb   = g_yg + (size_t)b * Hsz * Lsz;

    float accA[4][8], accG[4][8];
    #pragma unroll
    for (int m = 0; m < 4; m++)
        #pragma unroll
        for (int nn = 0; nn < 8; nn++) { accA[m][nn] = 0.f; accG[m][nn] = 0.f; }

    // W-load indices
    int wr = tid >> 2;          // 0..63
    int wc = (tid & 3) * 4;     // 0,4,8,12

    for (int k0 = 0; k0 < Hsz; k0 += BK) {
        // load W tiles (transposed into [k][m])
        {
            float4 va = *(const float4*)(wbase + (size_t)(h0 + wr) * Hsz + k0 + wc);
            float4 vg = *(const float4*)(wbase + (size_t)(h0 + wr + Hsz) * Hsz + k0 + wc);
            sWa[wc+0][wr] = va.x; sWa[wc+1][wr] = va.y; sWa[wc+2][wr] = va.z; sWa[wc+3][wr] = va.w;
            sWg[wc+0][wr] = vg.x; sWg[wc+1][wr] = vg.y; sWg[wc+2][wr] = vg.z; sWg[wc+3][wr] = vg.w;
        }
        // load Y tile: 16x128 floats = 512 float4, 2 per thread (coalesced)
        #pragma unroll
        for (int i = 0; i < 2; i++) {
            int idx = tid + i*256;
            int kk = idx >> 5;
            int ll = (idx & 31) * 4;
            float4 v = *(const float4*)(ygb + (size_t)(k0 + kk) * Lsz + l0 + ll);
            *(float4*)&sY[kk][ll] = v;
        }
        __syncthreads();

        #pragma unroll
        for (int k = 0; k < BK; k++) {
            float4 a4 = *(const float4*)&sWa[k][tm];
            float4 g4 = *(const float4*)&sWg[k][tm];
            float4 y0 = *(const float4*)&sY[k][tn];
            float4 y1 = *(const float4*)&sY[k][tn+4];
            float av[4] = {a4.x, a4.y, a4.z, a4.w};
            float gv[4] = {g4.x, g4.y, g4.z, g4.w};
            float yv[8] = {y0.x, y0.y, y0.z, y0.w, y1.x, y1.y, y1.z, y1.w};
            #pragma unroll
            for (int m = 0; m < 4; m++)
                #pragma unroll
                for (int nn = 0; nn < 8; nn++) {
                    accA[m][nn] = fmaf(av[m], yv[nn], accA[m][nn]);
                    accG[m][nn] = fmaf(gv[m], yv[nn], accG[m][nn]);
                }
        }
        __syncthreads();
    }

    // epilogue: GLU + residual
    const float* bb = glu_b + (size_t)il * H2sz;
    const float* ub = g_u + (size_t)b * Hsz * Lsz;
    float* zb       = g_z + (size_t)b * Hsz * Lsz;
    #pragma unroll
    for (int m = 0; m < 4; m++) {
        int hh = h0 + tm + m;
        float ba = bb[hh];
        float bg = bb[hh + Hsz];
        size_t rowoff = (size_t)hh * Lsz + l0 + tn;
        #pragma unroll
        for (int nn = 0; nn < 8; nn++) {
            float a = accA[m][nn] + ba;
            float g = accG[m][nn] + bg;
            float sig = 1.0f / (1.0f + expf(-g));
            zb[rowoff + nn] = fmaf(a, sig, ub[rowoff + nn]);
        }
    }
}

// ---------------------------------------------------------------------------
// LayerNorm over H (postnorm).  One thread per (b,l), two passes.
// reads g_z, writes g_u.
// ---------------------------------------------------------------------------
__global__ void layernorm_kernel(const float* __restrict__ ln_g,
                                 const float* __restrict__ ln_b,
                                 int il)
{
    int idx = blockIdx.x * blockDim.x + threadIdx.x;   // over B*L
    int b = idx >> 12;
    int l = idx & (Lsz - 1);
    const float* zb = g_z + (size_t)b*Hsz*Lsz + l;
    float s = 0.f, s2 = 0.f;
    #pragma unroll 4
    for (int hh = 0; hh < Hsz; hh++) {
        float v = zb[(size_t)hh * Lsz];
        s += v; s2 = fmaf(v, v, s2);
    }
    const float invH = 1.0f / (float)Hsz;
    float mu = s * invH;
    float var = s2 * invH - mu*mu;
    float rstd = rsqrtf(var + 1e-5f);
    float* ob = g_u + (size_t)b*Hsz*Lsz + l;
    const float* gi = ln_g + il*Hsz;
    const float* bi = ln_b + il*Hsz;
    #pragma unroll 4
    for (int hh = 0; hh < Hsz; hh++) {
        float v = zb[(size_t)hh * Lsz];
        ob[(size_t)hh * Lsz] = fmaf((v - mu) * rstd, gi[hh], bi[hh]);
    }
}

// ---------------------------------------------------------------------------
// Decoder: out[b] = sigmoid( sum_{h,l} u[b,h,l]*d1w[l]*d2w[h] + d1b*sum_h d2w[h] + d2b )
// ---------------------------------------------------------------------------
__global__ void decoder_kernel(const float* __restrict__ d1w,
                               const float* __restrict__ d1b,
                               const float* __restrict__ d2w,
                               const float* __restrict__ d2b,
                               float* __restrict__ out)
{
    int b = blockIdx.x;
    const float* hb = g_u + (size_t)b*Hsz*Lsz;
    float acc = 0.f;
    for (int i = threadIdx.x; i < Hsz*Lsz; i += blockDim.x) {
        int hh = i >> 12;
        int l  = i & (Lsz - 1);
        acc = fmaf(hb[i], d1w[l] * d2w[hh], acc);
    }
    __shared__ float red[256];
    red[threadIdx.x] = acc;
    __syncthreads();
    for (int s = 128; s > 0; s >>= 1) {
        if (threadIdx.x < s) red[threadIdx.x] += red[threadIdx.x + s];
        __syncthreads();
    }
    if (threadIdx.x == 0) {
        float sw = 0.f;
        for (int hh = 0; hh < Hsz; hh++) sw += d2w[hh];
        float v = red[0] + d1b[0]*sw + d2b[0];
        out[b] = 1.0f / (1.0f + expf(-v));
    }
}

// ---------------------------------------------------------------------------
// Launch
// ---------------------------------------------------------------------------
extern "C" void kernel_launch(void* const* d_in, const int* in_sizes, int n_in,
                              void* d_out, int out_size)
{
    const float* x          = (const float*)d_in[0];
    const float* enc_w      = (const float*)d_in[1];
    const float* enc_b      = (const float*)d_in[2];
    const float* log_dt     = (const float*)d_in[3];
    const float* log_A_real = (const float*)d_in[4];
    const float* A_imag     = (const float*)d_in[5];
    const float* C_re       = (const float*)d_in[6];
    const float* C_im       = (const float*)d_in[7];
    const float* Dv         = (const float*)d_in[8];
    const float* glu_w      = (const float*)d_in[9];
    const float* glu_b      = (const float*)d_in[10];
    const float* ln_g       = (const float*)d_in[11];
    const float* ln_b       = (const float*)d_in[12];
    const float* dec1_w     = (const float*)d_in[13];
    const float* dec1_b     = (const float*)d_in[14];
    const float* dec2_w     = (const float*)d_in[15];
    const float* dec2_b     = (const float*)d_in[16];
    float* out = (float*)d_out;

    // 1) Precompute S4D tables for all layers
    precompute_kernel<<<NLs*Hsz, 128>>>(log_dt, log_A_real, A_imag, C_re, C_im);

    // 2) Encoder
    {
        size_t total = (size_t)Bsz*Hsz*Lsz;
        encoder_kernel<<<(unsigned)(total/256), 256>>>(x, enc_w, enc_b);
    }

    // 3) Layers
    const int scan_smem = (2*Cc*U_PITCH + 2*Cc*S_PITCH + Tc) * (int)sizeof(float); // 41984 B
    for (int il = 0; il < NLs; il++) {
        s4d_scan_kernel<<<Bsz*Hsz, 256, scan_smem>>>(Dv, il);
        dim3 ggrid(Lsz/BN, Hsz/BM, Bsz);   // (32, 4, 32)
        glu_gemm_kernel<<<ggrid, 256>>>(glu_w, glu_b, il);
        layernorm_kernel<<<(Bsz*Lsz)/256, 256>>>(ln_g, ln_b, il);
    }

    // 4) Decoder
    decoder_kernel<<<Bsz, 256>>>(dec1_w, dec1_b, dec2_w, dec2_b, out);
}

// round 5
// speedup vs baseline: 1.3855x; 1.3855x over previous
#include <cuda_runtime.h>
#include <math.h>

// Problem constants
#define Bsz 32
#define Lsz 4096
#define Hsz 256
#define H2sz 512
#define NLs 4
#define N2s 32
#define Tc  128   // chunk length
#define Cc  32    // chunks per sequence (Tc*Cc == Lsz)
#define Kt  192   // GEMM K dim for output GEMM: 128 (u taps) + 64 (carry re/im)
#define BCt 1024  // B*Cc

// ---------------------------------------------------------------------------
// Scratch (device globals; no runtime allocation allowed)
// ---------------------------------------------------------------------------
__device__ float  g_u [(size_t)Bsz*Hsz*Lsz];       // current hidden state h (B,H,L)
__device__ float  g_yg[(size_t)Bsz*Hsz*Lsz];       // post-gelu S4D output
__device__ float  g_z [(size_t)Bsz*Hsz*Lsz];       // GLU output + residual (pre-LN)
__device__ float2 g_Q [(size_t)NLs*Hsz*Tc*N2s];    // Q[il][h][j][n] = r^(T-1-j)
__device__ float2 g_rT[(size_t)NLs*Hsz*N2s];       // r^T per mode
__device__ float  g_M [(size_t)NLs*Hsz*Kt*Tc];     // M[il][h][k][j]: k<128 tri conv, k>=128 carry inject
__device__ float  g_S [(size_t)Hsz*64*BCt];        // carries: [h][k(0..63)][b*32+c]  (per current layer)

// ---------------------------------------------------------------------------
// Precompute tables per (layer, h).  grid = NL*H blocks, 128 threads.
// Fills g_Q, g_rT and the dense output matrix g_M.
// ---------------------------------------------------------------------------
__global__ void precompute_kernel(const float* __restrict__ log_dt,
                                  const float* __restrict__ log_A_real,
                                  const float* __restrict__ A_imag,
                                  const float* __restrict__ C_re,
                                  const float* __restrict__ C_im)
{
    int ilh = blockIdx.x;
    int il = ilh >> 8;
    int h  = ilh & 255;
    __shared__ float s_dre[N2s], s_dim[N2s], s_Ckr[N2s], s_Cki[N2s];
    __shared__ float s_kc[Tc];

    int tid = threadIdx.x;
    if (tid < N2s) {
        int n = tid;
        float dt = expf(log_dt[il*Hsz + h]);
        size_t idx = ((size_t)il*Hsz + h)*N2s + n;
        float Are = -expf(log_A_real[idx]);
        float Aim = A_imag[idx];
        float dre = Are * dt, dim = Aim * dt;
        float er = expf(dre);
        float sr, cr0; sincosf(dim, &sr, &cr0);
        float rr = er * cr0, ri = er * sr;
        // Ck = C * (r - 1) / A
        float nr = rr - 1.0f, ni = ri;
        float den = Are*Are + Aim*Aim;
        float qr = (nr*Are + ni*Aim)/den;
        float qi = (ni*Are - nr*Aim)/den;
        float cre = C_re[idx], cim = C_im[idx];
        s_dre[n] = dre; s_dim[n] = dim;
        s_Ckr[n] = cre*qr - cim*qi;
        s_Cki[n] = cre*qi + cim*qr;
        // r^T
        float eT = expf(dre * (float)Tc);
        float sT, cT; sincosf(dim * (float)Tc, &sT, &cT);
        g_rT[((size_t)il*Hsz + h)*N2s + n] = make_float2(eT*cT, eT*sT);
    }
    __syncthreads();

    int j = tid;  // 0..127
    float2* Qh = g_Q + (((size_t)il*Hsz + h)*Tc + j)*N2s;
    float*  Mh = g_M + ((size_t)il*Hsz + h)*Kt*Tc;
    float ksum = 0.f;
    #pragma unroll 4
    for (int n = 0; n < N2s; n++) {
        float dre = s_dre[n], dim = s_dim[n];
        float Ckr = s_Ckr[n], Cki = s_Cki[n];
        // Q[j][n] = exp(dtA * (T-1-j))
        float m1 = (float)(Tc - 1 - j);
        float e1 = expf(dre*m1);
        float s1, c1; sincosf(dim*m1, &s1, &c1);
        Qh[n] = make_float2(e1*c1, e1*s1);
        // carry-injection rows: w = Ck * exp(dtA*(j+1))
        float m2 = (float)(j + 1);
        float e2 = expf(dre*m2);
        float s2, c2; sincosf(dim*m2, &s2, &c2);
        float pr = e2*c2, pi = e2*s2;
        float wr = Ckr*pr - Cki*pi;
        float wi = Ckr*pi + Cki*pr;
        Mh[(size_t)(128 + 2*n    )*Tc + j] =  2.f*wr;   // × Re(carry)
        Mh[(size_t)(128 + 2*n + 1)*Tc + j] = -2.f*wi;   // × Im(carry)
        // kconv[j] = 2*Re(Ck * exp(dtA*j))
        float m3 = (float)j;
        float e3 = expf(dre*m3);
        float s3, c3; sincosf(dim*m3, &s3, &c3);
        ksum += Ckr*(e3*c3) - Cki*(e3*s3);
    }
    s_kc[j] = 2.f*ksum;
    __syncthreads();

    // triangular conv rows: M[k][j] = kc[j-k] for k<=j else 0
    for (int k = 0; k < Tc; k++)
        Mh[(size_t)k*Tc + j] = (k <= j) ? s_kc[j - k] : 0.f;
}

// ---------------------------------------------------------------------------
// Encoder: g_u[b][h][l] = x[b][l]*enc_w[h] + enc_b[h]
// ---------------------------------------------------------------------------
__global__ void encoder_kernel(const float* __restrict__ x,
                               const float* __restrict__ ew,
                               const float* __restrict__ eb)
{
    size_t i = (size_t)blockIdx.x * blockDim.x + threadIdx.x;
    int l = (int)(i & (Lsz - 1));
    size_t bh = i >> 12;
    int hh = (int)(bh & (Hsz - 1));
    int b  = (int)(bh >> 8);
    g_u[i] = x[(size_t)b*Lsz + l]*ew[hh] + eb[hh];
}

// ---------------------------------------------------------------------------
// S4D states: chunk-end sums + inter-chunk scan -> exclusive carries in g_S.
// One block per (b,h), 256 threads.
// ---------------------------------------------------------------------------
#define S_PITCH 33

__global__ __launch_bounds__(256) void s4d_state_kernel(int il)
{
    __shared__ float2 Qsh[Tc*N2s];        // 32 KB, layout [j][n]
    __shared__ float  Sre[Cc*S_PITCH];
    __shared__ float  Sim[Cc*S_PITCH];

    int bh = blockIdx.x;            // b*H + h
    int h  = bh & (Hsz - 1);
    int b  = bh >> 8;
    int tid = threadIdx.x;

    // stage Q into smem (float4 copy)
    {
        const float4* src = (const float4*)(g_Q + ((size_t)il*Hsz + h)*Tc*N2s);
        float4* dst = (float4*)Qsh;
        #pragma unroll
        for (int i = 0; i < 8; i++)
            dst[tid + i*256] = src[tid + i*256];
    }
    __syncthreads();

    const float* ubase = g_u + (size_t)bh * Lsz;

    // ---- Phase 1: S[c][n] = sum_j Q[j][n]*u[c*T+j]; each thread: 4 chunks, 1 mode
    int n  = tid & 31;
    int cs = tid >> 5;  // 0..7
    {
        float sr0=0.f,si0=0.f,sr1=0.f,si1=0.f,sr2=0.f,si2=0.f,sr3=0.f,si3=0.f;
        const float* u0 = ubase + (cs     )*Tc;
        const float* u1 = ubase + (cs +  8)*Tc;
        const float* u2 = ubase + (cs + 16)*Tc;
        const float* u3 = ubase + (cs + 24)*Tc;
        #pragma unroll 4
        for (int j = 0; j < Tc; j++) {
            float2 q = Qsh[j*N2s + n];
            float a0 = __ldg(&u0[j]);
            float a1 = __ldg(&u1[j]);
            float a2 = __ldg(&u2[j]);
            float a3 = __ldg(&u3[j]);
            sr0 = fmaf(q.x, a0, sr0); si0 = fmaf(q.y, a0, si0);
            sr1 = fmaf(q.x, a1, sr1); si1 = fmaf(q.y, a1, si1);
            sr2 = fmaf(q.x, a2, sr2); si2 = fmaf(q.y, a2, si2);
            sr3 = fmaf(q.x, a3, sr3); si3 = fmaf(q.y, a3, si3);
        }
        Sre[(cs     )*S_PITCH + n] = sr0;  Sim[(cs     )*S_PITCH + n] = si0;
        Sre[(cs +  8)*S_PITCH + n] = sr1;  Sim[(cs +  8)*S_PITCH + n] = si1;
        Sre[(cs + 16)*S_PITCH + n] = sr2;  Sim[(cs + 16)*S_PITCH + n] = si2;
        Sre[(cs + 24)*S_PITCH + n] = sr3;  Sim[(cs + 24)*S_PITCH + n] = si3;
    }
    __syncthreads();

    // ---- Phase 2: inter-chunk scan (warp 0, lane = mode). Writes EXCLUSIVE carries.
    if (tid < 32) {
        float2 rt = g_rT[((size_t)il*Hsz + h)*N2s + n];
        float xr = 0.f, xi = 0.f;
        for (int c = 0; c < Cc; c++) {
            float sr = Sre[c*S_PITCH + n];
            float si = Sim[c*S_PITCH + n];
            Sre[c*S_PITCH + n] = xr;
            Sim[c*S_PITCH + n] = xi;
            float nxr = fmaf(rt.x, xr, fmaf(-rt.y, xi, sr));
            float nxi = fmaf(rt.x, xi, fmaf( rt.y, xr, si));
            xr = nxr; xi = nxi;
        }
    }
    __syncthreads();

    // ---- Write carries to g_S[h][k][b*32+c], k = 2n (re), 2n+1 (im)
    int c = tid & 31;
    int w = tid >> 5;
    #pragma unroll
    for (int i = 0; i < 8; i++) {
        int k = w*8 + i;                      // 0..63
        int nn = k >> 1;
        float v = (k & 1) ? Sim[c*S_PITCH + nn] : Sre[c*S_PITCH + nn];
        g_S[((size_t)h*64 + k)*BCt + b*32 + c] = v;
    }
}

// ---------------------------------------------------------------------------
// S4D output GEMM:  Y[j, bc] = sum_k M[h][k][j] * X[k][bc]
//   X[k][bc] = u[b,h,c*128+k]   (k < 128)
//            = carry[h][k-128][bc] from g_S  (k >= 128)
// Epilogue: y += D[h]*u, exact GELU, write g_yg.
// Tile: BM=128 (j), BN=64 (bc), BK=16, 256 threads, per-thread 8x4.
// ---------------------------------------------------------------------------
#define OB_BK 16
#define SX_PITCH 68

__global__ __launch_bounds__(256) void s4d_out_gemm(const float* __restrict__ Dvec, int il)
{
    __shared__ float sM[OB_BK][Tc];        // 8 KB
    __shared__ float sX[OB_BK][SX_PITCH];  // 4.25 KB

    int h   = blockIdx.y;
    int bc0 = blockIdx.x * 64;
    int tid = threadIdx.x;
    int tmj = (tid & 15) * 8;   // j offset 0..120
    int tnb = (tid >> 4) * 4;   // bc offset 0..60

    const float* Mbase = g_M + ((size_t)il*Hsz + h)*Kt*Tc;

    float acc[8][4];
    #pragma unroll
    for (int m = 0; m < 8; m++)
        #pragma unroll
        for (int q = 0; q < 4; q++) acc[m][q] = 0.f;

    // u-load indices (for k<128 tiles)
    int u_bcl = tid & 63;
    int u_kk4 = (tid >> 6) * 4;
    int u_b = (bc0 + u_bcl) >> 5;
    int u_c = (bc0 + u_bcl) & 31;
    const float* u_src = g_u + ((size_t)u_b*Hsz + h)*Lsz + u_c*Tc + u_kk4;

    // S-load indices (for k>=128 tiles)
    int s_kk  = tid >> 4;
    int s_bcl = (tid & 15) * 4;
    const float* s_src = g_S + ((size_t)h*64 + s_kk)*BCt + bc0 + s_bcl;

    for (int k0 = 0; k0 < Kt; k0 += OB_BK) {
        // load M tile: 16x128
        #pragma unroll
        for (int i = 0; i < 2; i++) {
            int idx = tid + i*256;
            int kk = idx >> 5;
            int jj = (idx & 31) * 4;
            *(float4*)&sM[kk][jj] = *(const float4*)(Mbase + (size_t)(k0 + kk)*Tc + jj);
        }
        // load X tile: 16x64
        if (k0 < 128) {
            float4 v = *(const float4*)(u_src + k0);
            sX[u_kk4+0][u_bcl] = v.x;
            sX[u_kk4+1][u_bcl] = v.y;
            sX[u_kk4+2][u_bcl] = v.z;
            sX[u_kk4+3][u_bcl] = v.w;
        } else {
            float4 v = *(const float4*)(s_src + (size_t)(k0 - 128)*BCt);
            *(float4*)&sX[s_kk][s_bcl] = v;
        }
        __syncthreads();

        #pragma unroll
        for (int kk = 0; kk < OB_BK; kk++) {
            float4 m0 = *(const float4*)&sM[kk][tmj];
            float4 m1 = *(const float4*)&sM[kk][tmj+4];
            float4 x0 = *(const float4*)&sX[kk][tnb];
            float mv[8] = {m0.x,m0.y,m0.z,m0.w,m1.x,m1.y,m1.z,m1.w};
            float xv[4] = {x0.x,x0.y,x0.z,x0.w};
            #pragma unroll
            for (int m = 0; m < 8; m++)
                #pragma unroll
                for (int q = 0; q < 4; q++)
                    acc[m][q] = fmaf(mv[m], xv[q], acc[m][q]);
        }
        __syncthreads();
    }

    // epilogue: D-skip + GELU, write g_yg
    float Dh = Dvec[il*Hsz + h];
    #pragma unroll
    for (int q = 0; q < 4; q++) {
        int bc = bc0 + tnb + q;
        int b = bc >> 5, c = bc & 31;
        size_t base = ((size_t)b*Hsz + h)*Lsz + c*Tc + tmj;
        float4 u0 = *(const float4*)(g_u + base);
        float4 u1 = *(const float4*)(g_u + base + 4);
        float uu[8] = {u0.x,u0.y,u0.z,u0.w,u1.x,u1.y,u1.z,u1.w};
        float yo[8];
        #pragma unroll
        for (int m = 0; m < 8; m++) {
            float yv = fmaf(Dh, uu[m], acc[m][q]);
            yo[m] = 0.5f * yv * (1.0f + erff(yv * 0.70710678118654752f));
        }
        *(float4*)(g_yg + base)     = make_float4(yo[0],yo[1],yo[2],yo[3]);
        *(float4*)(g_yg + base + 4) = make_float4(yo[4],yo[5],yo[6],yo[7]);
    }
}

// ---------------------------------------------------------------------------
// GLU 1x1-conv GEMM with fused sigmoid-gate + residual.
// Tile: BM=64 (h, dual accum), BN=128 (l), BK=16, 256 threads, TM=4, TN=8.
// ---------------------------------------------------------------------------
#define BM 64
#define BN 128
#define BK 16

__global__ __launch_bounds__(256) void glu_gemm_kernel(const float* __restrict__ glu_w,
                                                       const float* __restrict__ glu_b,
                                                       int il)
{
    __shared__ float sWa[BK][BM];
    __shared__ float sWg[BK][BM];
    __shared__ float sY [BK][BN];

    int b  = blockIdx.z;
    int h0 = blockIdx.y * BM;
    int l0 = blockIdx.x * BN;
    int tid = threadIdx.x;
    int tm = (tid & 15) * 4;   // 0..60
    int tn = (tid >> 4) * 8;   // 0..120

    const float* wbase = glu_w + (size_t)il * H2sz * Hsz;
    const float* ygb   = g_yg + (size_t)b * Hsz * Lsz;

    float accA[4][8], accG[4][8];
    #pragma unroll
    for (int m = 0; m < 4; m++)
        #pragma unroll
        for (int nn = 0; nn < 8; nn++) { accA[m][nn] = 0.f; accG[m][nn] = 0.f; }

    int wr = tid >> 2;          // 0..63
    int wc = (tid & 3) * 4;     // 0,4,8,12

    for (int k0 = 0; k0 < Hsz; k0 += BK) {
        {
            float4 va = *(const float4*)(wbase + (size_t)(h0 + wr) * Hsz + k0 + wc);
            float4 vg = *(const float4*)(wbase + (size_t)(h0 + wr + Hsz) * Hsz + k0 + wc);
            sWa[wc+0][wr] = va.x; sWa[wc+1][wr] = va.y; sWa[wc+2][wr] = va.z; sWa[wc+3][wr] = va.w;
            sWg[wc+0][wr] = vg.x; sWg[wc+1][wr] = vg.y; sWg[wc+2][wr] = vg.z; sWg[wc+3][wr] = vg.w;
        }
        #pragma unroll
        for (int i = 0; i < 2; i++) {
            int idx = tid + i*256;
            int kk = idx >> 5;
            int ll = (idx & 31) * 4;
            float4 v = *(const float4*)(ygb + (size_t)(k0 + kk) * Lsz + l0 + ll);
            *(float4*)&sY[kk][ll] = v;
        }
        __syncthreads();

        #pragma unroll
        for (int k = 0; k < BK; k++) {
            float4 a4 = *(const float4*)&sWa[k][tm];
            float4 g4 = *(const float4*)&sWg[k][tm];
            float4 y0 = *(const float4*)&sY[k][tn];
            float4 y1 = *(const float4*)&sY[k][tn+4];
            float av[4] = {a4.x, a4.y, a4.z, a4.w};
            float gv[4] = {g4.x, g4.y, g4.z, g4.w};
            float yv[8] = {y0.x, y0.y, y0.z, y0.w, y1.x, y1.y, y1.z, y1.w};
            #pragma unroll
            for (int m = 0; m < 4; m++)
                #pragma unroll
                for (int nn = 0; nn < 8; nn++) {
                    accA[m][nn] = fmaf(av[m], yv[nn], accA[m][nn]);
                    accG[m][nn] = fmaf(gv[m], yv[nn], accG[m][nn]);
                }
        }
        __syncthreads();
    }

    const float* bb = glu_b + (size_t)il * H2sz;
    const float* ub = g_u + (size_t)b * Hsz * Lsz;
    float* zb       = g_z + (size_t)b * Hsz * Lsz;
    #pragma unroll
    for (int m = 0; m < 4; m++) {
        int hh = h0 + tm + m;
        float ba = bb[hh];
        float bg = bb[hh + Hsz];
        size_t rowoff = (size_t)hh * Lsz + l0 + tn;
        #pragma unroll
        for (int nn = 0; nn < 8; nn++) {
            float a = accA[m][nn] + ba;
            float g = accG[m][nn] + bg;
            float sig = 1.0f / (1.0f + expf(-g));
            zb[rowoff + nn] = fmaf(a, sig, ub[rowoff + nn]);
        }
    }
}

// ---------------------------------------------------------------------------
// LayerNorm over H (postnorm).  One thread per (b,l), two passes.
// reads g_z, writes g_u.
// ---------------------------------------------------------------------------
__global__ void layernorm_kernel(const float* __restrict__ ln_g,
                                 const float* __restrict__ ln_b,
                                 int il)
{
    int idx = blockIdx.x * blockDim.x + threadIdx.x;   // over B*L
    int b = idx >> 12;
    int l = idx & (Lsz - 1);
    const float* zb = g_z + (size_t)b*Hsz*Lsz + l;
    float s = 0.f, s2 = 0.f;
    #pragma unroll 4
    for (int hh = 0; hh < Hsz; hh++) {
        float v = zb[(size_t)hh * Lsz];
        s += v; s2 = fmaf(v, v, s2);
    }
    const float invH = 1.0f / (float)Hsz;
    float mu = s * invH;
    float var = s2 * invH - mu*mu;
    float rstd = rsqrtf(var + 1e-5f);
    float* ob = g_u + (size_t)b*Hsz*Lsz + l;
    const float* gi = ln_g + il*Hsz;
    const float* bi = ln_b + il*Hsz;
    #pragma unroll 4
    for (int hh = 0; hh < Hsz; hh++) {
        float v = zb[(size_t)hh * Lsz];
        ob[(size_t)hh * Lsz] = fmaf((v - mu) * rstd, gi[hh], bi[hh]);
    }
}

// ---------------------------------------------------------------------------
// Decoder: out[b] = sigmoid( sum_{h,l} u[b,h,l]*d1w[l]*d2w[h] + d1b*sum_h d2w[h] + d2b )
// ---------------------------------------------------------------------------
__global__ void decoder_kernel(const float* __restrict__ d1w,
                               const float* __restrict__ d1b,
                               const float* __restrict__ d2w,
                               const float* __restrict__ d2b,
                               float* __restrict__ out)
{
    int b = blockIdx.x;
    const float* hb = g_u + (size_t)b*Hsz*Lsz;
    float acc = 0.f;
    for (int i = threadIdx.x; i < Hsz*Lsz; i += blockDim.x) {
        int hh = i >> 12;
        int l  = i & (Lsz - 1);
        acc = fmaf(hb[i], d1w[l] * d2w[hh], acc);
    }
    __shared__ float red[256];
    red[threadIdx.x] = acc;
    __syncthreads();
    for (int s = 128; s > 0; s >>= 1) {
        if (threadIdx.x < s) red[threadIdx.x] += red[threadIdx.x + s];
        __syncthreads();
    }
    if (threadIdx.x == 0) {
        float sw = 0.f;
        for (int hh = 0; hh < Hsz; hh++) sw += d2w[hh];
        float v = red[0] + d1b[0]*sw + d2b[0];
        out[b] = 1.0f / (1.0f + expf(-v));
    }
}

// ---------------------------------------------------------------------------
// Launch
// ---------------------------------------------------------------------------
extern "C" void kernel_launch(void* const* d_in, const int* in_sizes, int n_in,
                              void* d_out, int out_size)
{
    const float* x          = (const float*)d_in[0];
    const float* enc_w      = (const float*)d_in[1];
    const float* enc_b      = (const float*)d_in[2];
    const float* log_dt     = (const float*)d_in[3];
    const float* log_A_real = (const float*)d_in[4];
    const float* A_imag     = (const float*)d_in[5];
    const float* C_re       = (const float*)d_in[6];
    const float* C_im       = (const float*)d_in[7];
    const float* Dv         = (const float*)d_in[8];
    const float* glu_w      = (const float*)d_in[9];
    const float* glu_b      = (const float*)d_in[10];
    const float* ln_g       = (const float*)d_in[11];
    const float* ln_b       = (const float*)d_in[12];
    const float* dec1_w     = (const float*)d_in[13];
    const float* dec1_b     = (const float*)d_in[14];
    const float* dec2_w     = (const float*)d_in[15];
    const float* dec2_b     = (const float*)d_in[16];
    float* out = (float*)d_out;

    // 1) Precompute S4D tables + dense output matrices for all layers
    precompute_kernel<<<NLs*Hsz, 128>>>(log_dt, log_A_real, A_imag, C_re, C_im);

    // 2) Encoder
    {
        size_t total = (size_t)Bsz*Hsz*Lsz;
        encoder_kernel<<<(unsigned)(total/256), 256>>>(x, enc_w, enc_b);
    }

    // 3) Layers
    for (int il = 0; il < NLs; il++) {
        s4d_state_kernel<<<Bsz*Hsz, 256>>>(il);
        dim3 ogrid(BCt/64, Hsz);           // (16, 256)
        s4d_out_gemm<<<ogrid, 256>>>(Dv, il);
        dim3 ggrid(Lsz/BN, Hsz/BM, Bsz);   // (32, 4, 32)
        glu_gemm_kernel<<<ggrid, 256>>>(glu_w, glu_b, il);
        layernorm_kernel<<<(Bsz*Lsz)/256, 256>>>(ln_g, ln_b, il);
    }

    // 4) Decoder
    decoder_kernel<<<Bsz, 256>>>(dec1_w, dec1_b, dec2_w, dec2_b, out);
}

// round 11
// speedup vs baseline: 1.6510x; 1.1916x over previous
#include <cuda_runtime.h>
#include <cuda_bf16.h>
#include <math.h>
#include <stdint.h>

// Problem constants
#define Bsz 32
#define Lsz 4096
#define Hsz 256
#define H2sz 512
#define NLs 4
#define N2s 32
#define Tc  128   // chunk length
#define Cc  32    // chunks per sequence (Tc*Cc == Lsz)
#define Kt  192   // output GEMM K dim: 128 (u taps) + 64 (carry re/im)
#define BCt 1024  // B*Cc

// ---------------------------------------------------------------------------
// Scratch (device globals; no runtime allocation allowed)
// ---------------------------------------------------------------------------
__device__ float  g_u [(size_t)Bsz*Hsz*Lsz];       // current hidden state h (B,H,L)
__device__ float  g_yg[(size_t)Bsz*Hsz*Lsz];       // post-gelu S4D output (B,H,L) f32
__device__ float  g_z [(size_t)Bsz*Hsz*Lsz];       // GLU output + residual (pre-LN)
__device__ float2 g_Q [(size_t)NLs*Hsz*Tc*N2s];    // Q[il][h][j][n] = r^(T-1-j)
__device__ float2 g_rT[(size_t)NLs*Hsz*N2s];       // r^T per mode
__device__ float  g_M [(size_t)NLs*Hsz*Kt*Tc];     // M[il][h][k][j]
__device__ float  g_S [(size_t)Hsz*64*BCt];        // carries (per current layer)
// bf16 hi/lo split operands for tensor-core GLU GEMM
__device__ __align__(16) __nv_bfloat16 g_ygt_hi[(size_t)Bsz*Lsz*Hsz];  // Yt[b*L+l][h]
__device__ __align__(16) __nv_bfloat16 g_ygt_lo[(size_t)Bsz*Lsz*Hsz];
__device__ __align__(16) __nv_bfloat16 g_whi[(size_t)NLs*H2sz*Hsz];
__device__ __align__(16) __nv_bfloat16 g_wlo[(size_t)NLs*H2sz*Hsz];

// ---------------------------------------------------------------------------
// Warp-level MMA helpers (sm_80-era, legal on plain sm_103 target)
// ---------------------------------------------------------------------------
__device__ __forceinline__ uint32_t smem_u32(const void* p) {
    uint32_t a;
    asm("{ .reg .u64 t; cvta.to.shared.u64 t, %1; cvt.u32.u64 %0, t; }" : "=r"(a) : "l"(p));
    return a;
}
__device__ __forceinline__ void ldsm_x4(uint32_t* r, uint32_t addr) {
    asm volatile("ldmatrix.sync.aligned.m8n8.x4.shared.b16 {%0,%1,%2,%3}, [%4];"
        : "=r"(r[0]), "=r"(r[1]), "=r"(r[2]), "=r"(r[3]) : "r"(addr));
}
__device__ __forceinline__ void mma_bf16(float* d, const uint32_t* a, const uint32_t* b) {
    asm volatile("mma.sync.aligned.m16n8k16.row.col.f32.bf16.bf16.f32 "
        "{%0,%1,%2,%3}, {%4,%5,%6,%7}, {%8,%9}, {%0,%1,%2,%3};"
        : "+f"(d[0]), "+f"(d[1]), "+f"(d[2]), "+f"(d[3])
        : "r"(a[0]), "r"(a[1]), "r"(a[2]), "r"(a[3]), "r"(b[0]), "r"(b[1]));
}

// ---------------------------------------------------------------------------
// Precompute tables per (layer, h).  grid = NL*H blocks, 128 threads.
// ---------------------------------------------------------------------------
__global__ void precompute_kernel(const float* __restrict__ log_dt,
                                  const float* __restrict__ log_A_real,
                                  const float* __restrict__ A_imag,
                                  const float* __restrict__ C_re,
                                  const float* __restrict__ C_im)
{
    int ilh = blockIdx.x;
    int il = ilh >> 8;
    int h  = ilh & 255;
    __shared__ float s_dre[N2s], s_dim[N2s], s_Ckr[N2s], s_Cki[N2s];
    __shared__ float s_kc[Tc];

    int tid = threadIdx.x;
    if (tid < N2s) {
        int n = tid;
        float dt = expf(log_dt[il*Hsz + h]);
        size_t idx = ((size_t)il*Hsz + h)*N2s + n;
        float Are = -expf(log_A_real[idx]);
        float Aim = A_imag[idx];
        float dre = Are * dt, dim = Aim * dt;
        float er = expf(dre);
        float sr, cr0; sincosf(dim, &sr, &cr0);
        float rr = er * cr0, ri = er * sr;
        float nr = rr - 1.0f, ni = ri;
        float den = Are*Are + Aim*Aim;
        float qr = (nr*Are + ni*Aim)/den;
        float qi = (ni*Are - nr*Aim)/den;
        float cre = C_re[idx], cim = C_im[idx];
        s_dre[n] = dre; s_dim[n] = dim;
        s_Ckr[n] = cre*qr - cim*qi;
        s_Cki[n] = cre*qi + cim*qr;
        float eT = expf(dre * (float)Tc);
        float sT, cT; sincosf(dim * (float)Tc, &sT, &cT);
        g_rT[((size_t)il*Hsz + h)*N2s + n] = make_float2(eT*cT, eT*sT);
    }
    __syncthreads();

    int j = tid;  // 0..127
    float2* Qh = g_Q + (((size_t)il*Hsz + h)*Tc + j)*N2s;
    float*  Mh = g_M + ((size_t)il*Hsz + h)*Kt*Tc;
    float ksum = 0.f;
    #pragma unroll 4
    for (int n = 0; n < N2s; n++) {
        float dre = s_dre[n], dim = s_dim[n];
        float Ckr = s_Ckr[n], Cki = s_Cki[n];
        float m1 = (float)(Tc - 1 - j);
        float e1 = expf(dre*m1);
        float s1, c1; sincosf(dim*m1, &s1, &c1);
        Qh[n] = make_float2(e1*c1, e1*s1);
        float m2 = (float)(j + 1);
        float e2 = expf(dre*m2);
        float s2, c2; sincosf(dim*m2, &s2, &c2);
        float pr = e2*c2, pi = e2*s2;
        float wr = Ckr*pr - Cki*pi;
        float wi = Ckr*pi + Cki*pr;
        Mh[(size_t)(128 + 2*n    )*Tc + j] =  2.f*wr;
        Mh[(size_t)(128 + 2*n + 1)*Tc + j] = -2.f*wi;
        float m3 = (float)j;
        float e3 = expf(dre*m3);
        float s3, c3; sincosf(dim*m3, &s3, &c3);
        ksum += Ckr*(e3*c3) - Cki*(e3*s3);
    }
    s_kc[j] = 2.f*ksum;
    __syncthreads();

    for (int k = 0; k < Tc; k++)
        Mh[(size_t)k*Tc + j] = (k <= j) ? s_kc[j - k] : 0.f;
}

// ---------------------------------------------------------------------------
// GLU weight hi/lo bf16 split (all layers at once).
// ---------------------------------------------------------------------------
__global__ void wconvert_kernel(const float* __restrict__ glu_w)
{
    int i = blockIdx.x * 256 + threadIdx.x;   // < NLs*H2sz*Hsz = 524288
    float x = glu_w[i];
    __nv_bfloat16 hi = __float2bfloat16(x);
    g_whi[i] = hi;
    g_wlo[i] = __float2bfloat16(x - __bfloat162float(hi));
}

// ---------------------------------------------------------------------------
// Encoder: g_u[b][h][l] = x[b][l]*enc_w[h] + enc_b[h]
// ---------------------------------------------------------------------------
__global__ void encoder_kernel(const float* __restrict__ x,
                               const float* __restrict__ ew,
                               const float* __restrict__ eb)
{
    size_t i = (size_t)blockIdx.x * blockDim.x + threadIdx.x;
    int l = (int)(i & (Lsz - 1));
    size_t bh = i >> 12;
    int hh = (int)(bh & (Hsz - 1));
    int b  = (int)(bh >> 8);
    g_u[i] = x[(size_t)b*Lsz + l]*ew[hh] + eb[hh];
}

// ---------------------------------------------------------------------------
// S4D states: chunk-end sums + inter-chunk scan -> exclusive carries in g_S.
// ---------------------------------------------------------------------------
#define S_PITCH 33

__global__ __launch_bounds__(256) void s4d_state_kernel(int il)
{
    __shared__ float2 Qsh[Tc*N2s];
    __shared__ float  Sre[Cc*S_PITCH];
    __shared__ float  Sim[Cc*S_PITCH];

    int bh = blockIdx.x;
    int h  = bh & (Hsz - 1);
    int b  = bh >> 8;
    int tid = threadIdx.x;

    {
        const float4* src = (const float4*)(g_Q + ((size_t)il*Hsz + h)*Tc*N2s);
        float4* dst = (float4*)Qsh;
        #pragma unroll
        for (int i = 0; i < 8; i++)
            dst[tid + i*256] = src[tid + i*256];
    }
    __syncthreads();

    const float* ubase = g_u + (size_t)bh * Lsz;
    int n  = tid & 31;
    int cs = tid >> 5;
    {
        float sr0=0.f,si0=0.f,sr1=0.f,si1=0.f,sr2=0.f,si2=0.f,sr3=0.f,si3=0.f;
        const float* u0 = ubase + (cs     )*Tc;
        const float* u1 = ubase + (cs +  8)*Tc;
        const float* u2 = ubase + (cs + 16)*Tc;
        const float* u3 = ubase + (cs + 24)*Tc;
        #pragma unroll 4
        for (int j = 0; j < Tc; j++) {
            float2 q = Qsh[j*N2s + n];
            float a0 = __ldg(&u0[j]);
            float a1 = __ldg(&u1[j]);
            float a2 = __ldg(&u2[j]);
            float a3 = __ldg(&u3[j]);
            sr0 = fmaf(q.x, a0, sr0); si0 = fmaf(q.y, a0, si0);
            sr1 = fmaf(q.x, a1, sr1); si1 = fmaf(q.y, a1, si1);
            sr2 = fmaf(q.x, a2, sr2); si2 = fmaf(q.y, a2, si2);
            sr3 = fmaf(q.x, a3, sr3); si3 = fmaf(q.y, a3, si3);
        }
        Sre[(cs     )*S_PITCH + n] = sr0;  Sim[(cs     )*S_PITCH + n] = si0;
        Sre[(cs +  8)*S_PITCH + n] = sr1;  Sim[(cs +  8)*S_PITCH + n] = si1;
        Sre[(cs + 16)*S_PITCH + n] = sr2;  Sim[(cs + 16)*S_PITCH + n] = si2;
        Sre[(cs + 24)*S_PITCH + n] = sr3;  Sim[(cs + 24)*S_PITCH + n] = si3;
    }
    __syncthreads();

    if (tid < 32) {
        float2 rt = g_rT[((size_t)il*Hsz + h)*N2s + n];
        float xr = 0.f, xi = 0.f;
        for (int c = 0; c < Cc; c++) {
            float sr = Sre[c*S_PITCH + n];
            float si = Sim[c*S_PITCH + n];
            Sre[c*S_PITCH + n] = xr;
            Sim[c*S_PITCH + n] = xi;
            float nxr = fmaf(rt.x, xr, fmaf(-rt.y, xi, sr));
            float nxi = fmaf(rt.x, xi, fmaf( rt.y, xr, si));
            xr = nxr; xi = nxi;
        }
    }
    __syncthreads();

    int c = tid & 31;
    int w = tid >> 5;
    #pragma unroll
    for (int i = 0; i < 8; i++) {
        int k = w*8 + i;
        int nn = k >> 1;
        float v = (k & 1) ? Sim[c*S_PITCH + nn] : Sre[c*S_PITCH + nn];
        g_S[((size_t)h*64 + k)*BCt + b*32 + c] = v;
    }
}

// ---------------------------------------------------------------------------
// S4D output GEMM (fp32 SIMT):  Y[j, bc] = sum_k M[h][k][j] * X[k][bc]
// Epilogue: y += D[h]*u, exact GELU, write g_yg.
// ---------------------------------------------------------------------------
#define OB_BK 16
#define SX_PITCH 68

__global__ __launch_bounds__(256) void s4d_out_gemm(const float* __restrict__ Dvec, int il)
{
    __shared__ float sM[OB_BK][Tc];
    __shared__ float sX[OB_BK][SX_PITCH];

    int h   = blockIdx.y;
    int bc0 = blockIdx.x * 64;
    int tid = threadIdx.x;
    int tmj = (tid & 15) * 8;
    int tnb = (tid >> 4) * 4;

    const float* Mbase = g_M + ((size_t)il*Hsz + h)*Kt*Tc;

    float acc[8][4];
    #pragma unroll
    for (int m = 0; m < 8; m++)
        #pragma unroll
        for (int q = 0; q < 4; q++) acc[m][q] = 0.f;

    int u_bcl = tid & 63;
    int u_kk4 = (tid >> 6) * 4;
    int u_b = (bc0 + u_bcl) >> 5;
    int u_c = (bc0 + u_bcl) & 31;
    const float* u_src = g_u + ((size_t)u_b*Hsz + h)*Lsz + u_c*Tc + u_kk4;

    int s_kk  = tid >> 4;
    int s_bcl = (tid & 15) * 4;
    const float* s_src = g_S + ((size_t)h*64 + s_kk)*BCt + bc0 + s_bcl;

    for (int k0 = 0; k0 < Kt; k0 += OB_BK) {
        #pragma unroll
        for (int i = 0; i < 2; i++) {
            int idx = tid + i*256;
            int kk = idx >> 5;
            int jj = (idx & 31) * 4;
            *(float4*)&sM[kk][jj] = *(const float4*)(Mbase + (size_t)(k0 + kk)*Tc + jj);
        }
        if (k0 < 128) {
            float4 v = *(const float4*)(u_src + k0);
            sX[u_kk4+0][u_bcl] = v.x;
            sX[u_kk4+1][u_bcl] = v.y;
            sX[u_kk4+2][u_bcl] = v.z;
            sX[u_kk4+3][u_bcl] = v.w;
        } else {
            float4 v = *(const float4*)(s_src + (size_t)(k0 - 128)*BCt);
            *(float4*)&sX[s_kk][s_bcl] = v;
        }
        __syncthreads();

        #pragma unroll
        for (int kk = 0; kk < OB_BK; kk++) {
            float4 m0 = *(const float4*)&sM[kk][tmj];
            float4 m1 = *(const float4*)&sM[kk][tmj+4];
            float4 x0 = *(const float4*)&sX[kk][tnb];
            float mv[8] = {m0.x,m0.y,m0.z,m0.w,m1.x,m1.y,m1.z,m1.w};
            float xv[4] = {x0.x,x0.y,x0.z,x0.w};
            #pragma unroll
            for (int m = 0; m < 8; m++)
                #pragma unroll
                for (int q = 0; q < 4; q++)
                    acc[m][q] = fmaf(mv[m], xv[q], acc[m][q]);
        }
        __syncthreads();
    }

    float Dh = Dvec[il*Hsz + h];
    #pragma unroll
    for (int q = 0; q < 4; q++) {
        int bc = bc0 + tnb + q;
        int b = bc >> 5, c = bc & 31;
        size_t base = ((size_t)b*Hsz + h)*Lsz + c*Tc + tmj;
        float4 u0 = *(const float4*)(g_u + base);
        float4 u1 = *(const float4*)(g_u + base + 4);
        float uu[8] = {u0.x,u0.y,u0.z,u0.w,u1.x,u1.y,u1.z,u1.w};
        float yo[8];
        #pragma unroll
        for (int m = 0; m < 8; m++) {
            float yv = fmaf(Dh, uu[m], acc[m][q]);
            yo[m] = 0.5f * yv * (1.0f + erff(yv * 0.70710678118654752f));
        }
        *(float4*)(g_yg + base)     = make_float4(yo[0],yo[1],yo[2],yo[3]);
        *(float4*)(g_yg + base + 4) = make_float4(yo[4],yo[5],yo[6],yo[7]);
    }
}

// ---------------------------------------------------------------------------
// Transpose + bf16 hi/lo convert: g_yg [b][h][l] f32 -> g_ygt_{hi,lo} [b*L+l][h]
// ---------------------------------------------------------------------------
__global__ __launch_bounds__(256) void transpose_convert_kernel()
{
    __shared__ float tile[64][65];
    int b  = blockIdx.z;
    int h0 = blockIdx.y * 64;
    int l0 = blockIdx.x * 64;
    int tid = threadIdx.x;

    const float* src = g_yg + ((size_t)b*Hsz + h0)*Lsz + l0;
    #pragma unroll
    for (int i = 0; i < 4; i++) {
        int idx = tid + i*256;          // 0..1023 float4 units
        int r  = idx >> 4;              // h row 0..63
        int c4 = (idx & 15) * 4;        // l col
        float4 v = *(const float4*)(src + (size_t)r*Lsz + c4);
        tile[r][c4+0]=v.x; tile[r][c4+1]=v.y; tile[r][c4+2]=v.z; tile[r][c4+3]=v.w;
    }
    __syncthreads();

    __nv_bfloat16* dhi = g_ygt_hi + ((size_t)b*Lsz + l0)*Hsz + h0;
    __nv_bfloat16* dlo = g_ygt_lo + ((size_t)b*Lsz + l0)*Hsz + h0;
    #pragma unroll
    for (int i = 0; i < 8; i++) {
        int idx = tid + i*256;          // 0..2047: 64 l rows x 32 pairs
        int lr = idx >> 5;
        int p  = idx & 31;
        float x0 = tile[2*p][lr];
        float x1 = tile[2*p+1][lr];
        __nv_bfloat16 h0b = __float2bfloat16(x0);
        __nv_bfloat16 h1b = __float2bfloat16(x1);
        __nv_bfloat16 l0b = __float2bfloat16(x0 - __bfloat162float(h0b));
        __nv_bfloat16 l1b = __float2bfloat16(x1 - __bfloat162float(h1b));
        __nv_bfloat162 vh; vh.x = h0b; vh.y = h1b;
        __nv_bfloat162 vl; vl.x = l0b; vl.y = l1b;
        ((__nv_bfloat162*)(dhi + (size_t)lr*Hsz))[p] = vh;
        ((__nv_bfloat162*)(dlo + (size_t)lr*Hsz))[p] = vl;
    }
}

// ---------------------------------------------------------------------------
// GLU GEMM on mma.sync tensor cores (bf16 hi/lo split, fp32 accum).
// CTA: M=128 flat-l rows x N=128 B-rows, K=256 in chunks of 32.
//   sB row r (0..127): even -> W row h0+r/2 ('a'), odd -> W row 256+h0+r/2 ('g')
//   => thread accum regs (d0,d1)/(d2,d3) are (a,g) pairs for one h. No exchange.
// Epilogue: z = (a+ba)*sigmoid(g+bg) + u, write g_z [b][h][l].
// 8 warps as 4(M) x 2(N); warp tile 32x64; per warp 2x8 m16n8k16 tiles.
// ---------------------------------------------------------------------------
#define GP 40   // smem row pitch in bf16 (32 data + 8 pad; 80B rows, conflict-free ldmatrix)

__global__ __launch_bounds__(256) void glu_mma_kernel(const float* __restrict__ glu_b, int il)
{
    __shared__ __nv_bfloat16 sAhi[128*GP], sAlo[128*GP], sBhi[128*GP], sBlo[128*GP];

    int tid  = threadIdx.x;
    int lane = tid & 31;
    int wid  = tid >> 5;
    int wm   = wid & 3;          // 0..3 (M)
    int wn   = wid >> 2;         // 0..1 (N)
    int lbase = blockIdx.x * 128;       // flat b*L + l base
    int h0    = blockIdx.y * 64;        // h block
    int b     = lbase >> 12;

    uint32_t uAhi = smem_u32(sAhi), uAlo = smem_u32(sAlo);
    uint32_t uBhi = smem_u32(sBhi), uBlo = smem_u32(sBlo);

    float acc[2][8][4];
    #pragma unroll
    for (int mt = 0; mt < 2; mt++)
        #pragma unroll
        for (int nt = 0; nt < 8; nt++)
            #pragma unroll
            for (int q = 0; q < 4; q++) acc[mt][nt][q] = 0.f;

    // gmem load indexing (2 uint4 per array per thread per chunk)
    // idx = tid + t*256 in [0,512): r = idx>>2 (row), i = idx&3 (16B unit)
    // B row r -> W h2row
    for (int c = 0; c < 8; c++) {
        int k0 = c * 32;
        __syncthreads();
        #pragma unroll
        for (int t = 0; t < 2; t++) {
            int idx = tid + t*256;
            int r = idx >> 2, i = idx & 3;
            size_t ga = (size_t)(lbase + r)*Hsz + k0 + i*8;
            ((uint4*)sAhi)[r*5 + i] = *(const uint4*)(g_ygt_hi + ga);
            ((uint4*)sAlo)[r*5 + i] = *(const uint4*)(g_ygt_lo + ga);
            int i2 = r >> 1;
            int h2row = (r & 1) ? (256 + h0 + i2) : (h0 + i2);
            size_t gb = ((size_t)il*H2sz + h2row)*Hsz + k0 + i*8;
            ((uint4*)sBhi)[r*5 + i] = *(const uint4*)(g_whi + gb);
            ((uint4*)sBlo)[r*5 + i] = *(const uint4*)(g_wlo + gb);
        }
        __syncthreads();

        #pragma unroll
        for (int s = 0; s < 2; s++) {
            // A fragment addresses: row = warp m row + (lane&15); col = s*16 + (lane>>4)*8
            int acol = s*16 + ((lane >> 4) << 3);
            int arow0 = wm*32 + (lane & 15);
            // B fragment addresses: row(n) = base + (lane&7) + ((lane>>4)&1)*8 ; col(k) = s*16 + ((lane>>3)&1)*8
            int bn = wn*64 + (lane & 7) + (((lane >> 4) & 1) << 3);
            int bk = s*16 + (((lane >> 3) & 1) << 3);

            uint32_t ah[2][4], bh[4][4];
            #pragma unroll
            for (int mt = 0; mt < 2; mt++)
                ldsm_x4(ah[mt], uAhi + (uint32_t)(((arow0 + mt*16)*GP + acol) * 2));
            #pragma unroll
            for (int p = 0; p < 4; p++)
                ldsm_x4(bh[p], uBhi + (uint32_t)(((bn + p*16)*GP + bk) * 2));

            // pass 1: Ahi * Bhi
            #pragma unroll
            for (int mt = 0; mt < 2; mt++)
                #pragma unroll
                for (int nt = 0; nt < 8; nt++)
                    mma_bf16(acc[mt][nt], ah[mt], &bh[nt >> 1][(nt & 1) * 2]);

            // pass 2: Alo * Bhi
            {
                uint32_t al[4];
                #pragma unroll
                for (int mt = 0; mt < 2; mt++) {
                    ldsm_x4(al, uAlo + (uint32_t)(((arow0 + mt*16)*GP + acol) * 2));
                    #pragma unroll
                    for (int nt = 0; nt < 8; nt++)
                        mma_bf16(acc[mt][nt], al, &bh[nt >> 1][(nt & 1) * 2]);
                }
            }
            // pass 3: Ahi * Blo
            {
                uint32_t bl[4];
                #pragma unroll
                for (int p = 0; p < 4; p++) {
                    ldsm_x4(bl, uBlo + (uint32_t)(((bn + p*16)*GP + bk) * 2));
                    #pragma unroll
                    for (int mt = 0; mt < 2; mt++) {
                        mma_bf16(acc[mt][2*p    ], ah[mt], &bl[0]);
                        mma_bf16(acc[mt][2*p + 1], ah[mt], &bl[2]);
                    }
                }
            }
        }
    }

    // epilogue: (d0,d1)=(a,g) @ row l1; (d2,d3)=(a,g) @ row l1+8
    const float* bb = glu_b + (size_t)il * H2sz;
    int lrow0 = (lbase & (Lsz - 1)) + wm*32 + (lane >> 2);
    #pragma unroll
    for (int mt = 0; mt < 2; mt++) {
        int l1 = lrow0 + mt*16;
        #pragma unroll
        for (int nt = 0; nt < 8; nt++) {
            int h = h0 + wn*32 + nt*4 + (lane & 3);
            float ba = bb[h];
            float bg = bb[Hsz + h];
            size_t o1 = ((size_t)b*Hsz + h)*Lsz + l1;
            size_t o2 = o1 + 8;
            float a0 = acc[mt][nt][0] + ba;
            float g0 = acc[mt][nt][1] + bg;
            float a1 = acc[mt][nt][2] + ba;
            float g1 = acc[mt][nt][3] + bg;
            g_z[o1] = fmaf(a0, 1.0f/(1.0f + expf(-g0)), g_u[o1]);
            g_z[o2] = fmaf(a1, 1.0f/(1.0f + expf(-g1)), g_u[o2]);
        }
    }
}

// ---------------------------------------------------------------------------
// LayerNorm over H (postnorm).  reads g_z, writes g_u.
// ---------------------------------------------------------------------------
__global__ void layernorm_kernel(const float* __restrict__ ln_g,
                                 const float* __restrict__ ln_b,
                                 int il)
{
    int idx = blockIdx.x * blockDim.x + threadIdx.x;
    int b = idx >> 12;
    int l = idx & (Lsz - 1);
    const float* zb = g_z + (size_t)b*Hsz*Lsz + l;
    float s = 0.f, s2 = 0.f;
    #pragma unroll 4
    for (int hh = 0; hh < Hsz; hh++) {
        float v = zb[(size_t)hh * Lsz];
        s += v; s2 = fmaf(v, v, s2);
    }
    const float invH = 1.0f / (float)Hsz;
    float mu = s * invH;
    float var = s2 * invH - mu*mu;
    float rstd = rsqrtf(var + 1e-5f);
    float* ob = g_u + (size_t)b*Hsz*Lsz + l;
    const float* gi = ln_g + il*Hsz;
    const float* bi = ln_b + il*Hsz;
    #pragma unroll 4
    for (int hh = 0; hh < Hsz; hh++) {
        float v = zb[(size_t)hh * Lsz];
        ob[(size_t)hh * Lsz] = fmaf((v - mu) * rstd, gi[hh], bi[hh]);
    }
}

// ---------------------------------------------------------------------------
// Decoder
// ---------------------------------------------------------------------------
__global__ void decoder_kernel(const float* __restrict__ d1w,
                               const float* __restrict__ d1b,
                               const float* __restrict__ d2w,
                               const float* __restrict__ d2b,
                               float* __restrict__ out)
{
    int b = blockIdx.x;
    const float* hb = g_u + (size_t)b*Hsz*Lsz;
    float acc = 0.f;
    for (int i = threadIdx.x; i < Hsz*Lsz; i += blockDim.x) {
        int hh = i >> 12;
        int l  = i & (Lsz - 1);
        acc = fmaf(hb[i], d1w[l] * d2w[hh], acc);
    }
    __shared__ float red[256];
    red[threadIdx.x] = acc;
    __syncthreads();
    for (int s = 128; s > 0; s >>= 1) {
        if (threadIdx.x < s) red[threadIdx.x] += red[threadIdx.x + s];
        __syncthreads();
    }
    if (threadIdx.x == 0) {
        float sw = 0.f;
        for (int hh = 0; hh < Hsz; hh++) sw += d2w[hh];
        float v = red[0] + d1b[0]*sw + d2b[0];
        out[b] = 1.0f / (1.0f + expf(-v));
    }
}

// ---------------------------------------------------------------------------
// Launch
// ---------------------------------------------------------------------------
extern "C" void kernel_launch(void* const* d_in, const int* in_sizes, int n_in,
                              void* d_out, int out_size)
{
    const float* x          = (const float*)d_in[0];
    const float* enc_w      = (const float*)d_in[1];
    const float* enc_b      = (const float*)d_in[2];
    const float* log_dt     = (const float*)d_in[3];
    const float* log_A_real = (const float*)d_in[4];
    const float* A_imag     = (const float*)d_in[5];
    const float* C_re       = (const float*)d_in[6];
    const float* C_im       = (const float*)d_in[7];
    const float* Dv         = (const float*)d_in[8];
    const float* glu_w      = (const float*)d_in[9];
    const float* glu_b      = (const float*)d_in[10];
    const float* ln_g       = (const float*)d_in[11];
    const float* ln_b       = (const float*)d_in[12];
    const float* dec1_w     = (const float*)d_in[13];
    const float* dec1_b     = (const float*)d_in[14];
    const float* dec2_w     = (const float*)d_in[15];
    const float* dec2_b     = (const float*)d_in[16];
    float* out = (float*)d_out;

    // 1) Precompute tables + bf16 weight splits
    precompute_kernel<<<NLs*Hsz, 128>>>(log_dt, log_A_real, A_imag, C_re, C_im);
    wconvert_kernel<<<(NLs*H2sz*Hsz)/256, 256>>>(glu_w);

    // 2) Encoder
    {
        size_t total = (size_t)Bsz*Hsz*Lsz;
        encoder_kernel<<<(unsigned)(total/256), 256>>>(x, enc_w, enc_b);
    }

    // 3) Layers
    for (int il = 0; il < NLs; il++) {
        s4d_state_kernel<<<Bsz*Hsz, 256>>>(il);
        dim3 ogrid(BCt/64, Hsz);                    // (16, 256)
        s4d_out_gemm<<<ogrid, 256>>>(Dv, il);
        dim3 tgrid(Lsz/64, Hsz/64, Bsz);            // (64, 4, 32)
        transpose_convert_kernel<<<tgrid, 256>>>();
        dim3 ggrid((Bsz*Lsz)/128, Hsz/64);          // (1024, 4)
        glu_mma_kernel<<<ggrid, 256>>>(glu_b, il);
        layernorm_kernel<<<(Bsz*Lsz)/256, 256>>>(ln_g, ln_b, il);
    }

    // 4) Decoder
    decoder_kernel<<<Bsz, 256>>>(dec1_w, dec1_b, dec2_w, dec2_b, out);
}

// round 12
// speedup vs baseline: 1.7114x; 1.0366x over previous
#include <cuda_runtime.h>
#include <cuda_bf16.h>
#include <math.h>
#include <stdint.h>

// Problem constants
#define Bsz 32
#define Lsz 4096
#define Hsz 256
#define H2sz 512
#define NLs 4
#define N2s 32
#define Tc  128   // chunk length
#define Cc  32    // chunks per sequence (Tc*Cc == Lsz)
#define Kt  192   // output GEMM K dim: 128 (u taps) + 64 (carry re/im)
#define BCt 1024  // B*Cc

// ---------------------------------------------------------------------------
// Scratch (device globals; no runtime allocation allowed)
// ---------------------------------------------------------------------------
__device__ float  g_u [(size_t)Bsz*Hsz*Lsz];       // current hidden state h (B,H,L) fp32
__device__ float  g_yg[(size_t)Bsz*Hsz*Lsz];       // post-gelu S4D output (B,H,L) f32
__device__ float  g_z [(size_t)Bsz*Hsz*Lsz];       // GLU output + residual (pre-LN)
__device__ float2 g_Q [(size_t)NLs*Hsz*Tc*N2s];    // Q[il][h][j][n] = r^(T-1-j)
__device__ float2 g_rT[(size_t)NLs*Hsz*N2s];       // r^T per mode
// bf16 hi/lo operands
__device__ __align__(16) __nv_bfloat16 g_uhi[(size_t)Bsz*Hsz*Lsz];     // u bf16 hi (B,H,L)
__device__ __align__(16) __nv_bfloat16 g_ulo[(size_t)Bsz*Hsz*Lsz];     // u bf16 lo
__device__ __align__(16) __nv_bfloat16 g_Mthi[(size_t)NLs*Hsz*Tc*Kt];  // Mt[il][h][j][k]
__device__ __align__(16) __nv_bfloat16 g_Mtlo[(size_t)NLs*Hsz*Tc*Kt];
__device__ __align__(16) __nv_bfloat16 g_Shi[(size_t)Hsz*BCt*64];      // carries [h][bc][k]
__device__ __align__(16) __nv_bfloat16 g_Slo[(size_t)Hsz*BCt*64];
__device__ __align__(16) __nv_bfloat16 g_ygt_hi[(size_t)Bsz*Lsz*Hsz];  // Yt[b*L+l][h]
__device__ __align__(16) __nv_bfloat16 g_ygt_lo[(size_t)Bsz*Lsz*Hsz];
__device__ __align__(16) __nv_bfloat16 g_whi[(size_t)NLs*H2sz*Hsz];
__device__ __align__(16) __nv_bfloat16 g_wlo[(size_t)NLs*H2sz*Hsz];

// ---------------------------------------------------------------------------
// Warp-level MMA helpers (sm_80-era, legal on plain sm_103 target)
// ---------------------------------------------------------------------------
__device__ __forceinline__ uint32_t smem_u32(const void* p) {
    uint32_t a;
    asm("{ .reg .u64 t; cvta.to.shared.u64 t, %1; cvt.u32.u64 %0, t; }" : "=r"(a) : "l"(p));
    return a;
}
__device__ __forceinline__ void ldsm_x4(uint32_t* r, uint32_t addr) {
    asm volatile("ldmatrix.sync.aligned.m8n8.x4.shared.b16 {%0,%1,%2,%3}, [%4];"
        : "=r"(r[0]), "=r"(r[1]), "=r"(r[2]), "=r"(r[3]) : "r"(addr));
}
__device__ __forceinline__ void mma_bf16(float* d, const uint32_t* a, const uint32_t* b) {
    asm volatile("mma.sync.aligned.m16n8k16.row.col.f32.bf16.bf16.f32 "
        "{%0,%1,%2,%3}, {%4,%5,%6,%7}, {%8,%9}, {%0,%1,%2,%3};"
        : "+f"(d[0]), "+f"(d[1]), "+f"(d[2]), "+f"(d[3])
        : "r"(a[0]), "r"(a[1]), "r"(a[2]), "r"(a[3]), "r"(b[0]), "r"(b[1]));
}
__device__ __forceinline__ void split_bf16(float x, __nv_bfloat16& hi, __nv_bfloat16& lo) {
    hi = __float2bfloat16(x);
    lo = __float2bfloat16(x - __bfloat162float(hi));
}

// ---------------------------------------------------------------------------
// Precompute tables per (layer, h).  grid = NL*H blocks, 128 threads.
// Fills g_Q, g_rT and the transposed bf16 hi/lo output matrix Mt[j][k].
// ---------------------------------------------------------------------------
__global__ void precompute_kernel(const float* __restrict__ log_dt,
                                  const float* __restrict__ log_A_real,
                                  const float* __restrict__ A_imag,
                                  const float* __restrict__ C_re,
                                  const float* __restrict__ C_im)
{
    int ilh = blockIdx.x;
    int il = ilh >> 8;
    int h  = ilh & 255;
    __shared__ float s_dre[N2s], s_dim[N2s], s_Ckr[N2s], s_Cki[N2s];
    __shared__ float s_kc[Tc];

    int tid = threadIdx.x;
    if (tid < N2s) {
        int n = tid;
        float dt = expf(log_dt[il*Hsz + h]);
        size_t idx = ((size_t)il*Hsz + h)*N2s + n;
        float Are = -expf(log_A_real[idx]);
        float Aim = A_imag[idx];
        float dre = Are * dt, dim = Aim * dt;
        float er = expf(dre);
        float sr, cr0; sincosf(dim, &sr, &cr0);
        float rr = er * cr0, ri = er * sr;
        float nr = rr - 1.0f, ni = ri;
        float den = Are*Are + Aim*Aim;
        float qr = (nr*Are + ni*Aim)/den;
        float qi = (ni*Are - nr*Aim)/den;
        float cre = C_re[idx], cim = C_im[idx];
        s_dre[n] = dre; s_dim[n] = dim;
        s_Ckr[n] = cre*qr - cim*qi;
        s_Cki[n] = cre*qi + cim*qr;
        float eT = expf(dre * (float)Tc);
        float sT, cT; sincosf(dim * (float)Tc, &sT, &cT);
        g_rT[((size_t)il*Hsz + h)*N2s + n] = make_float2(eT*cT, eT*sT);
    }
    __syncthreads();

    int j = tid;  // 0..127
    float2* Qh = g_Q + (((size_t)il*Hsz + h)*Tc + j)*N2s;
    __nv_bfloat16* Mh = g_Mthi + (((size_t)il*Hsz + h)*Tc + j)*Kt;
    __nv_bfloat16* Ml = g_Mtlo + (((size_t)il*Hsz + h)*Tc + j)*Kt;
    float ksum = 0.f;
    #pragma unroll 4
    for (int n = 0; n < N2s; n++) {
        float dre = s_dre[n], dim = s_dim[n];
        float Ckr = s_Ckr[n], Cki = s_Cki[n];
        float m1 = (float)(Tc - 1 - j);
        float e1 = expf(dre*m1);
        float s1, c1; sincosf(dim*m1, &s1, &c1);
        Qh[n] = make_float2(e1*c1, e1*s1);
        float m2 = (float)(j + 1);
        float e2 = expf(dre*m2);
        float s2, c2; sincosf(dim*m2, &s2, &c2);
        float pr = e2*c2, pi = e2*s2;
        float wr = Ckr*pr - Cki*pi;
        float wi = Ckr*pi + Cki*pr;
        __nv_bfloat16 hb, lb;
        split_bf16( 2.f*wr, hb, lb); Mh[128 + 2*n    ] = hb; Ml[128 + 2*n    ] = lb;
        split_bf16(-2.f*wi, hb, lb); Mh[128 + 2*n + 1] = hb; Ml[128 + 2*n + 1] = lb;
        float m3 = (float)j;
        float e3 = expf(dre*m3);
        float s3, c3; sincosf(dim*m3, &s3, &c3);
        ksum += Ckr*(e3*c3) - Cki*(e3*s3);
    }
    s_kc[j] = 2.f*ksum;
    __syncthreads();

    for (int k = 0; k < Tc; k++) {
        float v = (k <= j) ? s_kc[j - k] : 0.f;
        __nv_bfloat16 hb, lb;
        split_bf16(v, hb, lb);
        Mh[k] = hb; Ml[k] = lb;
    }
}

// ---------------------------------------------------------------------------
// GLU weight hi/lo bf16 split (all layers at once).
// ---------------------------------------------------------------------------
__global__ void wconvert_kernel(const float* __restrict__ glu_w)
{
    int i = blockIdx.x * 256 + threadIdx.x;   // < NLs*H2sz*Hsz = 524288
    float x = glu_w[i];
    __nv_bfloat16 hi, lo;
    split_bf16(x, hi, lo);
    g_whi[i] = hi;
    g_wlo[i] = lo;
}

// ---------------------------------------------------------------------------
// Encoder: g_u[b][h][l] = x[b][l]*enc_w[h] + enc_b[h]  (+ bf16 hi/lo copies)
// ---------------------------------------------------------------------------
__global__ void encoder_kernel(const float* __restrict__ x,
                               const float* __restrict__ ew,
                               const float* __restrict__ eb)
{
    size_t i = (size_t)blockIdx.x * blockDim.x + threadIdx.x;
    int l = (int)(i & (Lsz - 1));
    size_t bh = i >> 12;
    int hh = (int)(bh & (Hsz - 1));
    int b  = (int)(bh >> 8);
    float v = x[(size_t)b*Lsz + l]*ew[hh] + eb[hh];
    g_u[i] = v;
    __nv_bfloat16 hi, lo;
    split_bf16(v, hi, lo);
    g_uhi[i] = hi;
    g_ulo[i] = lo;
}

// ---------------------------------------------------------------------------
// S4D states: chunk-end sums + inter-chunk scan -> exclusive carries (bf16 hi/lo)
// in g_Shi/g_Slo with layout [h][bc][64].
// ---------------------------------------------------------------------------
#define S_PITCH 33

__global__ __launch_bounds__(256) void s4d_state_kernel(int il)
{
    __shared__ float2 Qsh[Tc*N2s];
    __shared__ float  Sre[Cc*S_PITCH];
    __shared__ float  Sim[Cc*S_PITCH];

    int bh = blockIdx.x;
    int h  = bh & (Hsz - 1);
    int b  = bh >> 8;
    int tid = threadIdx.x;

    {
        const float4* src = (const float4*)(g_Q + ((size_t)il*Hsz + h)*Tc*N2s);
        float4* dst = (float4*)Qsh;
        #pragma unroll
        for (int i = 0; i < 8; i++)
            dst[tid + i*256] = src[tid + i*256];
    }
    __syncthreads();

    const float* ubase = g_u + (size_t)bh * Lsz;
    int n  = tid & 31;
    int cs = tid >> 5;
    {
        float sr0=0.f,si0=0.f,sr1=0.f,si1=0.f,sr2=0.f,si2=0.f,sr3=0.f,si3=0.f;
        const float* u0 = ubase + (cs     )*Tc;
        const float* u1 = ubase + (cs +  8)*Tc;
        const float* u2 = ubase + (cs + 16)*Tc;
        const float* u3 = ubase + (cs + 24)*Tc;
        #pragma unroll 4
        for (int j = 0; j < Tc; j++) {
            float2 q = Qsh[j*N2s + n];
            float a0 = __ldg(&u0[j]);
            float a1 = __ldg(&u1[j]);
            float a2 = __ldg(&u2[j]);
            float a3 = __ldg(&u3[j]);
            sr0 = fmaf(q.x, a0, sr0); si0 = fmaf(q.y, a0, si0);
            sr1 = fmaf(q.x, a1, sr1); si1 = fmaf(q.y, a1, si1);
            sr2 = fmaf(q.x, a2, sr2); si2 = fmaf(q.y, a2, si2);
            sr3 = fmaf(q.x, a3, sr3); si3 = fmaf(q.y, a3, si3);
        }
        Sre[(cs     )*S_PITCH + n] = sr0;  Sim[(cs     )*S_PITCH + n] = si0;
        Sre[(cs +  8)*S_PITCH + n] = sr1;  Sim[(cs +  8)*S_PITCH + n] = si1;
        Sre[(cs + 16)*S_PITCH + n] = sr2;  Sim[(cs + 16)*S_PITCH + n] = si2;
        Sre[(cs + 24)*S_PITCH + n] = sr3;  Sim[(cs + 24)*S_PITCH + n] = si3;
    }
    __syncthreads();

    if (tid < 32) {
        float2 rt = g_rT[((size_t)il*Hsz + h)*N2s + n];
        float xr = 0.f, xi = 0.f;
        for (int c = 0; c < Cc; c++) {
            float sr = Sre[c*S_PITCH + n];
            float si = Sim[c*S_PITCH + n];
            Sre[c*S_PITCH + n] = xr;
            Sim[c*S_PITCH + n] = xi;
            float nxr = fmaf(rt.x, xr, fmaf(-rt.y, xi, sr));
            float nxi = fmaf(rt.x, xi, fmaf( rt.y, xr, si));
            xr = nxr; xi = nxi;
        }
    }
    __syncthreads();

    // Write carries bf16 hi/lo to [h][b*32+c][k], k = 2n (re), 2n+1 (im).
    // thread: c = tid>>3 (0..31), kg = tid&7 -> 8 consecutive k.
    {
        int c  = tid >> 3;
        int kg = tid & 7;
        __nv_bfloat16 vh[8], vl[8];
        #pragma unroll
        for (int i = 0; i < 8; i++) {
            int k = kg*8 + i;
            int nn = k >> 1;
            float v = (k & 1) ? Sim[c*S_PITCH + nn] : Sre[c*S_PITCH + nn];
            split_bf16(v, vh[i], vl[i]);
        }
        size_t off = ((size_t)h*BCt + b*32 + c)*64 + kg*8;
        *(uint4*)(g_Shi + off) = *(uint4*)vh;
        *(uint4*)(g_Slo + off) = *(uint4*)vl;
    }
}

// ---------------------------------------------------------------------------
// S4D output GEMM on mma.sync (bf16 hi/lo, fp32 accum).
// Per CTA (h, bc-tile of 128): D[bc=128, j=128] = Xt[128,192] . Mt[128,192]^T
//   Xt rows (bc): k<128 from g_uhi/lo (contiguous l), k>=128 from g_Shi/lo.
//   B rows (j):   Mt[j][k] from g_Mthi/lo.
// Epilogue: yv = acc + D[h]*u, exact GELU, write g_yg [b][h][l] (coalesced pairs).
// 8 warps 4(M:bc) x 2(N:j); warp tile 32x64; K chunks of 32 (6 chunks).
// ---------------------------------------------------------------------------
#define GP 40   // smem row pitch in bf16

__global__ __launch_bounds__(256) void s4d_out_mma(const float* __restrict__ Dvec, int il)
{
    __shared__ __nv_bfloat16 sAhi[128*GP], sAlo[128*GP], sBhi[128*GP], sBlo[128*GP];

    int tid  = threadIdx.x;
    int lane = tid & 31;
    int wid  = tid >> 5;
    int wm   = wid & 3;
    int wn   = wid >> 2;
    int bc0  = blockIdx.x * 128;
    int h    = blockIdx.y;

    uint32_t uAhi = smem_u32(sAhi), uAlo = smem_u32(sAlo);
    uint32_t uBhi = smem_u32(sBhi), uBlo = smem_u32(sBlo);

    float acc[2][8][4];
    #pragma unroll
    for (int mt = 0; mt < 2; mt++)
        #pragma unroll
        for (int nt = 0; nt < 8; nt++)
            #pragma unroll
            for (int q = 0; q < 4; q++) acc[mt][nt][q] = 0.f;

    const __nv_bfloat16* Mtbh = g_Mthi + ((size_t)il*Hsz + h)*Tc*Kt;
    const __nv_bfloat16* Mtbl = g_Mtlo + ((size_t)il*Hsz + h)*Tc*Kt;

    for (int c = 0; c < 6; c++) {
        int k0 = c * 32;
        __syncthreads();
        #pragma unroll
        for (int t = 0; t < 2; t++) {
            int idx = tid + t*256;
            int r = idx >> 2, i = idx & 3;
            // A row r -> bc = bc0 + r
            int bc = bc0 + r;
            if (k0 < 128) {
                int b2 = bc >> 5, c2 = bc & 31;
                size_t ga = ((size_t)b2*Hsz + h)*Lsz + c2*Tc + k0 + i*8;
                ((uint4*)sAhi)[r*5 + i] = *(const uint4*)(g_uhi + ga);
                ((uint4*)sAlo)[r*5 + i] = *(const uint4*)(g_ulo + ga);
            } else {
                size_t ga = ((size_t)h*BCt + bc)*64 + (k0 - 128) + i*8;
                ((uint4*)sAhi)[r*5 + i] = *(const uint4*)(g_Shi + ga);
                ((uint4*)sAlo)[r*5 + i] = *(const uint4*)(g_Slo + ga);
            }
            // B row r -> j = r
            size_t gb = (size_t)r*Kt + k0 + i*8;
            ((uint4*)sBhi)[r*5 + i] = *(const uint4*)(Mtbh + gb);
            ((uint4*)sBlo)[r*5 + i] = *(const uint4*)(Mtbl + gb);
        }
        __syncthreads();

        #pragma unroll
        for (int s = 0; s < 2; s++) {
            int acol = s*16 + ((lane >> 4) << 3);
            int arow0 = wm*32 + (lane & 15);
            int bn = wn*64 + (lane & 7) + (((lane >> 4) & 1) << 3);
            int bk = s*16 + (((lane >> 3) & 1) << 3);

            uint32_t ah[2][4], bh[4][4];
            #pragma unroll
            for (int mt = 0; mt < 2; mt++)
                ldsm_x4(ah[mt], uAhi + (uint32_t)(((arow0 + mt*16)*GP + acol) * 2));
            #pragma unroll
            for (int p = 0; p < 4; p++)
                ldsm_x4(bh[p], uBhi + (uint32_t)(((bn + p*16)*GP + bk) * 2));

            #pragma unroll
            for (int mt = 0; mt < 2; mt++)
                #pragma unroll
                for (int nt = 0; nt < 8; nt++)
                    mma_bf16(acc[mt][nt], ah[mt], &bh[nt >> 1][(nt & 1) * 2]);

            {
                uint32_t al[4];
                #pragma unroll
                for (int mt = 0; mt < 2; mt++) {
                    ldsm_x4(al, uAlo + (uint32_t)(((arow0 + mt*16)*GP + acol) * 2));
                    #pragma unroll
                    for (int nt = 0; nt < 8; nt++)
                        mma_bf16(acc[mt][nt], al, &bh[nt >> 1][(nt & 1) * 2]);
                }
            }
            {
                uint32_t bl[4];
                #pragma unroll
                for (int p = 0; p < 4; p++) {
                    ldsm_x4(bl, uBlo + (uint32_t)(((bn + p*16)*GP + bk) * 2));
                    #pragma unroll
                    for (int mt = 0; mt < 2; mt++) {
                        mma_bf16(acc[mt][2*p    ], ah[mt], &bl[0]);
                        mma_bf16(acc[mt][2*p + 1], ah[mt], &bl[2]);
                    }
                }
            }
        }
    }

    // epilogue: thread (mt) rows bc = bc0 + wm*32 + mt*16 + (lane>>2) (+8 for d2,d3)
    //           cols j = wn*64 + nt*8 + (lane&3)*2 (pairs)
    float Dh = Dvec[il*Hsz + h];
    int r0 = wm*32 + (lane >> 2);
    #pragma unroll
    for (int mt = 0; mt < 2; mt++) {
        #pragma unroll
        for (int half = 0; half < 2; half++) {
            int bc = bc0 + r0 + mt*16 + half*8;
            int b2 = bc >> 5, c2 = bc & 31;
            size_t rowbase = ((size_t)b2*Hsz + h)*Lsz + c2*Tc;
            #pragma unroll
            for (int nt = 0; nt < 8; nt++) {
                int j = wn*64 + nt*8 + (lane & 3)*2;
                size_t o = rowbase + j;
                float2 uu = *(const float2*)(g_u + o);
                float y0 = fmaf(Dh, uu.x, acc[mt][nt][half*2 + 0]);
                float y1 = fmaf(Dh, uu.y, acc[mt][nt][half*2 + 1]);
                float2 yo;
                yo.x = 0.5f * y0 * (1.0f + erff(y0 * 0.70710678118654752f));
                yo.y = 0.5f * y1 * (1.0f + erff(y1 * 0.70710678118654752f));
                *(float2*)(g_yg + o) = yo;
            }
        }
    }
}

// ---------------------------------------------------------------------------
// Transpose + bf16 hi/lo convert: g_yg [b][h][l] f32 -> g_ygt_{hi,lo} [b*L+l][h]
// ---------------------------------------------------------------------------
__global__ __launch_bounds__(256) void transpose_convert_kernel()
{
    __shared__ float tile[64][65];
    int b  = blockIdx.z;
    int h0 = blockIdx.y * 64;
    int l0 = blockIdx.x * 64;
    int tid = threadIdx.x;

    const float* src = g_yg + ((size_t)b*Hsz + h0)*Lsz + l0;
    #pragma unroll
    for (int i = 0; i < 4; i++) {
        int idx = tid + i*256;
        int r  = idx >> 4;
        int c4 = (idx & 15) * 4;
        float4 v = *(const float4*)(src + (size_t)r*Lsz + c4);
        tile[r][c4+0]=v.x; tile[r][c4+1]=v.y; tile[r][c4+2]=v.z; tile[r][c4+3]=v.w;
    }
    __syncthreads();

    __nv_bfloat16* dhi = g_ygt_hi + ((size_t)b*Lsz + l0)*Hsz + h0;
    __nv_bfloat16* dlo = g_ygt_lo + ((size_t)b*Lsz + l0)*Hsz + h0;
    #pragma unroll
    for (int i = 0; i < 8; i++) {
        int idx = tid + i*256;
        int lr = idx >> 5;
        int p  = idx & 31;
        float x0 = tile[2*p][lr];
        float x1 = tile[2*p+1][lr];
        __nv_bfloat16 h0b, l0b, h1b, l1b;
        split_bf16(x0, h0b, l0b);
        split_bf16(x1, h1b, l1b);
        __nv_bfloat162 vh; vh.x = h0b; vh.y = h1b;
        __nv_bfloat162 vl; vl.x = l0b; vl.y = l1b;
        ((__nv_bfloat162*)(dhi + (size_t)lr*Hsz))[p] = vh;
        ((__nv_bfloat162*)(dlo + (size_t)lr*Hsz))[p] = vl;
    }
}

// ---------------------------------------------------------------------------
// GLU GEMM on mma.sync tensor cores (bf16 hi/lo split, fp32 accum).
// ---------------------------------------------------------------------------
__global__ __launch_bounds__(256) void glu_mma_kernel(const float* __restrict__ glu_b, int il)
{
    __shared__ __nv_bfloat16 sAhi[128*GP], sAlo[128*GP], sBhi[128*GP], sBlo[128*GP];

    int tid  = threadIdx.x;
    int lane = tid & 31;
    int wid  = tid >> 5;
    int wm   = wid & 3;
    int wn   = wid >> 2;
    int lbase = blockIdx.x * 128;
    int h0    = blockIdx.y * 64;
    int b     = lbase >> 12;

    uint32_t uAhi = smem_u32(sAhi), uAlo = smem_u32(sAlo);
    uint32_t uBhi = smem_u32(sBhi), uBlo = smem_u32(sBlo);

    float acc[2][8][4];
    #pragma unroll
    for (int mt = 0; mt < 2; mt++)
        #pragma unroll
        for (int nt = 0; nt < 8; nt++)
            #pragma unroll
            for (int q = 0; q < 4; q++) acc[mt][nt][q] = 0.f;

    for (int c = 0; c < 8; c++) {
        int k0 = c * 32;
        __syncthreads();
        #pragma unroll
        for (int t = 0; t < 2; t++) {
            int idx = tid + t*256;
            int r = idx >> 2, i = idx & 3;
            size_t ga = (size_t)(lbase + r)*Hsz + k0 + i*8;
            ((uint4*)sAhi)[r*5 + i] = *(const uint4*)(g_ygt_hi + ga);
            ((uint4*)sAlo)[r*5 + i] = *(const uint4*)(g_ygt_lo + ga);
            int i2 = r >> 1;
            int h2row = (r & 1) ? (256 + h0 + i2) : (h0 + i2);
            size_t gb = ((size_t)il*H2sz + h2row)*Hsz + k0 + i*8;
            ((uint4*)sBhi)[r*5 + i] = *(const uint4*)(g_whi + gb);
            ((uint4*)sBlo)[r*5 + i] = *(const uint4*)(g_wlo + gb);
        }
        __syncthreads();

        #pragma unroll
        for (int s = 0; s < 2; s++) {
            int acol = s*16 + ((lane >> 4) << 3);
            int arow0 = wm*32 + (lane & 15);
            int bn = wn*64 + (lane & 7) + (((lane >> 4) & 1) << 3);
            int bk = s*16 + (((lane >> 3) & 1) << 3);

            uint32_t ah[2][4], bh[4][4];
            #pragma unroll
            for (int mt = 0; mt < 2; mt++)
                ldsm_x4(ah[mt], uAhi + (uint32_t)(((arow0 + mt*16)*GP + acol) * 2));
            #pragma unroll
            for (int p = 0; p < 4; p++)
                ldsm_x4(bh[p], uBhi + (uint32_t)(((bn + p*16)*GP + bk) * 2));

            #pragma unroll
            for (int mt = 0; mt < 2; mt++)
                #pragma unroll
                for (int nt = 0; nt < 8; nt++)
                    mma_bf16(acc[mt][nt], ah[mt], &bh[nt >> 1][(nt & 1) * 2]);

            {
                uint32_t al[4];
                #pragma unroll
                for (int mt = 0; mt < 2; mt++) {
                    ldsm_x4(al, uAlo + (uint32_t)(((arow0 + mt*16)*GP + acol) * 2));
                    #pragma unroll
                    for (int nt = 0; nt < 8; nt++)
                        mma_bf16(acc[mt][nt], al, &bh[nt >> 1][(nt & 1) * 2]);
                }
            }
            {
                uint32_t bl[4];
                #pragma unroll
                for (int p = 0; p < 4; p++) {
                    ldsm_x4(bl, uBlo + (uint32_t)(((bn + p*16)*GP + bk) * 2));
                    #pragma unroll
                    for (int mt = 0; mt < 2; mt++) {
                        mma_bf16(acc[mt][2*p    ], ah[mt], &bl[0]);
                        mma_bf16(acc[mt][2*p + 1], ah[mt], &bl[2]);
                    }
                }
            }
        }
    }

    const float* bb = glu_b + (size_t)il * H2sz;
    int lrow0 = (lbase & (Lsz - 1)) + wm*32 + (lane >> 2);
    #pragma unroll
    for (int mt = 0; mt < 2; mt++) {
        int l1 = lrow0 + mt*16;
        #pragma unroll
        for (int nt = 0; nt < 8; nt++) {
            int h = h0 + wn*32 + nt*4 + (lane & 3);
            float ba = bb[h];
            float bg = bb[Hsz + h];
            size_t o1 = ((size_t)b*Hsz + h)*Lsz + l1;
            size_t o2 = o1 + 8;
            float a0 = acc[mt][nt][0] + ba;
            float g0 = acc[mt][nt][1] + bg;
            float a1 = acc[mt][nt][2] + ba;
            float g1 = acc[mt][nt][3] + bg;
            g_z[o1] = fmaf(a0, 1.0f/(1.0f + expf(-g0)), g_u[o1]);
            g_z[o2] = fmaf(a1, 1.0f/(1.0f + expf(-g1)), g_u[o2]);
        }
    }
}

// ---------------------------------------------------------------------------
// LayerNorm over H (postnorm).  reads g_z, writes g_u fp32 + bf16 hi/lo.
// ---------------------------------------------------------------------------
__global__ void layernorm_kernel(const float* __restrict__ ln_g,
                                 const float* __restrict__ ln_b,
                                 int il)
{
    int idx = blockIdx.x * blockDim.x + threadIdx.x;
    int b = idx >> 12;
    int l = idx & (Lsz - 1);
    const float* zb = g_z + (size_t)b*Hsz*Lsz + l;
    float s = 0.f, s2 = 0.f;
    #pragma unroll 4
    for (int hh = 0; hh < Hsz; hh++) {
        float v = zb[(size_t)hh * Lsz];
        s += v; s2 = fmaf(v, v, s2);
    }
    const float invH = 1.0f / (float)Hsz;
    float mu = s * invH;
    float var = s2 * invH - mu*mu;
    float rstd = rsqrtf(var + 1e-5f);
    size_t base = (size_t)b*Hsz*Lsz + l;
    const float* gi = ln_g + il*Hsz;
    const float* bi = ln_b + il*Hsz;
    #pragma unroll 4
    for (int hh = 0; hh < Hsz; hh++) {
        float v = zb[(size_t)hh * Lsz];
        float o = fmaf((v - mu) * rstd, gi[hh], bi[hh]);
        size_t off = base + (size_t)hh * Lsz;
        g_u[off] = o;
        __nv_bfloat16 hi, lo;
        split_bf16(o, hi, lo);
        g_uhi[off] = hi;
        g_ulo[off] = lo;
    }
}

// ---------------------------------------------------------------------------
// Decoder
// ---------------------------------------------------------------------------
__global__ void decoder_kernel(const float* __restrict__ d1w,
                               const float* __restrict__ d1b,
                               const float* __restrict__ d2w,
                               const float* __restrict__ d2b,
                               float* __restrict__ out)
{
    int b = blockIdx.x;
    const float* hb = g_u + (size_t)b*Hsz*Lsz;
    float acc = 0.f;
    for (int i = threadIdx.x; i < Hsz*Lsz; i += blockDim.x) {
        int hh = i >> 12;
        int l  = i & (Lsz - 1);
        acc = fmaf(hb[i], d1w[l] * d2w[hh], acc);
    }
    __shared__ float red[256];
    red[threadIdx.x] = acc;
    __syncthreads();
    for (int s = 128; s > 0; s >>= 1) {
        if (threadIdx.x < s) red[threadIdx.x] += red[threadIdx.x + s];
        __syncthreads();
    }
    if (threadIdx.x == 0) {
        float sw = 0.f;
        for (int hh = 0; hh < Hsz; hh++) sw += d2w[hh];
        float v = red[0] + d1b[0]*sw + d2b[0];
        out[b] = 1.0f / (1.0f + expf(-v));
    }
}

// ---------------------------------------------------------------------------
// Launch
// ---------------------------------------------------------------------------
extern "C" void kernel_launch(void* const* d_in, const int* in_sizes, int n_in,
                              void* d_out, int out_size)
{
    const float* x          = (const float*)d_in[0];
    const float* enc_w      = (const float*)d_in[1];
    const float* enc_b      = (const float*)d_in[2];
    const float* log_dt     = (const float*)d_in[3];
    const float* log_A_real = (const float*)d_in[4];
    const float* A_imag     = (const float*)d_in[5];
    const float* C_re       = (const float*)d_in[6];
    const float* C_im       = (const float*)d_in[7];
    const float* Dv         = (const float*)d_in[8];
    const float* glu_w      = (const float*)d_in[9];
    const float* glu_b      = (const float*)d_in[10];
    const float* ln_g       = (const float*)d_in[11];
    const float* ln_b       = (const float*)d_in[12];
    const float* dec1_w     = (const float*)d_in[13];
    const float* dec1_b     = (const float*)d_in[14];
    const float* dec2_w     = (const float*)d_in[15];
    const float* dec2_b     = (const float*)d_in[16];
    float* out = (float*)d_out;

    // 1) Precompute tables + bf16 weight splits
    precompute_kernel<<<NLs*Hsz, 128>>>(log_dt, log_A_real, A_imag, C_re, C_im);
    wconvert_kernel<<<(NLs*H2sz*Hsz)/256, 256>>>(glu_w);

    // 2) Encoder
    {
        size_t total = (size_t)Bsz*Hsz*Lsz;
        encoder_kernel<<<(unsigned)(total/256), 256>>>(x, enc_w, enc_b);
    }

    // 3) Layers
    for (int il = 0; il < NLs; il++) {
        s4d_state_kernel<<<Bsz*Hsz, 256>>>(il);
        dim3 ogrid(BCt/128, Hsz);                   // (8, 256)
        s4d_out_mma<<<ogrid, 256>>>(Dv, il);
        dim3 tgrid(Lsz/64, Hsz/64, Bsz);            // (64, 4, 32)
        transpose_convert_kernel<<<tgrid, 256>>>();
        dim3 ggrid((Bsz*Lsz)/128, Hsz/64);          // (1024, 4)
        glu_mma_kernel<<<ggrid, 256>>>(glu_b, il);
        layernorm_kernel<<<(Bsz*Lsz)/256, 256>>>(ln_g, ln_b, il);
    }

    // 4) Decoder
    decoder_kernel<<<Bsz, 256>>>(dec1_w, dec1_b, dec2_w, dec2_b, out);
}

// round 13
// speedup vs baseline: 1.8940x; 1.1067x over previous
#include <cuda_runtime.h>
#include <cuda_bf16.h>
#include <math.h>
#include <stdint.h>

// Problem constants
#define Bsz 32
#define Lsz 4096
#define Hsz 256
#define H2sz 512
#define NLs 4
#define N2s 32
#define Tc  128   // chunk length
#define Cc  32    // chunks per sequence (Tc*Cc == Lsz)
#define Kt  192   // output GEMM K dim: 128 (u taps) + 64 (carry re/im)
#define BCt 1024  // B*Cc

// ---------------------------------------------------------------------------
// Scratch (device globals; no runtime allocation allowed)
// ---------------------------------------------------------------------------
__device__ float  g_u [(size_t)Bsz*Hsz*Lsz];       // current hidden state h (B,H,L) fp32
__device__ float  g_yg[(size_t)Bsz*Hsz*Lsz];       // post-gelu S4D output (B,H,L) f32
__device__ float  g_z [(size_t)Bsz*Hsz*Lsz];       // GLU output + residual (pre-LN)
__device__ float2 g_rT[(size_t)NLs*Hsz*N2s];       // r^T per mode
// bf16 hi/lo operands
__device__ __align__(16) __nv_bfloat16 g_uhi[(size_t)Bsz*Hsz*Lsz];     // u bf16 hi (B,H,L)
__device__ __align__(16) __nv_bfloat16 g_ulo[(size_t)Bsz*Hsz*Lsz];     // u bf16 lo
__device__ __align__(16) __nv_bfloat16 g_Qthi[(size_t)NLs*Hsz*64*Tc];  // Qt[il][h][2n(+1)][j]
__device__ __align__(16) __nv_bfloat16 g_Qtlo[(size_t)NLs*Hsz*64*Tc];
__device__ __align__(16) __nv_bfloat16 g_Mthi[(size_t)NLs*Hsz*Tc*Kt];  // Mt[il][h][j][k]
__device__ __align__(16) __nv_bfloat16 g_Mtlo[(size_t)NLs*Hsz*Tc*Kt];
__device__ __align__(16) __nv_bfloat16 g_Shi[(size_t)Hsz*BCt*64];      // carries [h][bc][k]
__device__ __align__(16) __nv_bfloat16 g_Slo[(size_t)Hsz*BCt*64];
__device__ __align__(16) __nv_bfloat16 g_ygt_hi[(size_t)Bsz*Lsz*Hsz];  // Yt[b*L+l][h]
__device__ __align__(16) __nv_bfloat16 g_ygt_lo[(size_t)Bsz*Lsz*Hsz];
__device__ __align__(16) __nv_bfloat16 g_whi[(size_t)NLs*H2sz*Hsz];
__device__ __align__(16) __nv_bfloat16 g_wlo[(size_t)NLs*H2sz*Hsz];

// ---------------------------------------------------------------------------
// Warp-level MMA helpers (sm_80-era, legal on plain sm_103 target)
// ---------------------------------------------------------------------------
__device__ __forceinline__ uint32_t smem_u32(const void* p) {
    uint32_t a;
    asm("{ .reg .u64 t; cvta.to.shared.u64 t, %1; cvt.u32.u64 %0, t; }" : "=r"(a) : "l"(p));
    return a;
}
__device__ __forceinline__ void ldsm_x4(uint32_t* r, uint32_t addr) {
    asm volatile("ldmatrix.sync.aligned.m8n8.x4.shared.b16 {%0,%1,%2,%3}, [%4];"
        : "=r"(r[0]), "=r"(r[1]), "=r"(r[2]), "=r"(r[3]) : "r"(addr));
}
__device__ __forceinline__ void mma_bf16(float* d, const uint32_t* a, const uint32_t* b) {
    asm volatile("mma.sync.aligned.m16n8k16.row.col.f32.bf16.bf16.f32 "
        "{%0,%1,%2,%3}, {%4,%5,%6,%7}, {%8,%9}, {%0,%1,%2,%3};"
        : "+f"(d[0]), "+f"(d[1]), "+f"(d[2]), "+f"(d[3])
        : "r"(a[0]), "r"(a[1]), "r"(a[2]), "r"(a[3]), "r"(b[0]), "r"(b[1]));
}
__device__ __forceinline__ void split_bf16(float x, __nv_bfloat16& hi, __nv_bfloat16& lo) {
    hi = __float2bfloat16(x);
    lo = __float2bfloat16(x - __bfloat162float(hi));
}

// ---------------------------------------------------------------------------
// Precompute tables per (layer, h).  grid = NL*H blocks, 128 threads.
// Fills g_rT, bf16 Qt[2n/2n+1][j] and transposed bf16 Mt[j][k].
// ---------------------------------------------------------------------------
__global__ void precompute_kernel(const float* __restrict__ log_dt,
                                  const float* __restrict__ log_A_real,
                                  const float* __restrict__ A_imag,
                                  const float* __restrict__ C_re,
                                  const float* __restrict__ C_im)
{
    int ilh = blockIdx.x;
    int il = ilh >> 8;
    int h  = ilh & 255;
    __shared__ float s_dre[N2s], s_dim[N2s], s_Ckr[N2s], s_Cki[N2s];
    __shared__ float s_kc[Tc];

    int tid = threadIdx.x;
    if (tid < N2s) {
        int n = tid;
        float dt = expf(log_dt[il*Hsz + h]);
        size_t idx = ((size_t)il*Hsz + h)*N2s + n;
        float Are = -expf(log_A_real[idx]);
        float Aim = A_imag[idx];
        float dre = Are * dt, dim = Aim * dt;
        float er = expf(dre);
        float sr, cr0; sincosf(dim, &sr, &cr0);
        float rr = er * cr0, ri = er * sr;
        float nr = rr - 1.0f, ni = ri;
        float den = Are*Are + Aim*Aim;
        float qr = (nr*Are + ni*Aim)/den;
        float qi = (ni*Are - nr*Aim)/den;
        float cre = C_re[idx], cim = C_im[idx];
        s_dre[n] = dre; s_dim[n] = dim;
        s_Ckr[n] = cre*qr - cim*qi;
        s_Cki[n] = cre*qi + cim*qr;
        float eT = expf(dre * (float)Tc);
        float sT, cT; sincosf(dim * (float)Tc, &sT, &cT);
        g_rT[((size_t)il*Hsz + h)*N2s + n] = make_float2(eT*cT, eT*sT);
    }
    __syncthreads();

    int j = tid;  // 0..127
    __nv_bfloat16* Qth = g_Qthi + ((size_t)il*Hsz + h)*64*Tc;
    __nv_bfloat16* Qtl = g_Qtlo + ((size_t)il*Hsz + h)*64*Tc;
    __nv_bfloat16* Mh = g_Mthi + (((size_t)il*Hsz + h)*Tc + j)*Kt;
    __nv_bfloat16* Ml = g_Mtlo + (((size_t)il*Hsz + h)*Tc + j)*Kt;
    float ksum = 0.f;
    #pragma unroll 4
    for (int n = 0; n < N2s; n++) {
        float dre = s_dre[n], dim = s_dim[n];
        float Ckr = s_Ckr[n], Cki = s_Cki[n];
        float m1 = (float)(Tc - 1 - j);
        float e1 = expf(dre*m1);
        float s1, c1; sincosf(dim*m1, &s1, &c1);
        __nv_bfloat16 hb, lb;
        split_bf16(e1*c1, hb, lb); Qth[(2*n    )*Tc + j] = hb; Qtl[(2*n    )*Tc + j] = lb;
        split_bf16(e1*s1, hb, lb); Qth[(2*n + 1)*Tc + j] = hb; Qtl[(2*n + 1)*Tc + j] = lb;
        float m2 = (float)(j + 1);
        float e2 = expf(dre*m2);
        float s2, c2; sincosf(dim*m2, &s2, &c2);
        float pr = e2*c2, pi = e2*s2;
        float wr = Ckr*pr - Cki*pi;
        float wi = Ckr*pi + Cki*pr;
        split_bf16( 2.f*wr, hb, lb); Mh[128 + 2*n    ] = hb; Ml[128 + 2*n    ] = lb;
        split_bf16(-2.f*wi, hb, lb); Mh[128 + 2*n + 1] = hb; Ml[128 + 2*n + 1] = lb;
        float m3 = (float)j;
        float e3 = expf(dre*m3);
        float s3, c3; sincosf(dim*m3, &s3, &c3);
        ksum += Ckr*(e3*c3) - Cki*(e3*s3);
    }
    s_kc[j] = 2.f*ksum;
    __syncthreads();

    for (int k = 0; k < Tc; k++) {
        float v = (k <= j) ? s_kc[j - k] : 0.f;
        __nv_bfloat16 hb, lb;
        split_bf16(v, hb, lb);
        Mh[k] = hb; Ml[k] = lb;
    }
}

// ---------------------------------------------------------------------------
// GLU weight hi/lo bf16 split (all layers at once).
// ---------------------------------------------------------------------------
__global__ void wconvert_kernel(const float* __restrict__ glu_w)
{
    int i = blockIdx.x * 256 + threadIdx.x;   // < NLs*H2sz*Hsz = 524288
    float x = glu_w[i];
    __nv_bfloat16 hi, lo;
    split_bf16(x, hi, lo);
    g_whi[i] = hi;
    g_wlo[i] = lo;
}

// ---------------------------------------------------------------------------
// Encoder: g_u[b][h][l] = x[b][l]*enc_w[h] + enc_b[h]  (+ bf16 hi/lo copies)
// ---------------------------------------------------------------------------
__global__ void encoder_kernel(const float* __restrict__ x,
                               const float* __restrict__ ew,
                               const float* __restrict__ eb)
{
    size_t i = (size_t)blockIdx.x * blockDim.x + threadIdx.x;
    int l = (int)(i & (Lsz - 1));
    size_t bh = i >> 12;
    int hh = (int)(bh & (Hsz - 1));
    int b  = (int)(bh >> 8);
    float v = x[(size_t)b*Lsz + l]*ew[hh] + eb[hh];
    g_u[i] = v;
    __nv_bfloat16 hi, lo;
    split_bf16(v, hi, lo);
    g_uhi[i] = hi;
    g_ulo[i] = lo;
}

// ---------------------------------------------------------------------------
// S4D states on mma.sync, fused with inter-chunk scan + carry write-out.
// Per CTA (h, bc-tile of 128): S[bc=128, col=64] = Xu[128,128] . Qt[64,128]^T
//   (col 2n = Re state of mode n, col 2n+1 = Im)
// Then: dump S to smem (transposed), scan c=0..31 per (b_local, n) -> exclusive
// carries, bf16 hi/lo write to g_Shi/g_Slo [h][bc][64].
// 8 warps 4(M:bc) x 2(N:col); warp tile 32x32; K=128 in 4 chunks of 32.
// ---------------------------------------------------------------------------
#define GP 40        // mma smem row pitch in bf16
#define SSC_P 132    // scan buffer pitch (floats)

__global__ __launch_bounds__(256) void s4d_state_mma(int il)
{
    __shared__ __align__(16) char smraw[34048];
    __nv_bfloat16* sAhi = (__nv_bfloat16*)(smraw);            // 128*GP*2 = 10240
    __nv_bfloat16* sAlo = (__nv_bfloat16*)(smraw + 10240);    // 10240
    __nv_bfloat16* sBhi = (__nv_bfloat16*)(smraw + 20480);    // 64*GP*2 = 5120
    __nv_bfloat16* sBlo = (__nv_bfloat16*)(smraw + 25600);    // 5120
    float* Ssc = (float*)smraw;                               // [64][SSC_P] = 33792 (reuse)

    int tid  = threadIdx.x;
    int lane = tid & 31;
    int wid  = tid >> 5;
    int wm   = wid & 3;
    int wn   = wid >> 2;
    int bc0  = blockIdx.x * 128;
    int h    = blockIdx.y;

    uint32_t uAhi = smem_u32(sAhi), uAlo = smem_u32(sAlo);
    uint32_t uBhi = smem_u32(sBhi), uBlo = smem_u32(sBlo);

    float acc[2][4][4];
    #pragma unroll
    for (int mt = 0; mt < 2; mt++)
        #pragma unroll
        for (int nt = 0; nt < 4; nt++)
            #pragma unroll
            for (int q = 0; q < 4; q++) acc[mt][nt][q] = 0.f;

    const __nv_bfloat16* Qtbh = g_Qthi + ((size_t)il*Hsz + h)*64*Tc;
    const __nv_bfloat16* Qtbl = g_Qtlo + ((size_t)il*Hsz + h)*64*Tc;

    for (int c = 0; c < 4; c++) {
        int k0 = c * 32;
        __syncthreads();
        // A tiles: 128 rows x 32 k (hi & lo), 512 uint4 units per array
        #pragma unroll
        for (int t = 0; t < 2; t++) {
            int idx = tid + t*256;
            int r = idx >> 2, i = idx & 3;
            int bc = bc0 + r;
            int b2 = bc >> 5, c2 = bc & 31;
            size_t ga = ((size_t)b2*Hsz + h)*Lsz + c2*Tc + k0 + i*8;
            ((uint4*)sAhi)[r*5 + i] = *(const uint4*)(g_uhi + ga);
            ((uint4*)sAlo)[r*5 + i] = *(const uint4*)(g_ulo + ga);
        }
        // B tiles: 64 rows x 32 k, 256 uint4 units per array
        {
            int r = tid >> 2, i = tid & 3;
            size_t gb = (size_t)r*Tc + k0 + i*8;
            ((uint4*)sBhi)[r*5 + i] = *(const uint4*)(Qtbh + gb);
            ((uint4*)sBlo)[r*5 + i] = *(const uint4*)(Qtbl + gb);
        }
        __syncthreads();

        #pragma unroll
        for (int s = 0; s < 2; s++) {
            int acol = s*16 + ((lane >> 4) << 3);
            int arow0 = wm*32 + (lane & 15);
            int bn = wn*32 + (lane & 7) + (((lane >> 4) & 1) << 3);
            int bk = s*16 + (((lane >> 3) & 1) << 3);

            uint32_t ah[2][4], bh[2][4];
            #pragma unroll
            for (int mt = 0; mt < 2; mt++)
                ldsm_x4(ah[mt], uAhi + (uint32_t)(((arow0 + mt*16)*GP + acol) * 2));
            #pragma unroll
            for (int p = 0; p < 2; p++)
                ldsm_x4(bh[p], uBhi + (uint32_t)(((bn + p*16)*GP + bk) * 2));

            #pragma unroll
            for (int mt = 0; mt < 2; mt++)
                #pragma unroll
                for (int nt = 0; nt < 4; nt++)
                    mma_bf16(acc[mt][nt], ah[mt], &bh[nt >> 1][(nt & 1) * 2]);

            {
                uint32_t al[4];
                #pragma unroll
                for (int mt = 0; mt < 2; mt++) {
                    ldsm_x4(al, uAlo + (uint32_t)(((arow0 + mt*16)*GP + acol) * 2));
                    #pragma unroll
                    for (int nt = 0; nt < 4; nt++)
                        mma_bf16(acc[mt][nt], al, &bh[nt >> 1][(nt & 1) * 2]);
                }
            }
            {
                uint32_t bl[4];
                #pragma unroll
                for (int p = 0; p < 2; p++) {
                    ldsm_x4(bl, uBlo + (uint32_t)(((bn + p*16)*GP + bk) * 2));
                    #pragma unroll
                    for (int mt = 0; mt < 2; mt++) {
                        mma_bf16(acc[mt][2*p    ], ah[mt], &bl[0]);
                        mma_bf16(acc[mt][2*p + 1], ah[mt], &bl[2]);
                    }
                }
            }
        }
    }

    // ---- Dump accumulators to transposed scan buffer Ssc[col][bc_local]
    __syncthreads();   // tiles dead; Ssc aliases them
    #pragma unroll
    for (int mt = 0; mt < 2; mt++) {
        #pragma unroll
        for (int half = 0; half < 2; half++) {
            int rr = wm*32 + (lane >> 2) + half*8 + mt*16;
            #pragma unroll
            for (int nt = 0; nt < 4; nt++) {
                int jc = wn*32 + nt*8 + (lane & 3)*2;
                Ssc[jc*SSC_P + rr]       = acc[mt][nt][half*2 + 0];
                Ssc[(jc + 1)*SSC_P + rr] = acc[mt][nt][half*2 + 1];
            }
        }
    }
    __syncthreads();

    // ---- Inter-chunk scan: thread t<128 handles (b_local = t>>5, mode n = t&31)
    if (tid < 128) {
        int n = tid & 31;
        int bl = tid >> 5;
        float2 rt = g_rT[((size_t)il*Hsz + h)*N2s + n];
        float xr = 0.f, xi = 0.f;
        float* Sr = &Ssc[(2*n    )*SSC_P + bl*32];
        float* Si = &Ssc[(2*n + 1)*SSC_P + bl*32];
        #pragma unroll 4
        for (int c = 0; c < Cc; c++) {
            float sr = Sr[c];
            float si = Si[c];
            Sr[c] = xr;          // exclusive carry
            Si[c] = xi;
            float nxr = fmaf(rt.x, xr, fmaf(-rt.y, xi, sr));
            float nxi = fmaf(rt.x, xi, fmaf( rt.y, xr, si));
            xr = nxr; xi = nxi;
        }
    }
    __syncthreads();

    // ---- Write carries bf16 hi/lo to g_S [h][bc][k]; coalesced 64B per thread
    {
        int r    = tid >> 1;           // bc local 0..127
        int half = tid & 1;            // k half: 0..31 / 32..63
        __nv_bfloat16 vh[32], vl[32];
        #pragma unroll
        for (int i = 0; i < 32; i++) {
            int k = half*32 + i;
            split_bf16(Ssc[k*SSC_P + r], vh[i], vl[i]);
        }
        size_t off = ((size_t)h*BCt + bc0 + r)*64 + half*32;
        #pragma unroll
        for (int i = 0; i < 4; i++) {
            *(uint4*)(g_Shi + off + i*8) = ((uint4*)vh)[i];
            *(uint4*)(g_Slo + off + i*8) = ((uint4*)vl)[i];
        }
    }
}

// ---------------------------------------------------------------------------
// S4D output GEMM on mma.sync (bf16 hi/lo, fp32 accum).
// Per CTA (h, bc-tile of 128): D[bc=128, j=128] = Xt[128,192] . Mt[128,192]^T
// Epilogue: yv = acc + D[h]*u, exact GELU, write g_yg [b][h][l].
// ---------------------------------------------------------------------------
__global__ __launch_bounds__(256) void s4d_out_mma(const float* __restrict__ Dvec, int il)
{
    __shared__ __nv_bfloat16 sAhi[128*GP], sAlo[128*GP], sBhi[128*GP], sBlo[128*GP];

    int tid  = threadIdx.x;
    int lane = tid & 31;
    int wid  = tid >> 5;
    int wm   = wid & 3;
    int wn   = wid >> 2;
    int bc0  = blockIdx.x * 128;
    int h    = blockIdx.y;

    uint32_t uAhi = smem_u32(sAhi), uAlo = smem_u32(sAlo);
    uint32_t uBhi = smem_u32(sBhi), uBlo = smem_u32(sBlo);

    float acc[2][8][4];
    #pragma unroll
    for (int mt = 0; mt < 2; mt++)
        #pragma unroll
        for (int nt = 0; nt < 8; nt++)
            #pragma unroll
            for (int q = 0; q < 4; q++) acc[mt][nt][q] = 0.f;

    const __nv_bfloat16* Mtbh = g_Mthi + ((size_t)il*Hsz + h)*Tc*Kt;
    const __nv_bfloat16* Mtbl = g_Mtlo + ((size_t)il*Hsz + h)*Tc*Kt;

    for (int c = 0; c < 6; c++) {
        int k0 = c * 32;
        __syncthreads();
        #pragma unroll
        for (int t = 0; t < 2; t++) {
            int idx = tid + t*256;
            int r = idx >> 2, i = idx & 3;
            int bc = bc0 + r;
            if (k0 < 128) {
                int b2 = bc >> 5, c2 = bc & 31;
                size_t ga = ((size_t)b2*Hsz + h)*Lsz + c2*Tc + k0 + i*8;
                ((uint4*)sAhi)[r*5 + i] = *(const uint4*)(g_uhi + ga);
                ((uint4*)sAlo)[r*5 + i] = *(const uint4*)(g_ulo + ga);
            } else {
                size_t ga = ((size_t)h*BCt + bc)*64 + (k0 - 128) + i*8;
                ((uint4*)sAhi)[r*5 + i] = *(const uint4*)(g_Shi + ga);
                ((uint4*)sAlo)[r*5 + i] = *(const uint4*)(g_Slo + ga);
            }
            size_t gb = (size_t)r*Kt + k0 + i*8;
            ((uint4*)sBhi)[r*5 + i] = *(const uint4*)(Mtbh + gb);
            ((uint4*)sBlo)[r*5 + i] = *(const uint4*)(Mtbl + gb);
        }
        __syncthreads();

        #pragma unroll
        for (int s = 0; s < 2; s++) {
            int acol = s*16 + ((lane >> 4) << 3);
            int arow0 = wm*32 + (lane & 15);
            int bn = wn*64 + (lane & 7) + (((lane >> 4) & 1) << 3);
            int bk = s*16 + (((lane >> 3) & 1) << 3);

            uint32_t ah[2][4], bh[4][4];
            #pragma unroll
            for (int mt = 0; mt < 2; mt++)
                ldsm_x4(ah[mt], uAhi + (uint32_t)(((arow0 + mt*16)*GP + acol) * 2));
            #pragma unroll
            for (int p = 0; p < 4; p++)
                ldsm_x4(bh[p], uBhi + (uint32_t)(((bn + p*16)*GP + bk) * 2));

            #pragma unroll
            for (int mt = 0; mt < 2; mt++)
                #pragma unroll
                for (int nt = 0; nt < 8; nt++)
                    mma_bf16(acc[mt][nt], ah[mt], &bh[nt >> 1][(nt & 1) * 2]);

            {
                uint32_t al[4];
                #pragma unroll
                for (int mt = 0; mt < 2; mt++) {
                    ldsm_x4(al, uAlo + (uint32_t)(((arow0 + mt*16)*GP + acol) * 2));
                    #pragma unroll
                    for (int nt = 0; nt < 8; nt++)
                        mma_bf16(acc[mt][nt], al, &bh[nt >> 1][(nt & 1) * 2]);
                }
            }
            {
                uint32_t bl[4];
                #pragma unroll
                for (int p = 0; p < 4; p++) {
                    ldsm_x4(bl, uBlo + (uint32_t)(((bn + p*16)*GP + bk) * 2));
                    #pragma unroll
                    for (int mt = 0; mt < 2; mt++) {
                        mma_bf16(acc[mt][2*p    ], ah[mt], &bl[0]);
                        mma_bf16(acc[mt][2*p + 1], ah[mt], &bl[2]);
                    }
                }
            }
        }
    }

    float Dh = Dvec[il*Hsz + h];
    int r0 = wm*32 + (lane >> 2);
    #pragma unroll
    for (int mt = 0; mt < 2; mt++) {
        #pragma unroll
        for (int half = 0; half < 2; half++) {
            int bc = bc0 + r0 + mt*16 + half*8;
            int b2 = bc >> 5, c2 = bc & 31;
            size_t rowbase = ((size_t)b2*Hsz + h)*Lsz + c2*Tc;
            #pragma unroll
            for (int nt = 0; nt < 8; nt++) {
                int j = wn*64 + nt*8 + (lane & 3)*2;
                size_t o = rowbase + j;
                float2 uu = *(const float2*)(g_u + o);
                float y0 = fmaf(Dh, uu.x, acc[mt][nt][half*2 + 0]);
                float y1 = fmaf(Dh, uu.y, acc[mt][nt][half*2 + 1]);
                float2 yo;
                yo.x = 0.5f * y0 * (1.0f + erff(y0 * 0.70710678118654752f));
                yo.y = 0.5f * y1 * (1.0f + erff(y1 * 0.70710678118654752f));
                *(float2*)(g_yg + o) = yo;
            }
        }
    }
}

// ---------------------------------------------------------------------------
// Transpose + bf16 hi/lo convert: g_yg [b][h][l] f32 -> g_ygt_{hi,lo} [b*L+l][h]
// ---------------------------------------------------------------------------
__global__ __launch_bounds__(256) void transpose_convert_kernel()
{
    __shared__ float tile[64][65];
    int b  = blockIdx.z;
    int h0 = blockIdx.y * 64;
    int l0 = blockIdx.x * 64;
    int tid = threadIdx.x;

    const float* src = g_yg + ((size_t)b*Hsz + h0)*Lsz + l0;
    #pragma unroll
    for (int i = 0; i < 4; i++) {
        int idx = tid + i*256;
        int r  = idx >> 4;
        int c4 = (idx & 15) * 4;
        float4 v = *(const float4*)(src + (size_t)r*Lsz + c4);
        tile[r][c4+0]=v.x; tile[r][c4+1]=v.y; tile[r][c4+2]=v.z; tile[r][c4+3]=v.w;
    }
    __syncthreads();

    __nv_bfloat16* dhi = g_ygt_hi + ((size_t)b*Lsz + l0)*Hsz + h0;
    __nv_bfloat16* dlo = g_ygt_lo + ((size_t)b*Lsz + l0)*Hsz + h0;
    #pragma unroll
    for (int i = 0; i < 8; i++) {
        int idx = tid + i*256;
        int lr = idx >> 5;
        int p  = idx & 31;
        float x0 = tile[2*p][lr];
        float x1 = tile[2*p+1][lr];
        __nv_bfloat16 h0b, l0b, h1b, l1b;
        split_bf16(x0, h0b, l0b);
        split_bf16(x1, h1b, l1b);
        __nv_bfloat162 vh; vh.x = h0b; vh.y = h1b;
        __nv_bfloat162 vl; vl.x = l0b; vl.y = l1b;
        ((__nv_bfloat162*)(dhi + (size_t)lr*Hsz))[p] = vh;
        ((__nv_bfloat162*)(dlo + (size_t)lr*Hsz))[p] = vl;
    }
}

// ---------------------------------------------------------------------------
// GLU GEMM on mma.sync tensor cores (bf16 hi/lo split, fp32 accum).
// ---------------------------------------------------------------------------
__global__ __launch_bounds__(256) void glu_mma_kernel(const float* __restrict__ glu_b, int il)
{
    __shared__ __nv_bfloat16 sAhi[128*GP], sAlo[128*GP], sBhi[128*GP], sBlo[128*GP];

    int tid  = threadIdx.x;
    int lane = tid & 31;
    int wid  = tid >> 5;
    int wm   = wid & 3;
    int wn   = wid >> 2;
    int lbase = blockIdx.x * 128;
    int h0    = blockIdx.y * 64;
    int b     = lbase >> 12;

    uint32_t uAhi = smem_u32(sAhi), uAlo = smem_u32(sAlo);
    uint32_t uBhi = smem_u32(sBhi), uBlo = smem_u32(sBlo);

    float acc[2][8][4];
    #pragma unroll
    for (int mt = 0; mt < 2; mt++)
        #pragma unroll
        for (int nt = 0; nt < 8; nt++)
            #pragma unroll
            for (int q = 0; q < 4; q++) acc[mt][nt][q] = 0.f;

    for (int c = 0; c < 8; c++) {
        int k0 = c * 32;
        __syncthreads();
        #pragma unroll
        for (int t = 0; t < 2; t++) {
            int idx = tid + t*256;
            int r = idx >> 2, i = idx & 3;
            size_t ga = (size_t)(lbase + r)*Hsz + k0 + i*8;
            ((uint4*)sAhi)[r*5 + i] = *(const uint4*)(g_ygt_hi + ga);
            ((uint4*)sAlo)[r*5 + i] = *(const uint4*)(g_ygt_lo + ga);
            int i2 = r >> 1;
            int h2row = (r & 1) ? (256 + h0 + i2) : (h0 + i2);
            size_t gb = ((size_t)il*H2sz + h2row)*Hsz + k0 + i*8;
            ((uint4*)sBhi)[r*5 + i] = *(const uint4*)(g_whi + gb);
            ((uint4*)sBlo)[r*5 + i] = *(const uint4*)(g_wlo + gb);
        }
        __syncthreads();

        #pragma unroll
        for (int s = 0; s < 2; s++) {
            int acol = s*16 + ((lane >> 4) << 3);
            int arow0 = wm*32 + (lane & 15);
            int bn = wn*64 + (lane & 7) + (((lane >> 4) & 1) << 3);
            int bk = s*16 + (((lane >> 3) & 1) << 3);

            uint32_t ah[2][4], bh[4][4];
            #pragma unroll
            for (int mt = 0; mt < 2; mt++)
                ldsm_x4(ah[mt], uAhi + (uint32_t)(((arow0 + mt*16)*GP + acol) * 2));
            #pragma unroll
            for (int p = 0; p < 4; p++)
                ldsm_x4(bh[p], uBhi + (uint32_t)(((bn + p*16)*GP + bk) * 2));

            #pragma unroll
            for (int mt = 0; mt < 2; mt++)
                #pragma unroll
                for (int nt = 0; nt < 8; nt++)
                    mma_bf16(acc[mt][nt], ah[mt], &bh[nt >> 1][(nt & 1) * 2]);

            {
                uint32_t al[4];
                #pragma unroll
                for (int mt = 0; mt < 2; mt++) {
                    ldsm_x4(al, uAlo + (uint32_t)(((arow0 + mt*16)*GP + acol) * 2));
                    #pragma unroll
                    for (int nt = 0; nt < 8; nt++)
                        mma_bf16(acc[mt][nt], al, &bh[nt >> 1][(nt & 1) * 2]);
                }
            }
            {
                uint32_t bl[4];
                #pragma unroll
                for (int p = 0; p < 4; p++) {
                    ldsm_x4(bl, uBlo + (uint32_t)(((bn + p*16)*GP + bk) * 2));
                    #pragma unroll
                    for (int mt = 0; mt < 2; mt++) {
                        mma_bf16(acc[mt][2*p    ], ah[mt], &bl[0]);
                        mma_bf16(acc[mt][2*p + 1], ah[mt], &bl[2]);
                    }
                }
            }
        }
    }

    const float* bb = glu_b + (size_t)il * H2sz;
    int lrow0 = (lbase & (Lsz - 1)) + wm*32 + (lane >> 2);
    #pragma unroll
    for (int mt = 0; mt < 2; mt++) {
        int l1 = lrow0 + mt*16;
        #pragma unroll
        for (int nt = 0; nt < 8; nt++) {
            int h = h0 + wn*32 + nt*4 + (lane & 3);
            float ba = bb[h];
            float bg = bb[Hsz + h];
            size_t o1 = ((size_t)b*Hsz + h)*Lsz + l1;
            size_t o2 = o1 + 8;
            float a0 = acc[mt][nt][0] + ba;
            float g0 = acc[mt][nt][1] + bg;
            float a1 = acc[mt][nt][2] + ba;
            float g1 = acc[mt][nt][3] + bg;
            g_z[o1] = fmaf(a0, 1.0f/(1.0f + expf(-g0)), g_u[o1]);
            g_z[o2] = fmaf(a1, 1.0f/(1.0f + expf(-g1)), g_u[o2]);
        }
    }
}

// ---------------------------------------------------------------------------
// LayerNorm over H (postnorm).  reads g_z, writes g_u fp32 + bf16 hi/lo.
// ---------------------------------------------------------------------------
__global__ void layernorm_kernel(const float* __restrict__ ln_g,
                                 const float* __restrict__ ln_b,
                                 int il)
{
    int idx = blockIdx.x * blockDim.x + threadIdx.x;
    int b = idx >> 12;
    int l = idx & (Lsz - 1);
    const float* zb = g_z + (size_t)b*Hsz*Lsz + l;
    float s = 0.f, s2 = 0.f;
    #pragma unroll 4
    for (int hh = 0; hh < Hsz; hh++) {
        float v = zb[(size_t)hh * Lsz];
        s += v; s2 = fmaf(v, v, s2);
    }
    const float invH = 1.0f / (float)Hsz;
    float mu = s * invH;
    float var = s2 * invH - mu*mu;
    float rstd = rsqrtf(var + 1e-5f);
    size_t base = (size_t)b*Hsz*Lsz + l;
    const float* gi = ln_g + il*Hsz;
    const float* bi = ln_b + il*Hsz;
    #pragma unroll 4
    for (int hh = 0; hh < Hsz; hh++) {
        float v = zb[(size_t)hh * Lsz];
        float o = fmaf((v - mu) * rstd, gi[hh], bi[hh]);
        size_t off = base + (size_t)hh * Lsz;
        g_u[off] = o;
        __nv_bfloat16 hi, lo;
        split_bf16(o, hi, lo);
        g_uhi[off] = hi;
        g_ulo[off] = lo;
    }
}

// ---------------------------------------------------------------------------
// Decoder
// ---------------------------------------------------------------------------
__global__ void decoder_kernel(const float* __restrict__ d1w,
                               const float* __restrict__ d1b,
                               const float* __restrict__ d2w,
                               const float* __restrict__ d2b,
                               float* __restrict__ out)
{
    int b = blockIdx.x;
    const float* hb = g_u + (size_t)b*Hsz*Lsz;
    float acc = 0.f;
    for (int i = threadIdx.x; i < Hsz*Lsz; i += blockDim.x) {
        int hh = i >> 12;
        int l  = i & (Lsz - 1);
        acc = fmaf(hb[i], d1w[l] * d2w[hh], acc);
    }
    __shared__ float red[256];
    red[threadIdx.x] = acc;
    __syncthreads();
    for (int s = 128; s > 0; s >>= 1) {
        if (threadIdx.x < s) red[threadIdx.x] += red[threadIdx.x + s];
        __syncthreads();
    }
    if (threadIdx.x == 0) {
        float sw = 0.f;
        for (int hh = 0; hh < Hsz; hh++) sw += d2w[hh];
        float v = red[0] + d1b[0]*sw + d2b[0];
        out[b] = 1.0f / (1.0f + expf(-v));
    }
}

// ---------------------------------------------------------------------------
// Launch
// ---------------------------------------------------------------------------
extern "C" void kernel_launch(void* const* d_in, const int* in_sizes, int n_in,
                              void* d_out, int out_size)
{
    const float* x          = (const float*)d_in[0];
    const float* enc_w      = (const float*)d_in[1];
    const float* enc_b      = (const float*)d_in[2];
    const float* log_dt     = (const float*)d_in[3];
    const float* log_A_real = (const float*)d_in[4];
    const float* A_imag     = (const float*)d_in[5];
    const float* C_re       = (const float*)d_in[6];
    const float* C_im       = (const float*)d_in[7];
    const float* Dv         = (const float*)d_in[8];
    const float* glu_w      = (const float*)d_in[9];
    const float* glu_b      = (const float*)d_in[10];
    const float* ln_g       = (const float*)d_in[11];
    const float* ln_b       = (const float*)d_in[12];
    const float* dec1_w     = (const float*)d_in[13];
    const float* dec1_b     = (const float*)d_in[14];
    const float* dec2_w     = (const float*)d_in[15];
    const float* dec2_b     = (const float*)d_in[16];
    float* out = (float*)d_out;

    // 1) Precompute tables + bf16 weight splits
    precompute_kernel<<<NLs*Hsz, 128>>>(log_dt, log_A_real, A_imag, C_re, C_im);
    wconvert_kernel<<<(NLs*H2sz*Hsz)/256, 256>>>(glu_w);

    // 2) Encoder
    {
        size_t total = (size_t)Bsz*Hsz*Lsz;
        encoder_kernel<<<(unsigned)(total/256), 256>>>(x, enc_w, enc_b);
    }

    // 3) Layers
    for (int il = 0; il < NLs; il++) {
        dim3 sgrid(BCt/128, Hsz);                   // (8, 256)
        s4d_state_mma<<<sgrid, 256>>>(il);
        dim3 ogrid(BCt/128, Hsz);                   // (8, 256)
        s4d_out_mma<<<ogrid, 256>>>(Dv, il);
        dim3 tgrid(Lsz/64, Hsz/64, Bsz);            // (64, 4, 32)
        transpose_convert_kernel<<<tgrid, 256>>>();
        dim3 ggrid((Bsz*Lsz)/128, Hsz/64);          // (1024, 4)
        glu_mma_kernel<<<ggrid, 256>>>(glu_b, il);
        layernorm_kernel<<<(Bsz*Lsz)/256, 256>>>(ln_g, ln_b, il);
    }

    // 4) Decoder
    decoder_kernel<<<Bsz, 256>>>(dec1_w, dec1_b, dec2_w, dec2_b, out);
}

// round 14
// speedup vs baseline: 2.0431x; 1.0787x over previous
#include <cuda_runtime.h>
#include <cuda_bf16.h>
#include <math.h>
#include <stdint.h>

// Problem constants
#define Bsz 32
#define Lsz 4096
#define Hsz 256
#define H2sz 512
#define NLs 4
#define N2s 32
#define Tc  128   // chunk length
#define Cc  32    // chunks per sequence (Tc*Cc == Lsz)
#define Kt  192   // output GEMM K dim: 128 (u taps) + 64 (carry re/im)
#define BCt 1024  // B*Cc
#define PCH 24    // smem tile pitch in bf16 (16 data + 8 pad; 48B rows)

// ---------------------------------------------------------------------------
// Scratch (device globals; no runtime allocation allowed)
// ---------------------------------------------------------------------------
__device__ float  g_u [(size_t)Bsz*Hsz*Lsz];       // current hidden state h (B,H,L) fp32
__device__ float  g_yg[(size_t)Bsz*Hsz*Lsz];       // post-gelu S4D output (B,H,L) f32
__device__ float  g_z [(size_t)Bsz*Hsz*Lsz];       // GLU output + residual (pre-LN)
__device__ float2 g_rT[(size_t)NLs*Hsz*N2s];       // r^T per mode
// bf16 hi/lo operands
__device__ __align__(16) __nv_bfloat16 g_uhi[(size_t)Bsz*Hsz*Lsz];     // u bf16 hi (B,H,L)
__device__ __align__(16) __nv_bfloat16 g_ulo[(size_t)Bsz*Hsz*Lsz];     // u bf16 lo
__device__ __align__(16) __nv_bfloat16 g_Qthi[(size_t)NLs*Hsz*64*Tc];  // Qt[il][h][2n(+1)][j]
__device__ __align__(16) __nv_bfloat16 g_Qtlo[(size_t)NLs*Hsz*64*Tc];
__device__ __align__(16) __nv_bfloat16 g_Mthi[(size_t)NLs*Hsz*Tc*Kt];  // Mt[il][h][j][k]
__device__ __align__(16) __nv_bfloat16 g_Mtlo[(size_t)NLs*Hsz*Tc*Kt];
__device__ __align__(16) __nv_bfloat16 g_Shi[(size_t)Hsz*BCt*64];      // carries [h][bc][k]
__device__ __align__(16) __nv_bfloat16 g_Slo[(size_t)Hsz*BCt*64];
__device__ __align__(16) __nv_bfloat16 g_ygt_hi[(size_t)Bsz*Lsz*Hsz];  // Yt[b*L+l][h]
__device__ __align__(16) __nv_bfloat16 g_ygt_lo[(size_t)Bsz*Lsz*Hsz];
__device__ __align__(16) __nv_bfloat16 g_whi[(size_t)NLs*H2sz*Hsz];
__device__ __align__(16) __nv_bfloat16 g_wlo[(size_t)NLs*H2sz*Hsz];

// ---------------------------------------------------------------------------
// Warp-level MMA + cp.async helpers (sm_80-era, legal on plain sm_103 target)
// ---------------------------------------------------------------------------
__device__ __forceinline__ uint32_t smem_u32(const void* p) {
    uint32_t a;
    asm("{ .reg .u64 t; cvta.to.shared.u64 t, %1; cvt.u32.u64 %0, t; }" : "=r"(a) : "l"(p));
    return a;
}
__device__ __forceinline__ void ldsm_x4(uint32_t* r, uint32_t addr) {
    asm volatile("ldmatrix.sync.aligned.m8n8.x4.shared.b16 {%0,%1,%2,%3}, [%4];"
        : "=r"(r[0]), "=r"(r[1]), "=r"(r[2]), "=r"(r[3]) : "r"(addr));
}
__device__ __forceinline__ void mma_bf16(float* d, const uint32_t* a, const uint32_t* b) {
    asm volatile("mma.sync.aligned.m16n8k16.row.col.f32.bf16.bf16.f32 "
        "{%0,%1,%2,%3}, {%4,%5,%6,%7}, {%8,%9}, {%0,%1,%2,%3};"
        : "+f"(d[0]), "+f"(d[1]), "+f"(d[2]), "+f"(d[3])
        : "r"(a[0]), "r"(a[1]), "r"(a[2]), "r"(a[3]), "r"(b[0]), "r"(b[1]));
}
__device__ __forceinline__ void cp_async16(uint32_t dst, const void* src) {
    asm volatile("cp.async.cg.shared.global [%0], [%1], 16;" :: "r"(dst), "l"(src));
}
__device__ __forceinline__ void cp_commit() { asm volatile("cp.async.commit_group;" ::: "memory"); }
__device__ __forceinline__ void cp_wait1()  { asm volatile("cp.async.wait_group 1;" ::: "memory"); }
__device__ __forceinline__ void cp_wait0()  { asm volatile("cp.async.wait_group 0;" ::: "memory"); }
__device__ __forceinline__ void split_bf16(float x, __nv_bfloat16& hi, __nv_bfloat16& lo) {
    hi = __float2bfloat16(x);
    lo = __float2bfloat16(x - __bfloat162float(hi));
}

// ---------------------------------------------------------------------------
// Precompute tables per (layer, h).  grid = NL*H blocks, 128 threads.
// ---------------------------------------------------------------------------
__global__ void precompute_kernel(const float* __restrict__ log_dt,
                                  const float* __restrict__ log_A_real,
                                  const float* __restrict__ A_imag,
                                  const float* __restrict__ C_re,
                                  const float* __restrict__ C_im)
{
    int ilh = blockIdx.x;
    int il = ilh >> 8;
    int h  = ilh & 255;
    __shared__ float s_dre[N2s], s_dim[N2s], s_Ckr[N2s], s_Cki[N2s];
    __shared__ float s_kc[Tc];

    int tid = threadIdx.x;
    if (tid < N2s) {
        int n = tid;
        float dt = expf(log_dt[il*Hsz + h]);
        size_t idx = ((size_t)il*Hsz + h)*N2s + n;
        float Are = -expf(log_A_real[idx]);
        float Aim = A_imag[idx];
        float dre = Are * dt, dim = Aim * dt;
        float er = expf(dre);
        float sr, cr0; sincosf(dim, &sr, &cr0);
        float rr = er * cr0, ri = er * sr;
        float nr = rr - 1.0f, ni = ri;
        float den = Are*Are + Aim*Aim;
        float qr = (nr*Are + ni*Aim)/den;
        float qi = (ni*Are - nr*Aim)/den;
        float cre = C_re[idx], cim = C_im[idx];
        s_dre[n] = dre; s_dim[n] = dim;
        s_Ckr[n] = cre*qr - cim*qi;
        s_Cki[n] = cre*qi + cim*qr;
        float eT = expf(dre * (float)Tc);
        float sT, cT; sincosf(dim * (float)Tc, &sT, &cT);
        g_rT[((size_t)il*Hsz + h)*N2s + n] = make_float2(eT*cT, eT*sT);
    }
    __syncthreads();

    int j = tid;  // 0..127
    __nv_bfloat16* Qth = g_Qthi + ((size_t)il*Hsz + h)*64*Tc;
    __nv_bfloat16* Qtl = g_Qtlo + ((size_t)il*Hsz + h)*64*Tc;
    __nv_bfloat16* Mh = g_Mthi + (((size_t)il*Hsz + h)*Tc + j)*Kt;
    __nv_bfloat16* Ml = g_Mtlo + (((size_t)il*Hsz + h)*Tc + j)*Kt;
    float ksum = 0.f;
    #pragma unroll 4
    for (int n = 0; n < N2s; n++) {
        float dre = s_dre[n], dim = s_dim[n];
        float Ckr = s_Ckr[n], Cki = s_Cki[n];
        float m1 = (float)(Tc - 1 - j);
        float e1 = expf(dre*m1);
        float s1, c1; sincosf(dim*m1, &s1, &c1);
        __nv_bfloat16 hb, lb;
        split_bf16(e1*c1, hb, lb); Qth[(2*n    )*Tc + j] = hb; Qtl[(2*n    )*Tc + j] = lb;
        split_bf16(e1*s1, hb, lb); Qth[(2*n + 1)*Tc + j] = hb; Qtl[(2*n + 1)*Tc + j] = lb;
        float m2 = (float)(j + 1);
        float e2 = expf(dre*m2);
        float s2, c2; sincosf(dim*m2, &s2, &c2);
        float pr = e2*c2, pi = e2*s2;
        float wr = Ckr*pr - Cki*pi;
        float wi = Ckr*pi + Cki*pr;
        split_bf16( 2.f*wr, hb, lb); Mh[128 + 2*n    ] = hb; Ml[128 + 2*n    ] = lb;
        split_bf16(-2.f*wi, hb, lb); Mh[128 + 2*n + 1] = hb; Ml[128 + 2*n + 1] = lb;
        float m3 = (float)j;
        float e3 = expf(dre*m3);
        float s3, c3; sincosf(dim*m3, &s3, &c3);
        ksum += Ckr*(e3*c3) - Cki*(e3*s3);
    }
    s_kc[j] = 2.f*ksum;
    __syncthreads();

    for (int k = 0; k < Tc; k++) {
        float v = (k <= j) ? s_kc[j - k] : 0.f;
        __nv_bfloat16 hb, lb;
        split_bf16(v, hb, lb);
        Mh[k] = hb; Ml[k] = lb;
    }
}

// ---------------------------------------------------------------------------
// GLU weight hi/lo bf16 split (all layers at once).
// ---------------------------------------------------------------------------
__global__ void wconvert_kernel(const float* __restrict__ glu_w)
{
    int i = blockIdx.x * 256 + threadIdx.x;
    float x = glu_w[i];
    __nv_bfloat16 hi, lo;
    split_bf16(x, hi, lo);
    g_whi[i] = hi;
    g_wlo[i] = lo;
}

// ---------------------------------------------------------------------------
// Encoder: g_u[b][h][l] = x[b][l]*enc_w[h] + enc_b[h]  (+ bf16 hi/lo copies)
// ---------------------------------------------------------------------------
__global__ void encoder_kernel(const float* __restrict__ x,
                               const float* __restrict__ ew,
                               const float* __restrict__ eb)
{
    size_t i = (size_t)blockIdx.x * blockDim.x + threadIdx.x;
    int l = (int)(i & (Lsz - 1));
    size_t bh = i >> 12;
    int hh = (int)(bh & (Hsz - 1));
    int b  = (int)(bh >> 8);
    float v = x[(size_t)b*Lsz + l]*ew[hh] + eb[hh];
    g_u[i] = v;
    __nv_bfloat16 hi, lo;
    split_bf16(v, hi, lo);
    g_uhi[i] = hi;
    g_ulo[i] = lo;
}

// ---------------------------------------------------------------------------
// S4D states on mma.sync (cp.async pipelined), fused scan + carry write-out.
// Per CTA (h, bc-tile of 128): S[bc=128, col=64] = Xu[128,128] . Qt[64,128]^T
// K=128 in 8 chunks of 16, 2-stage cp.async pipeline.
// ---------------------------------------------------------------------------
#define ST_ASZ (128*PCH*2)     // 6144 B
#define ST_BSZ (64*PCH*2)      // 3072 B
#define ST_STAGE (2*ST_ASZ + 2*ST_BSZ)   // 18432
#define SSC_P 132              // scan buffer pitch (floats)

__global__ __launch_bounds__(256) void s4d_state_mma(int il)
{
    __shared__ __align__(16) char smraw[2*ST_STAGE];   // 36864; scan buf aliases
    float* Ssc = (float*)smraw;                        // [64][SSC_P] = 33792

    int tid  = threadIdx.x;
    int lane = tid & 31;
    int wid  = tid >> 5;
    int wm   = wid & 3;
    int wn   = wid >> 2;
    int bc0  = blockIdx.x * 128;
    int h    = blockIdx.y;

    uint32_t sbase = smem_u32(smraw);
    uint32_t uA[2][2], uB[2][2];
    #pragma unroll
    for (int st = 0; st < 2; st++) {
        uA[st][0] = sbase + st*ST_STAGE;
        uA[st][1] = sbase + st*ST_STAGE + ST_ASZ;
        uB[st][0] = sbase + st*ST_STAGE + 2*ST_ASZ;
        uB[st][1] = sbase + st*ST_STAGE + 2*ST_ASZ + ST_BSZ;
    }

    float acc[2][4][4];
    #pragma unroll
    for (int mt = 0; mt < 2; mt++)
        #pragma unroll
        for (int nt = 0; nt < 4; nt++)
            #pragma unroll
            for (int q = 0; q < 4; q++) acc[mt][nt][q] = 0.f;

    // per-thread load indices
    int r = tid >> 1, i = tid & 1;
    int bcr = bc0 + r;
    int b2 = bcr >> 5, c2 = bcr & 31;
    const __nv_bfloat16* gAhi = g_uhi + ((size_t)b2*Hsz + h)*Lsz + c2*Tc + i*8;
    const __nv_bfloat16* gAlo = g_ulo + ((size_t)b2*Hsz + h)*Lsz + c2*Tc + i*8;
    const __nv_bfloat16* gBhi = g_Qthi + ((size_t)il*Hsz + h)*64*Tc + (size_t)r*Tc + i*8;  // r<64 only
    const __nv_bfloat16* gBlo = g_Qtlo + ((size_t)il*Hsz + h)*64*Tc + (size_t)r*Tc + i*8;
    uint32_t doff = (uint32_t)(r*PCH + i*8)*2;

    auto load = [&](int c, int st) {
        int k0 = c*16;
        cp_async16(uA[st][0] + doff, gAhi + k0);
        cp_async16(uA[st][1] + doff, gAlo + k0);
        if (tid < 128) {
            cp_async16(uB[st][0] + doff, gBhi + k0);
            cp_async16(uB[st][1] + doff, gBlo + k0);
        }
        cp_commit();
    };
    auto compute = [&](int st) {
        int acol = ((lane >> 4) << 3);
        int arow0 = wm*32 + (lane & 15);
        int bn = wn*32 + (lane & 7) + (((lane >> 4) & 1) << 3);
        int bkk = ((lane >> 3) & 1) << 3;
        uint32_t ah[2][4], bhf[2][4];
        #pragma unroll
        for (int mt = 0; mt < 2; mt++)
            ldsm_x4(ah[mt], uA[st][0] + (uint32_t)(((arow0 + mt*16)*PCH + acol) * 2));
        #pragma unroll
        for (int p = 0; p < 2; p++)
            ldsm_x4(bhf[p], uB[st][0] + (uint32_t)(((bn + p*16)*PCH + bkk) * 2));
        #pragma unroll
        for (int mt = 0; mt < 2; mt++)
            #pragma unroll
            for (int nt = 0; nt < 4; nt++)
                mma_bf16(acc[mt][nt], ah[mt], &bhf[nt >> 1][(nt & 1) * 2]);
        {
            uint32_t al[4];
            #pragma unroll
            for (int mt = 0; mt < 2; mt++) {
                ldsm_x4(al, uA[st][1] + (uint32_t)(((arow0 + mt*16)*PCH + acol) * 2));
                #pragma unroll
                for (int nt = 0; nt < 4; nt++)
                    mma_bf16(acc[mt][nt], al, &bhf[nt >> 1][(nt & 1) * 2]);
            }
        }
        {
            uint32_t bl[4];
            #pragma unroll
            for (int p = 0; p < 2; p++) {
                ldsm_x4(bl, uB[st][1] + (uint32_t)(((bn + p*16)*PCH + bkk) * 2));
                #pragma unroll
                for (int mt = 0; mt < 2; mt++) {
                    mma_bf16(acc[mt][2*p    ], ah[mt], &bl[0]);
                    mma_bf16(acc[mt][2*p + 1], ah[mt], &bl[2]);
                }
            }
        }
    };

    load(0, 0); load(1, 1);
    #pragma unroll 1
    for (int c = 0; c < 8; c++) {
        if (c + 1 < 8) cp_wait1(); else cp_wait0();
        __syncthreads();
        compute(c & 1);
        __syncthreads();
        if (c + 2 < 8) load(c + 2, c & 1);
    }

    // ---- Dump accumulators to transposed scan buffer Ssc[col][bc_local]
    #pragma unroll
    for (int mt = 0; mt < 2; mt++) {
        #pragma unroll
        for (int half = 0; half < 2; half++) {
            int rr = wm*32 + (lane >> 2) + half*8 + mt*16;
            #pragma unroll
            for (int nt = 0; nt < 4; nt++) {
                int jc = wn*32 + nt*8 + (lane & 3)*2;
                Ssc[jc*SSC_P + rr]       = acc[mt][nt][half*2 + 0];
                Ssc[(jc + 1)*SSC_P + rr] = acc[mt][nt][half*2 + 1];
            }
        }
    }
    __syncthreads();

    // ---- Inter-chunk scan: thread t<128 handles (b_local = t>>5, mode n = t&31)
    if (tid < 128) {
        int n = tid & 31;
        int bl = tid >> 5;
        float2 rt = g_rT[((size_t)il*Hsz + h)*N2s + n];
        float xr = 0.f, xi = 0.f;
        float* Sr = &Ssc[(2*n    )*SSC_P + bl*32];
        float* Si = &Ssc[(2*n + 1)*SSC_P + bl*32];
        #pragma unroll 4
        for (int c = 0; c < Cc; c++) {
            float sr = Sr[c];
            float si = Si[c];
            Sr[c] = xr;
            Si[c] = xi;
            float nxr = fmaf(rt.x, xr, fmaf(-rt.y, xi, sr));
            float nxi = fmaf(rt.x, xi, fmaf( rt.y, xr, si));
            xr = nxr; xi = nxi;
        }
    }
    __syncthreads();

    // ---- Write carries bf16 hi/lo to g_S [h][bc][k]
    {
        int rr   = tid >> 1;
        int half = tid & 1;
        __nv_bfloat16 vh[32], vl[32];
        #pragma unroll
        for (int i2 = 0; i2 < 32; i2++) {
            int k = half*32 + i2;
            split_bf16(Ssc[k*SSC_P + rr], vh[i2], vl[i2]);
        }
        size_t off = ((size_t)h*BCt + bc0 + rr)*64 + half*32;
        #pragma unroll
        for (int i2 = 0; i2 < 4; i2++) {
            *(uint4*)(g_Shi + off + i2*8) = ((uint4*)vh)[i2];
            *(uint4*)(g_Slo + off + i2*8) = ((uint4*)vl)[i2];
        }
    }
}

// ---------------------------------------------------------------------------
// S4D output GEMM on mma.sync (cp.async pipelined, bf16 hi/lo, fp32 accum).
// D[bc=128, j=128] = Xt[128,192] . Mt[128,192]^T, K in 12 chunks of 16.
// Epilogue: yv = acc + D[h]*u, exact GELU, write g_yg [b][h][l].
// ---------------------------------------------------------------------------
#define TL_ASZ (128*PCH*2)             // 6144 B
#define TL_STAGE (4*TL_ASZ)            // 24576

__global__ __launch_bounds__(256) void s4d_out_mma(const float* __restrict__ Dvec, int il)
{
    __shared__ __align__(16) char smraw[2*TL_STAGE];   // 49152 = 48KB

    int tid  = threadIdx.x;
    int lane = tid & 31;
    int wid  = tid >> 5;
    int wm   = wid & 3;
    int wn   = wid >> 2;
    int bc0  = blockIdx.x * 128;
    int h    = blockIdx.y;

    uint32_t sbase = smem_u32(smraw);
    uint32_t uT[2][4];
    #pragma unroll
    for (int st = 0; st < 2; st++)
        #pragma unroll
        for (int a = 0; a < 4; a++)
            uT[st][a] = sbase + st*TL_STAGE + a*TL_ASZ;

    float acc[2][8][4];
    #pragma unroll
    for (int mt = 0; mt < 2; mt++)
        #pragma unroll
        for (int nt = 0; nt < 8; nt++)
            #pragma unroll
            for (int q = 0; q < 4; q++) acc[mt][nt][q] = 0.f;

    int r = tid >> 1, i = tid & 1;
    int bcr = bc0 + r;
    int b2 = bcr >> 5, c2 = bcr & 31;
    const __nv_bfloat16* gAhi_u = g_uhi + ((size_t)b2*Hsz + h)*Lsz + c2*Tc + i*8;
    const __nv_bfloat16* gAlo_u = g_ulo + ((size_t)b2*Hsz + h)*Lsz + c2*Tc + i*8;
    const __nv_bfloat16* gAhi_s = g_Shi + ((size_t)h*BCt + bcr)*64 + i*8;
    const __nv_bfloat16* gAlo_s = g_Slo + ((size_t)h*BCt + bcr)*64 + i*8;
    const __nv_bfloat16* gBhi = g_Mthi + ((size_t)il*Hsz + h)*Tc*Kt + (size_t)r*Kt + i*8;
    const __nv_bfloat16* gBlo = g_Mtlo + ((size_t)il*Hsz + h)*Tc*Kt + (size_t)r*Kt + i*8;
    uint32_t doff = (uint32_t)(r*PCH + i*8)*2;

    auto load = [&](int c, int st) {
        int k0 = c*16;
        if (k0 < 128) {
            cp_async16(uT[st][0] + doff, gAhi_u + k0);
            cp_async16(uT[st][1] + doff, gAlo_u + k0);
        } else {
            cp_async16(uT[st][0] + doff, gAhi_s + (k0 - 128));
            cp_async16(uT[st][1] + doff, gAlo_s + (k0 - 128));
        }
        cp_async16(uT[st][2] + doff, gBhi + k0);
        cp_async16(uT[st][3] + doff, gBlo + k0);
        cp_commit();
    };
    auto compute = [&](int st) {
        int acol = ((lane >> 4) << 3);
        int arow0 = wm*32 + (lane & 15);
        int bn = wn*64 + (lane & 7) + (((lane >> 4) & 1) << 3);
        int bkk = ((lane >> 3) & 1) << 3;
        uint32_t ah[2][4], bhf[4][4];
        #pragma unroll
        for (int mt = 0; mt < 2; mt++)
            ldsm_x4(ah[mt], uT[st][0] + (uint32_t)(((arow0 + mt*16)*PCH + acol) * 2));
        #pragma unroll
        for (int p = 0; p < 4; p++)
            ldsm_x4(bhf[p], uT[st][2] + (uint32_t)(((bn + p*16)*PCH + bkk) * 2));
        #pragma unroll
        for (int mt = 0; mt < 2; mt++)
            #pragma unroll
            for (int nt = 0; nt < 8; nt++)
                mma_bf16(acc[mt][nt], ah[mt], &bhf[nt >> 1][(nt & 1) * 2]);
        {
            uint32_t al[4];
            #pragma unroll
            for (int mt = 0; mt < 2; mt++) {
                ldsm_x4(al, uT[st][1] + (uint32_t)(((arow0 + mt*16)*PCH + acol) * 2));
                #pragma unroll
                for (int nt = 0; nt < 8; nt++)
                    mma_bf16(acc[mt][nt], al, &bhf[nt >> 1][(nt & 1) * 2]);
            }
        }
        {
            uint32_t bl[4];
            #pragma unroll
            for (int p = 0; p < 4; p++) {
                ldsm_x4(bl, uT[st][3] + (uint32_t)(((bn + p*16)*PCH + bkk) * 2));
                #pragma unroll
                for (int mt = 0; mt < 2; mt++) {
                    mma_bf16(acc[mt][2*p    ], ah[mt], &bl[0]);
                    mma_bf16(acc[mt][2*p + 1], ah[mt], &bl[2]);
                }
            }
        }
    };

    load(0, 0); load(1, 1);
    #pragma unroll 1
    for (int c = 0; c < 12; c++) {
        if (c + 1 < 12) cp_wait1(); else cp_wait0();
        __syncthreads();
        compute(c & 1);
        __syncthreads();
        if (c + 2 < 12) load(c + 2, c & 1);
    }

    float Dh = Dvec[il*Hsz + h];
    int r0 = wm*32 + (lane >> 2);
    #pragma unroll
    for (int mt = 0; mt < 2; mt++) {
        #pragma unroll
        for (int half = 0; half < 2; half++) {
            int bc = bc0 + r0 + mt*16 + half*8;
            int bb2 = bc >> 5, cc2 = bc & 31;
            size_t rowbase = ((size_t)bb2*Hsz + h)*Lsz + cc2*Tc;
            #pragma unroll
            for (int nt = 0; nt < 8; nt++) {
                int j = wn*64 + nt*8 + (lane & 3)*2;
                size_t o = rowbase + j;
                float2 uu = *(const float2*)(g_u + o);
                float y0 = fmaf(Dh, uu.x, acc[mt][nt][half*2 + 0]);
                float y1 = fmaf(Dh, uu.y, acc[mt][nt][half*2 + 1]);
                float2 yo;
                yo.x = 0.5f * y0 * (1.0f + erff(y0 * 0.70710678118654752f));
                yo.y = 0.5f * y1 * (1.0f + erff(y1 * 0.70710678118654752f));
                *(float2*)(g_yg + o) = yo;
            }
        }
    }
}

// ---------------------------------------------------------------------------
// Transpose + bf16 hi/lo convert: g_yg [b][h][l] f32 -> g_ygt_{hi,lo} [b*L+l][h]
// ---------------------------------------------------------------------------
__global__ __launch_bounds__(256) void transpose_convert_kernel()
{
    __shared__ float tile[64][65];
    int b  = blockIdx.z;
    int h0 = blockIdx.y * 64;
    int l0 = blockIdx.x * 64;
    int tid = threadIdx.x;

    const float* src = g_yg + ((size_t)b*Hsz + h0)*Lsz + l0;
    #pragma unroll
    for (int i = 0; i < 4; i++) {
        int idx = tid + i*256;
        int r  = idx >> 4;
        int c4 = (idx & 15) * 4;
        float4 v = *(const float4*)(src + (size_t)r*Lsz + c4);
        tile[r][c4+0]=v.x; tile[r][c4+1]=v.y; tile[r][c4+2]=v.z; tile[r][c4+3]=v.w;
    }
    __syncthreads();

    __nv_bfloat16* dhi = g_ygt_hi + ((size_t)b*Lsz + l0)*Hsz + h0;
    __nv_bfloat16* dlo = g_ygt_lo + ((size_t)b*Lsz + l0)*Hsz + h0;
    #pragma unroll
    for (int i = 0; i < 8; i++) {
        int idx = tid + i*256;
        int lr = idx >> 5;
        int p  = idx & 31;
        float x0 = tile[2*p][lr];
        float x1 = tile[2*p+1][lr];
        __nv_bfloat16 h0b, l0b, h1b, l1b;
        split_bf16(x0, h0b, l0b);
        split_bf16(x1, h1b, l1b);
        __nv_bfloat162 vh; vh.x = h0b; vh.y = h1b;
        __nv_bfloat162 vl; vl.x = l0b; vl.y = l1b;
        ((__nv_bfloat162*)(dhi + (size_t)lr*Hsz))[p] = vh;
        ((__nv_bfloat162*)(dlo + (size_t)lr*Hsz))[p] = vl;
    }
}

// ---------------------------------------------------------------------------
// GLU GEMM on mma.sync (cp.async pipelined, bf16 hi/lo split, fp32 accum).
// K=256 in 16 chunks of 16, 2-stage pipeline. Epilogue unchanged.
// ---------------------------------------------------------------------------
__global__ __launch_bounds__(256) void glu_mma_kernel(const float* __restrict__ glu_b, int il)
{
    __shared__ __align__(16) char smraw[2*TL_STAGE];   // 49152 = 48KB

    int tid  = threadIdx.x;
    int lane = tid & 31;
    int wid  = tid >> 5;
    int wm   = wid & 3;
    int wn   = wid >> 2;
    int lbase = blockIdx.x * 128;
    int h0    = blockIdx.y * 64;
    int b     = lbase >> 12;

    uint32_t sbase = smem_u32(smraw);
    uint32_t uT[2][4];
    #pragma unroll
    for (int st = 0; st < 2; st++)
        #pragma unroll
        for (int a = 0; a < 4; a++)
            uT[st][a] = sbase + st*TL_STAGE + a*TL_ASZ;

    float acc[2][8][4];
    #pragma unroll
    for (int mt = 0; mt < 2; mt++)
        #pragma unroll
        for (int nt = 0; nt < 8; nt++)
            #pragma unroll
            for (int q = 0; q < 4; q++) acc[mt][nt][q] = 0.f;

    int r = tid >> 1, i = tid & 1;
    const __nv_bfloat16* gAhi = g_ygt_hi + (size_t)(lbase + r)*Hsz + i*8;
    const __nv_bfloat16* gAlo = g_ygt_lo + (size_t)(lbase + r)*Hsz + i*8;
    int i2 = r >> 1;
    int h2row = (r & 1) ? (256 + h0 + i2) : (h0 + i2);
    const __nv_bfloat16* gBhi = g_whi + ((size_t)il*H2sz + h2row)*Hsz + i*8;
    const __nv_bfloat16* gBlo = g_wlo + ((size_t)il*H2sz + h2row)*Hsz + i*8;
    uint32_t doff = (uint32_t)(r*PCH + i*8)*2;

    auto load = [&](int c, int st) {
        int k0 = c*16;
        cp_async16(uT[st][0] + doff, gAhi + k0);
        cp_async16(uT[st][1] + doff, gAlo + k0);
        cp_async16(uT[st][2] + doff, gBhi + k0);
        cp_async16(uT[st][3] + doff, gBlo + k0);
        cp_commit();
    };
    auto compute = [&](int st) {
        int acol = ((lane >> 4) << 3);
        int arow0 = wm*32 + (lane & 15);
        int bn = wn*64 + (lane & 7) + (((lane >> 4) & 1) << 3);
        int bkk = ((lane >> 3) & 1) << 3;
        uint32_t ah[2][4], bhf[4][4];
        #pragma unroll
        for (int mt = 0; mt < 2; mt++)
            ldsm_x4(ah[mt], uT[st][0] + (uint32_t)(((arow0 + mt*16)*PCH + acol) * 2));
        #pragma unroll
        for (int p = 0; p < 4; p++)
            ldsm_x4(bhf[p], uT[st][2] + (uint32_t)(((bn + p*16)*PCH + bkk) * 2));
        #pragma unroll
        for (int mt = 0; mt < 2; mt++)
            #pragma unroll
            for (int nt = 0; nt < 8; nt++)
                mma_bf16(acc[mt][nt], ah[mt], &bhf[nt >> 1][(nt & 1) * 2]);
        {
            uint32_t al[4];
            #pragma unroll
            for (int mt = 0; mt < 2; mt++) {
                ldsm_x4(al, uT[st][1] + (uint32_t)(((arow0 + mt*16)*PCH + acol) * 2));
                #pragma unroll
                for (int nt = 0; nt < 8; nt++)
                    mma_bf16(acc[mt][nt], al, &bhf[nt >> 1][(nt & 1) * 2]);
            }
        }
        {
            uint32_t bl[4];
            #pragma unroll
            for (int p = 0; p < 4; p++) {
                ldsm_x4(bl, uT[st][3] + (uint32_t)(((bn + p*16)*PCH + bkk) * 2));
                #pragma unroll
                for (int mt = 0; mt < 2; mt++) {
                    mma_bf16(acc[mt][2*p    ], ah[mt], &bl[0]);
                    mma_bf16(acc[mt][2*p + 1], ah[mt], &bl[2]);
                }
            }
        }
    };

    load(0, 0); load(1, 1);
    #pragma unroll 1
    for (int c = 0; c < 16; c++) {
        if (c + 1 < 16) cp_wait1(); else cp_wait0();
        __syncthreads();
        compute(c & 1);
        __syncthreads();
        if (c + 2 < 16) load(c + 2, c & 1);
    }

    const float* bb = glu_b + (size_t)il * H2sz;
    int lrow0 = (lbase & (Lsz - 1)) + wm*32 + (lane >> 2);
    #pragma unroll
    for (int mt = 0; mt < 2; mt++) {
        int l1 = lrow0 + mt*16;
        #pragma unroll
        for (int nt = 0; nt < 8; nt++) {
            int h = h0 + wn*32 + nt*4 + (lane & 3);
            float ba = bb[h];
            float bg = bb[Hsz + h];
            size_t o1 = ((size_t)b*Hsz + h)*Lsz + l1;
            size_t o2 = o1 + 8;
            float a0 = acc[mt][nt][0] + ba;
            float g0 = acc[mt][nt][1] + bg;
            float a1 = acc[mt][nt][2] + ba;
            float g1 = acc[mt][nt][3] + bg;
            g_z[o1] = fmaf(a0, 1.0f/(1.0f + expf(-g0)), g_u[o1]);
            g_z[o2] = fmaf(a1, 1.0f/(1.0f + expf(-g1)), g_u[o2]);
        }
    }
}

// ---------------------------------------------------------------------------
// LayerNorm over H (postnorm).  reads g_z, writes g_u fp32 + bf16 hi/lo.
// ---------------------------------------------------------------------------
__global__ void layernorm_kernel(const float* __restrict__ ln_g,
                                 const float* __restrict__ ln_b,
                                 int il)
{
    int idx = blockIdx.x * blockDim.x + threadIdx.x;
    int b = idx >> 12;
    int l = idx & (Lsz - 1);
    const float* zb = g_z + (size_t)b*Hsz*Lsz + l;
    float s = 0.f, s2 = 0.f;
    #pragma unroll 4
    for (int hh = 0; hh < Hsz; hh++) {
        float v = zb[(size_t)hh * Lsz];
        s += v; s2 = fmaf(v, v, s2);
    }
    const float invH = 1.0f / (float)Hsz;
    float mu = s * invH;
    float var = s2 * invH - mu*mu;
    float rstd = rsqrtf(var + 1e-5f);
    size_t base = (size_t)b*Hsz*Lsz + l;
    const float* gi = ln_g + il*Hsz;
    const float* bi = ln_b + il*Hsz;
    #pragma unroll 4
    for (int hh = 0; hh < Hsz; hh++) {
        float v = zb[(size_t)hh * Lsz];
        float o = fmaf((v - mu) * rstd, gi[hh], bi[hh]);
        size_t off = base + (size_t)hh * Lsz;
        g_u[off] = o;
        __nv_bfloat16 hi, lo;
        split_bf16(o, hi, lo);
        g_uhi[off] = hi;
        g_ulo[off] = lo;
    }
}

// ---------------------------------------------------------------------------
// Decoder
// ---------------------------------------------------------------------------
__global__ void decoder_kernel(const float* __restrict__ d1w,
                               const float* __restrict__ d1b,
                               const float* __restrict__ d2w,
                               const float* __restrict__ d2b,
                               float* __restrict__ out)
{
    int b = blockIdx.x;
    const float* hb = g_u + (size_t)b*Hsz*Lsz;
    float acc = 0.f;
    for (int i = threadIdx.x; i < Hsz*Lsz; i += blockDim.x) {
        int hh = i >> 12;
        int l  = i & (Lsz - 1);
        acc = fmaf(hb[i], d1w[l] * d2w[hh], acc);
    }
    __shared__ float red[256];
    red[threadIdx.x] = acc;
    __syncthreads();
    for (int s = 128; s > 0; s >>= 1) {
        if (threadIdx.x < s) red[threadIdx.x] += red[threadIdx.x + s];
        __syncthreads();
    }
    if (threadIdx.x == 0) {
        float sw = 0.f;
        for (int hh = 0; hh < Hsz; hh++) sw += d2w[hh];
        float v = red[0] + d1b[0]*sw + d2b[0];
        out[b] = 1.0f / (1.0f + expf(-v));
    }
}

// ---------------------------------------------------------------------------
// Launch
// ---------------------------------------------------------------------------
extern "C" void kernel_launch(void* const* d_in, const int* in_sizes, int n_in,
                              void* d_out, int out_size)
{
    const float* x          = (const float*)d_in[0];
    const float* enc_w      = (const float*)d_in[1];
    const float* enc_b      = (const float*)d_in[2];
    const float* log_dt     = (const float*)d_in[3];
    const float* log_A_real = (const float*)d_in[4];
    const float* A_imag     = (const float*)d_in[5];
    const float* C_re       = (const float*)d_in[6];
    const float* C_im       = (const float*)d_in[7];
    const float* Dv         = (const float*)d_in[8];
    const float* glu_w      = (const float*)d_in[9];
    const float* glu_b      = (const float*)d_in[10];
    const float* ln_g       = (const float*)d_in[11];
    const float* ln_b       = (const float*)d_in[12];
    const float* dec1_w     = (const float*)d_in[13];
    const float* dec1_b     = (const float*)d_in[14];
    const float* dec2_w     = (const float*)d_in[15];
    const float* dec2_b     = (const float*)d_in[16];
    float* out = (float*)d_out;

    // 1) Precompute tables + bf16 weight splits
    precompute_kernel<<<NLs*Hsz, 128>>>(log_dt, log_A_real, A_imag, C_re, C_im);
    wconvert_kernel<<<(NLs*H2sz*Hsz)/256, 256>>>(glu_w);

    // 2) Encoder
    {
        size_t total = (size_t)Bsz*Hsz*Lsz;
        encoder_kernel<<<(unsigned)(total/256), 256>>>(x, enc_w, enc_b);
    }

    // 3) Layers
    for (int il = 0; il < NLs; il++) {
        dim3 sgrid(BCt/128, Hsz);                   // (8, 256)
        s4d_state_mma<<<sgrid, 256>>>(il);
        dim3 ogrid(BCt/128, Hsz);                   // (8, 256)
        s4d_out_mma<<<ogrid, 256>>>(Dv, il);
        dim3 tgrid(Lsz/64, Hsz/64, Bsz);            // (64, 4, 32)
        transpose_convert_kernel<<<tgrid, 256>>>();
        dim3 ggrid((Bsz*Lsz)/128, Hsz/64);          // (1024, 4)
        glu_mma_kernel<<<ggrid, 256>>>(glu_b, il);
        layernorm_kernel<<<(Bsz*Lsz)/256, 256>>>(ln_g, ln_b, il);
    }

    // 4) Decoder
    decoder_kernel<<<Bsz, 256>>>(dec1_w, dec1_b, dec2_w, dec2_b, out);
}

// round 15
// speedup vs baseline: 2.3543x; 1.1523x over previous
#include <cuda_runtime.h>
#include <cuda_bf16.h>
#include <math.h>
#include <stdint.h>

// Problem constants
#define Bsz 32
#define Lsz 4096
#define Hsz 256
#define H2sz 512
#define NLs 4
#define N2s 32
#define Tc  128   // chunk length
#define Cc  32    // chunks per sequence (Tc*Cc == Lsz)
#define Kt  192   // output GEMM K dim: 128 (u taps) + 64 (carry re/im)
#define BCt 1024  // B*Cc
#define PCH 24    // smem tile pitch in bf16 (16 data + 8 pad; 48B rows)
#define AP  136   // glu A-tile pitch in bf16 (128 data + 8 pad; 272B rows)

// ---------------------------------------------------------------------------
// Scratch (device globals; no runtime allocation allowed)
// ---------------------------------------------------------------------------
__device__ float  g_u [(size_t)Bsz*Hsz*Lsz];       // current hidden state h (B,H,L) fp32
__device__ float  g_z [(size_t)Bsz*Hsz*Lsz];       // GLU output + residual (pre-LN)
__device__ float2 g_rT[(size_t)NLs*Hsz*N2s];       // r^T per mode
__device__ float  g_dec[256];                      // decoder partials
// bf16 hi/lo operands
__device__ __align__(16) __nv_bfloat16 g_uhi[(size_t)Bsz*Hsz*Lsz];     // u bf16 hi (B,H,L)
__device__ __align__(16) __nv_bfloat16 g_ulo[(size_t)Bsz*Hsz*Lsz];     // u bf16 lo
__device__ __align__(16) __nv_bfloat16 g_yghi[(size_t)Bsz*Hsz*Lsz];    // post-gelu bf16 hi (B,H,L)
__device__ __align__(16) __nv_bfloat16 g_yglo[(size_t)Bsz*Hsz*Lsz];    // post-gelu bf16 lo
__device__ __align__(16) __nv_bfloat16 g_Qthi[(size_t)NLs*Hsz*64*Tc];  // Qt[il][h][2n(+1)][j]
__device__ __align__(16) __nv_bfloat16 g_Qtlo[(size_t)NLs*Hsz*64*Tc];
__device__ __align__(16) __nv_bfloat16 g_Mthi[(size_t)NLs*Hsz*Tc*Kt];  // Mt[il][h][j][k]
__device__ __align__(16) __nv_bfloat16 g_Mtlo[(size_t)NLs*Hsz*Tc*Kt];
__device__ __align__(16) __nv_bfloat16 g_Shi[(size_t)Hsz*BCt*64];      // carries [h][bc][k]
__device__ __align__(16) __nv_bfloat16 g_Slo[(size_t)Hsz*BCt*64];
__device__ __align__(16) __nv_bfloat16 g_whi[(size_t)NLs*H2sz*Hsz];
__device__ __align__(16) __nv_bfloat16 g_wlo[(size_t)NLs*H2sz*Hsz];

// ---------------------------------------------------------------------------
// Warp-level MMA + cp.async helpers (sm_80-era, legal on plain sm_103 target)
// ---------------------------------------------------------------------------
__device__ __forceinline__ uint32_t smem_u32(const void* p) {
    uint32_t a;
    asm("{ .reg .u64 t; cvta.to.shared.u64 t, %1; cvt.u32.u64 %0, t; }" : "=r"(a) : "l"(p));
    return a;
}
__device__ __forceinline__ void ldsm_x4(uint32_t* r, uint32_t addr) {
    asm volatile("ldmatrix.sync.aligned.m8n8.x4.shared.b16 {%0,%1,%2,%3}, [%4];"
        : "=r"(r[0]), "=r"(r[1]), "=r"(r[2]), "=r"(r[3]) : "r"(addr));
}
__device__ __forceinline__ void ldsm_x4_t(uint32_t* r, uint32_t addr) {
    asm volatile("ldmatrix.sync.aligned.m8n8.x4.trans.shared.b16 {%0,%1,%2,%3}, [%4];"
        : "=r"(r[0]), "=r"(r[1]), "=r"(r[2]), "=r"(r[3]) : "r"(addr));
}
__device__ __forceinline__ void mma_bf16(float* d, const uint32_t* a, const uint32_t* b) {
    asm volatile("mma.sync.aligned.m16n8k16.row.col.f32.bf16.bf16.f32 "
        "{%0,%1,%2,%3}, {%4,%5,%6,%7}, {%8,%9}, {%0,%1,%2,%3};"
        : "+f"(d[0]), "+f"(d[1]), "+f"(d[2]), "+f"(d[3])
        : "r"(a[0]), "r"(a[1]), "r"(a[2]), "r"(a[3]), "r"(b[0]), "r"(b[1]));
}
__device__ __forceinline__ void cp_async16(uint32_t dst, const void* src) {
    asm volatile("cp.async.cg.shared.global [%0], [%1], 16;" :: "r"(dst), "l"(src));
}
__device__ __forceinline__ void cp_commit() { asm volatile("cp.async.commit_group;" ::: "memory"); }
__device__ __forceinline__ void cp_wait1()  { asm volatile("cp.async.wait_group 1;" ::: "memory"); }
__device__ __forceinline__ void cp_wait0()  { asm volatile("cp.async.wait_group 0;" ::: "memory"); }
__device__ __forceinline__ void split_bf16(float x, __nv_bfloat16& hi, __nv_bfloat16& lo) {
    hi = __float2bfloat16(x);
    lo = __float2bfloat16(x - __bfloat162float(hi));
}

// ---------------------------------------------------------------------------
// Precompute tables per (layer, h).  grid = NL*H blocks, 128 threads.
// ---------------------------------------------------------------------------
__global__ void precompute_kernel(const float* __restrict__ log_dt,
                                  const float* __restrict__ log_A_real,
                                  const float* __restrict__ A_imag,
                                  const float* __restrict__ C_re,
                                  const float* __restrict__ C_im)
{
    int ilh = blockIdx.x;
    int il = ilh >> 8;
    int h  = ilh & 255;
    __shared__ float s_dre[N2s], s_dim[N2s], s_Ckr[N2s], s_Cki[N2s];
    __shared__ float s_kc[Tc];

    int tid = threadIdx.x;
    if (tid < N2s) {
        int n = tid;
        float dt = expf(log_dt[il*Hsz + h]);
        size_t idx = ((size_t)il*Hsz + h)*N2s + n;
        float Are = -expf(log_A_real[idx]);
        float Aim = A_imag[idx];
        float dre = Are * dt, dim = Aim * dt;
        float er = expf(dre);
        float sr, cr0; sincosf(dim, &sr, &cr0);
        float rr = er * cr0, ri = er * sr;
        float nr = rr - 1.0f, ni = ri;
        float den = Are*Are + Aim*Aim;
        float qr = (nr*Are + ni*Aim)/den;
        float qi = (ni*Are - nr*Aim)/den;
        float cre = C_re[idx], cim = C_im[idx];
        s_dre[n] = dre; s_dim[n] = dim;
        s_Ckr[n] = cre*qr - cim*qi;
        s_Cki[n] = cre*qi + cim*qr;
        float eT = expf(dre * (float)Tc);
        float sT, cT; sincosf(dim * (float)Tc, &sT, &cT);
        g_rT[((size_t)il*Hsz + h)*N2s + n] = make_float2(eT*cT, eT*sT);
    }
    __syncthreads();

    int j = tid;  // 0..127
    __nv_bfloat16* Qth = g_Qthi + ((size_t)il*Hsz + h)*64*Tc;
    __nv_bfloat16* Qtl = g_Qtlo + ((size_t)il*Hsz + h)*64*Tc;
    __nv_bfloat16* Mh = g_Mthi + (((size_t)il*Hsz + h)*Tc + j)*Kt;
    __nv_bfloat16* Ml = g_Mtlo + (((size_t)il*Hsz + h)*Tc + j)*Kt;
    float ksum = 0.f;
    #pragma unroll 4
    for (int n = 0; n < N2s; n++) {
        float dre = s_dre[n], dim = s_dim[n];
        float Ckr = s_Ckr[n], Cki = s_Cki[n];
        float m1 = (float)(Tc - 1 - j);
        float e1 = expf(dre*m1);
        float s1, c1; sincosf(dim*m1, &s1, &c1);
        __nv_bfloat16 hb, lb;
        split_bf16(e1*c1, hb, lb); Qth[(2*n    )*Tc + j] = hb; Qtl[(2*n    )*Tc + j] = lb;
        split_bf16(e1*s1, hb, lb); Qth[(2*n + 1)*Tc + j] = hb; Qtl[(2*n + 1)*Tc + j] = lb;
        float m2 = (float)(j + 1);
        float e2 = expf(dre*m2);
        float s2, c2; sincosf(dim*m2, &s2, &c2);
        float pr = e2*c2, pi = e2*s2;
        float wr = Ckr*pr - Cki*pi;
        float wi = Ckr*pi + Cki*pr;
        split_bf16( 2.f*wr, hb, lb); Mh[128 + 2*n    ] = hb; Ml[128 + 2*n    ] = lb;
        split_bf16(-2.f*wi, hb, lb); Mh[128 + 2*n + 1] = hb; Ml[128 + 2*n + 1] = lb;
        float m3 = (float)j;
        float e3 = expf(dre*m3);
        float s3, c3; sincosf(dim*m3, &s3, &c3);
        ksum += Ckr*(e3*c3) - Cki*(e3*s3);
    }
    s_kc[j] = 2.f*ksum;
    __syncthreads();

    for (int k = 0; k < Tc; k++) {
        float v = (k <= j) ? s_kc[j - k] : 0.f;
        __nv_bfloat16 hb, lb;
        split_bf16(v, hb, lb);
        Mh[k] = hb; Ml[k] = lb;
    }
}

// ---------------------------------------------------------------------------
// GLU weight hi/lo bf16 split (all layers at once).
// ---------------------------------------------------------------------------
__global__ void wconvert_kernel(const float* __restrict__ glu_w)
{
    int i = blockIdx.x * 256 + threadIdx.x;
    float x = glu_w[i];
    __nv_bfloat16 hi, lo;
    split_bf16(x, hi, lo);
    g_whi[i] = hi;
    g_wlo[i] = lo;
}

// ---------------------------------------------------------------------------
// Encoder: g_u[b][h][l] = x[b][l]*enc_w[h] + enc_b[h]  (+ bf16 hi/lo copies)
// ---------------------------------------------------------------------------
__global__ void encoder_kernel(const float* __restrict__ x,
                               const float* __restrict__ ew,
                               const float* __restrict__ eb)
{
    size_t i = (size_t)blockIdx.x * blockDim.x + threadIdx.x;
    int l = (int)(i & (Lsz - 1));
    size_t bh = i >> 12;
    int hh = (int)(bh & (Hsz - 1));
    int b  = (int)(bh >> 8);
    float v = x[(size_t)b*Lsz + l]*ew[hh] + eb[hh];
    g_u[i] = v;
    __nv_bfloat16 hi, lo;
    split_bf16(v, hi, lo);
    g_uhi[i] = hi;
    g_ulo[i] = lo;
}

// ---------------------------------------------------------------------------
// S4D states on mma.sync (cp.async pipelined), fused scan + carry write-out.
// ---------------------------------------------------------------------------
#define ST_ASZ (128*PCH*2)     // 6144 B
#define ST_BSZ (64*PCH*2)      // 3072 B
#define ST_STAGE (2*ST_ASZ + 2*ST_BSZ)   // 18432
#define SSC_P 132              // scan buffer pitch (floats)

__global__ __launch_bounds__(256) void s4d_state_mma(int il)
{
    __shared__ __align__(16) char smraw[2*ST_STAGE];   // 36864; scan buf aliases
    float* Ssc = (float*)smraw;                        // [64][SSC_P] = 33792

    int tid  = threadIdx.x;
    int lane = tid & 31;
    int wid  = tid >> 5;
    int wm   = wid & 3;
    int wn   = wid >> 2;
    int bc0  = blockIdx.x * 128;
    int h    = blockIdx.y;

    uint32_t sbase = smem_u32(smraw);
    uint32_t uA[2][2], uB[2][2];
    #pragma unroll
    for (int st = 0; st < 2; st++) {
        uA[st][0] = sbase + st*ST_STAGE;
        uA[st][1] = sbase + st*ST_STAGE + ST_ASZ;
        uB[st][0] = sbase + st*ST_STAGE + 2*ST_ASZ;
        uB[st][1] = sbase + st*ST_STAGE + 2*ST_ASZ + ST_BSZ;
    }

    float acc[2][4][4];
    #pragma unroll
    for (int mt = 0; mt < 2; mt++)
        #pragma unroll
        for (int nt = 0; nt < 4; nt++)
            #pragma unroll
            for (int q = 0; q < 4; q++) acc[mt][nt][q] = 0.f;

    int r = tid >> 1, i = tid & 1;
    int bcr = bc0 + r;
    int b2 = bcr >> 5, c2 = bcr & 31;
    const __nv_bfloat16* gAhi = g_uhi + ((size_t)b2*Hsz + h)*Lsz + c2*Tc + i*8;
    const __nv_bfloat16* gAlo = g_ulo + ((size_t)b2*Hsz + h)*Lsz + c2*Tc + i*8;
    const __nv_bfloat16* gBhi = g_Qthi + ((size_t)il*Hsz + h)*64*Tc + (size_t)r*Tc + i*8;
    const __nv_bfloat16* gBlo = g_Qtlo + ((size_t)il*Hsz + h)*64*Tc + (size_t)r*Tc + i*8;
    uint32_t doff = (uint32_t)(r*PCH + i*8)*2;

    auto load = [&](int c, int st) {
        int k0 = c*16;
        cp_async16(uA[st][0] + doff, gAhi + k0);
        cp_async16(uA[st][1] + doff, gAlo + k0);
        if (tid < 128) {
            cp_async16(uB[st][0] + doff, gBhi + k0);
            cp_async16(uB[st][1] + doff, gBlo + k0);
        }
        cp_commit();
    };
    auto compute = [&](int st) {
        int acol = ((lane >> 4) << 3);
        int arow0 = wm*32 + (lane & 15);
        int bn = wn*32 + (lane & 7) + (((lane >> 4) & 1) << 3);
        int bkk = ((lane >> 3) & 1) << 3;
        uint32_t ah[2][4], bhf[2][4];
        #pragma unroll
        for (int mt = 0; mt < 2; mt++)
            ldsm_x4(ah[mt], uA[st][0] + (uint32_t)(((arow0 + mt*16)*PCH + acol) * 2));
        #pragma unroll
        for (int p = 0; p < 2; p++)
            ldsm_x4(bhf[p], uB[st][0] + (uint32_t)(((bn + p*16)*PCH + bkk) * 2));
        #pragma unroll
        for (int mt = 0; mt < 2; mt++)
            #pragma unroll
            for (int nt = 0; nt < 4; nt++)
                mma_bf16(acc[mt][nt], ah[mt], &bhf[nt >> 1][(nt & 1) * 2]);
        {
            uint32_t al[4];
            #pragma unroll
            for (int mt = 0; mt < 2; mt++) {
                ldsm_x4(al, uA[st][1] + (uint32_t)(((arow0 + mt*16)*PCH + acol) * 2));
                #pragma unroll
                for (int nt = 0; nt < 4; nt++)
                    mma_bf16(acc[mt][nt], al, &bhf[nt >> 1][(nt & 1) * 2]);
            }
        }
        {
            uint32_t bl[4];
            #pragma unroll
            for (int p = 0; p < 2; p++) {
                ldsm_x4(bl, uB[st][1] + (uint32_t)(((bn + p*16)*PCH + bkk) * 2));
                #pragma unroll
                for (int mt = 0; mt < 2; mt++) {
                    mma_bf16(acc[mt][2*p    ], ah[mt], &bl[0]);
                    mma_bf16(acc[mt][2*p + 1], ah[mt], &bl[2]);
                }
            }
        }
    };

    load(0, 0); load(1, 1);
    #pragma unroll 1
    for (int c = 0; c < 8; c++) {
        if (c + 1 < 8) cp_wait1(); else cp_wait0();
        __syncthreads();
        compute(c & 1);
        __syncthreads();
        if (c + 2 < 8) load(c + 2, c & 1);
    }

    // ---- Dump accumulators to transposed scan buffer Ssc[col][bc_local]
    #pragma unroll
    for (int mt = 0; mt < 2; mt++) {
        #pragma unroll
        for (int half = 0; half < 2; half++) {
            int rr = wm*32 + (lane >> 2) + half*8 + mt*16;
            #pragma unroll
            for (int nt = 0; nt < 4; nt++) {
                int jc = wn*32 + nt*8 + (lane & 3)*2;
                Ssc[jc*SSC_P + rr]       = acc[mt][nt][half*2 + 0];
                Ssc[(jc + 1)*SSC_P + rr] = acc[mt][nt][half*2 + 1];
            }
        }
    }
    __syncthreads();

    // ---- Inter-chunk scan
    if (tid < 128) {
        int n = tid & 31;
        int bl = tid >> 5;
        float2 rt = g_rT[((size_t)il*Hsz + h)*N2s + n];
        float xr = 0.f, xi = 0.f;
        float* Sr = &Ssc[(2*n    )*SSC_P + bl*32];
        float* Si = &Ssc[(2*n + 1)*SSC_P + bl*32];
        #pragma unroll 4
        for (int c = 0; c < Cc; c++) {
            float sr = Sr[c];
            float si = Si[c];
            Sr[c] = xr;
            Si[c] = xi;
            float nxr = fmaf(rt.x, xr, fmaf(-rt.y, xi, sr));
            float nxi = fmaf(rt.x, xi, fmaf( rt.y, xr, si));
            xr = nxr; xi = nxi;
        }
    }
    __syncthreads();

    // ---- Write carries bf16 hi/lo to g_S [h][bc][k]
    {
        int rr   = tid >> 1;
        int half = tid & 1;
        __nv_bfloat16 vh[32], vl[32];
        #pragma unroll
        for (int i2 = 0; i2 < 32; i2++) {
            int k = half*32 + i2;
            split_bf16(Ssc[k*SSC_P + rr], vh[i2], vl[i2]);
        }
        size_t off = ((size_t)h*BCt + bc0 + rr)*64 + half*32;
        #pragma unroll
        for (int i2 = 0; i2 < 4; i2++) {
            *(uint4*)(g_Shi + off + i2*8) = ((uint4*)vh)[i2];
            *(uint4*)(g_Slo + off + i2*8) = ((uint4*)vl)[i2];
        }
    }
}

// ---------------------------------------------------------------------------
// S4D output GEMM on mma.sync (cp.async pipelined, bf16 hi/lo, fp32 accum).
// D[bc=128, j=128] = Xt[128,192] . Mt[128,192]^T, K in 12 chunks of 16.
// Epilogue: yv = acc + D[h]*u, exact GELU, write bf16 hi/lo g_yg [b][h][l].
// ---------------------------------------------------------------------------
#define TL_ASZ (128*PCH*2)             // 6144 B
#define TL_STAGE (4*TL_ASZ)            // 24576

__global__ __launch_bounds__(256) void s4d_out_mma(const float* __restrict__ Dvec, int il)
{
    __shared__ __align__(16) char smraw[2*TL_STAGE];   // 49152 = 48KB

    int tid  = threadIdx.x;
    int lane = tid & 31;
    int wid  = tid >> 5;
    int wm   = wid & 3;
    int wn   = wid >> 2;
    int bc0  = blockIdx.x * 128;
    int h    = blockIdx.y;

    uint32_t sbase = smem_u32(smraw);
    uint32_t uT[2][4];
    #pragma unroll
    for (int st = 0; st < 2; st++)
        #pragma unroll
        for (int a = 0; a < 4; a++)
            uT[st][a] = sbase + st*TL_STAGE + a*TL_ASZ;

    float acc[2][8][4];
    #pragma unroll
    for (int mt = 0; mt < 2; mt++)
        #pragma unroll
        for (int nt = 0; nt < 8; nt++)
            #pragma unroll
            for (int q = 0; q < 4; q++) acc[mt][nt][q] = 0.f;

    int r = tid >> 1, i = tid & 1;
    int bcr = bc0 + r;
    int b2 = bcr >> 5, c2 = bcr & 31;
    const __nv_bfloat16* gAhi_u = g_uhi + ((size_t)b2*Hsz + h)*Lsz + c2*Tc + i*8;
    const __nv_bfloat16* gAlo_u = g_ulo + ((size_t)b2*Hsz + h)*Lsz + c2*Tc + i*8;
    const __nv_bfloat16* gAhi_s = g_Shi + ((size_t)h*BCt + bcr)*64 + i*8;
    const __nv_bfloat16* gAlo_s = g_Slo + ((size_t)h*BCt + bcr)*64 + i*8;
    const __nv_bfloat16* gBhi = g_Mthi + ((size_t)il*Hsz + h)*Tc*Kt + (size_t)r*Kt + i*8;
    const __nv_bfloat16* gBlo = g_Mtlo + ((size_t)il*Hsz + h)*Tc*Kt + (size_t)r*Kt + i*8;
    uint32_t doff = (uint32_t)(r*PCH + i*8)*2;

    auto load = [&](int c, int st) {
        int k0 = c*16;
        if (k0 < 128) {
            cp_async16(uT[st][0] + doff, gAhi_u + k0);
            cp_async16(uT[st][1] + doff, gAlo_u + k0);
        } else {
            cp_async16(uT[st][0] + doff, gAhi_s + (k0 - 128));
            cp_async16(uT[st][1] + doff, gAlo_s + (k0 - 128));
        }
        cp_async16(uT[st][2] + doff, gBhi + k0);
        cp_async16(uT[st][3] + doff, gBlo + k0);
        cp_commit();
    };
    auto compute = [&](int st) {
        int acol = ((lane >> 4) << 3);
        int arow0 = wm*32 + (lane & 15);
        int bn = wn*64 + (lane & 7) + (((lane >> 4) & 1) << 3);
        int bkk = ((lane >> 3) & 1) << 3;
        uint32_t ah[2][4], bhf[4][4];
        #pragma unroll
        for (int mt = 0; mt < 2; mt++)
            ldsm_x4(ah[mt], uT[st][0] + (uint32_t)(((arow0 + mt*16)*PCH + acol) * 2));
        #pragma unroll
        for (int p = 0; p < 4; p++)
            ldsm_x4(bhf[p], uT[st][2] + (uint32_t)(((bn + p*16)*PCH + bkk) * 2));
        #pragma unroll
        for (int mt = 0; mt < 2; mt++)
            #pragma unroll
            for (int nt = 0; nt < 8; nt++)
                mma_bf16(acc[mt][nt], ah[mt], &bhf[nt >> 1][(nt & 1) * 2]);
        {
            uint32_t al[4];
            #pragma unroll
            for (int mt = 0; mt < 2; mt++) {
                ldsm_x4(al, uT[st][1] + (uint32_t)(((arow0 + mt*16)*PCH + acol) * 2));
                #pragma unroll
                for (int nt = 0; nt < 8; nt++)
                    mma_bf16(acc[mt][nt], al, &bhf[nt >> 1][(nt & 1) * 2]);
            }
        }
        {
            uint32_t bl[4];
            #pragma unroll
            for (int p = 0; p < 4; p++) {
                ldsm_x4(bl, uT[st][3] + (uint32_t)(((bn + p*16)*PCH + bkk) * 2));
                #pragma unroll
                for (int mt = 0; mt < 2; mt++) {
                    mma_bf16(acc[mt][2*p    ], ah[mt], &bl[0]);
                    mma_bf16(acc[mt][2*p + 1], ah[mt], &bl[2]);
                }
            }
        }
    };

    load(0, 0); load(1, 1);
    #pragma unroll 1
    for (int c = 0; c < 12; c++) {
        if (c + 1 < 12) cp_wait1(); else cp_wait0();
        __syncthreads();
        compute(c & 1);
        __syncthreads();
        if (c + 2 < 12) load(c + 2, c & 1);
    }

    float Dh = Dvec[il*Hsz + h];
    int r0 = wm*32 + (lane >> 2);
    #pragma unroll
    for (int mt = 0; mt < 2; mt++) {
        #pragma unroll
        for (int half = 0; half < 2; half++) {
            int bc = bc0 + r0 + mt*16 + half*8;
            int bb2 = bc >> 5, cc2 = bc & 31;
            size_t rowbase = ((size_t)bb2*Hsz + h)*Lsz + cc2*Tc;
            #pragma unroll
            for (int nt = 0; nt < 8; nt++) {
                int j = wn*64 + nt*8 + (lane & 3)*2;
                size_t o = rowbase + j;
                float2 uu = *(const float2*)(g_u + o);
                float y0 = fmaf(Dh, uu.x, acc[mt][nt][half*2 + 0]);
                float y1 = fmaf(Dh, uu.y, acc[mt][nt][half*2 + 1]);
                y0 = 0.5f * y0 * (1.0f + erff(y0 * 0.70710678118654752f));
                y1 = 0.5f * y1 * (1.0f + erff(y1 * 0.70710678118654752f));
                __nv_bfloat16 h0b, l0b, h1b, l1b;
                split_bf16(y0, h0b, l0b);
                split_bf16(y1, h1b, l1b);
                __nv_bfloat162 vh; vh.x = h0b; vh.y = h1b;
                __nv_bfloat162 vl; vl.x = l0b; vl.y = l1b;
                *(__nv_bfloat162*)(g_yghi + o) = vh;
                *(__nv_bfloat162*)(g_yglo + o) = vl;
            }
        }
    }
}

// ---------------------------------------------------------------------------
// GLU GEMM on mma.sync (cp.async pipelined, bf16 hi/lo split, fp32 accum).
// A consumed directly from g_yghi/lo [b][h][l] via ldmatrix.trans (no transpose
// kernel). A chunk = 16 h-rows x 128 l-cols, pitch AP. B unchanged.
// ---------------------------------------------------------------------------
#define GA_SZ (16*AP*2)                 // 4352 B
#define GB_SZ (128*PCH*2)               // 6144 B
#define G_STAGE (2*GA_SZ + 2*GB_SZ)     // 20992

__global__ __launch_bounds__(256) void glu_mma_kernel(const float* __restrict__ glu_b, int il)
{
    __shared__ __align__(16) char smraw[2*G_STAGE];   // 41984

    int tid  = threadIdx.x;
    int lane = tid & 31;
    int wid  = tid >> 5;
    int wm   = wid & 3;
    int wn   = wid >> 2;
    int lbase = blockIdx.x * 128;      // flat b*L + l
    int h0    = blockIdx.y * 64;
    int b     = lbase >> 12;
    int lb    = lbase & (Lsz - 1);

    uint32_t sbase = smem_u32(smraw);
    uint32_t uA[2][2], uB[2][2];
    #pragma unroll
    for (int st = 0; st < 2; st++) {
        uA[st][0] = sbase + st*G_STAGE;
        uA[st][1] = sbase + st*G_STAGE + GA_SZ;
        uB[st][0] = sbase + st*G_STAGE + 2*GA_SZ;
        uB[st][1] = sbase + st*G_STAGE + 2*GA_SZ + GB_SZ;
    }

    float acc[2][8][4];
    #pragma unroll
    for (int mt = 0; mt < 2; mt++)
        #pragma unroll
        for (int nt = 0; nt < 8; nt++)
            #pragma unroll
            for (int q = 0; q < 4; q++) acc[mt][nt][q] = 0.f;

    // A loads: row = h-in-chunk (tid>>4), cu = l-unit (tid&15)
    int arow = tid >> 4, acu = tid & 15;
    size_t gAbase = ((size_t)b*Hsz + arow)*Lsz + lb + acu*8;   // + k0*Lsz per chunk
    uint32_t doffA = (uint32_t)(arow*AP + acu*8)*2;
    // B loads: r = tid>>1 (W row within tile), i = tid&1
    int r = tid >> 1, i = tid & 1;
    int i2 = r >> 1;
    int h2row = (r & 1) ? (256 + h0 + i2) : (h0 + i2);
    const __nv_bfloat16* gBhi = g_whi + ((size_t)il*H2sz + h2row)*Hsz + i*8;
    const __nv_bfloat16* gBlo = g_wlo + ((size_t)il*H2sz + h2row)*Hsz + i*8;
    uint32_t doffB = (uint32_t)(r*PCH + i*8)*2;

    auto load = [&](int c, int st) {
        int k0 = c*16;
        size_t ga = gAbase + (size_t)k0*Lsz;
        cp_async16(uA[st][0] + doffA, g_yghi + ga);
        cp_async16(uA[st][1] + doffA, g_yglo + ga);
        cp_async16(uB[st][0] + doffB, gBhi + k0);
        cp_async16(uB[st][1] + doffB, gBlo + k0);
        cp_commit();
    };
    auto compute = [&](int st) {
        // A via ldmatrix.trans from [k][m] storage:
        //   addr row = (lane&7) + ((lane>>4)&1)*8, col = m0 + ((lane>>3)&1)*8
        int atr = (lane & 7) + (((lane >> 4) & 1) << 3);
        int atc = ((lane >> 3) & 1) << 3;
        int bn = wn*64 + (lane & 7) + (((lane >> 4) & 1) << 3);
        int bkk = ((lane >> 3) & 1) << 3;
        uint32_t ah[2][4], bhf[4][4];
        #pragma unroll
        for (int mt = 0; mt < 2; mt++) {
            int m0 = wm*32 + mt*16;
            ldsm_x4_t(ah[mt], uA[st][0] + (uint32_t)((atr*AP + m0 + atc) * 2));
        }
        #pragma unroll
        for (int p = 0; p < 4; p++)
            ldsm_x4(bhf[p], uB[st][0] + (uint32_t)(((bn + p*16)*PCH + bkk) * 2));
        #pragma unroll
        for (int mt = 0; mt < 2; mt++)
            #pragma unroll
            for (int nt = 0; nt < 8; nt++)
                mma_bf16(acc[mt][nt], ah[mt], &bhf[nt >> 1][(nt & 1) * 2]);
        {
            uint32_t al[4];
            #pragma unroll
            for (int mt = 0; mt < 2; mt++) {
                int m0 = wm*32 + mt*16;
                ldsm_x4_t(al, uA[st][1] + (uint32_t)((atr*AP + m0 + atc) * 2));
                #pragma unroll
                for (int nt = 0; nt < 8; nt++)
                    mma_bf16(acc[mt][nt], al, &bhf[nt >> 1][(nt & 1) * 2]);
            }
        }
        {
            uint32_t bl[4];
            #pragma unroll
            for (int p = 0; p < 4; p++) {
                ldsm_x4(bl, uB[st][1] + (uint32_t)(((bn + p*16)*PCH + bkk) * 2));
                #pragma unroll
                for (int mt = 0; mt < 2; mt++) {
                    mma_bf16(acc[mt][2*p    ], ah[mt], &bl[0]);
                    mma_bf16(acc[mt][2*p + 1], ah[mt], &bl[2]);
                }
            }
        }
    };

    load(0, 0); load(1, 1);
    #pragma unroll 1
    for (int c = 0; c < 16; c++) {
        if (c + 1 < 16) cp_wait1(); else cp_wait0();
        __syncthreads();
        compute(c & 1);
        __syncthreads();
        if (c + 2 < 16) load(c + 2, c & 1);
    }

    const float* bb = glu_b + (size_t)il * H2sz;
    int lrow0 = lb + wm*32 + (lane >> 2);
    #pragma unroll
    for (int mt = 0; mt < 2; mt++) {
        int l1 = lrow0 + mt*16;
        #pragma unroll
        for (int nt = 0; nt < 8; nt++) {
            int h = h0 + wn*32 + nt*4 + (lane & 3);
            float ba = bb[h];
            float bg = bb[Hsz + h];
            size_t o1 = ((size_t)b*Hsz + h)*Lsz + l1;
            size_t o2 = o1 + 8;
            float a0 = acc[mt][nt][0] + ba;
            float g0 = acc[mt][nt][1] + bg;
            float a1 = acc[mt][nt][2] + ba;
            float g1 = acc[mt][nt][3] + bg;
            g_z[o1] = fmaf(a0, 1.0f/(1.0f + expf(-g0)), g_u[o1]);
            g_z[o2] = fmaf(a1, 1.0f/(1.0f + expf(-g1)), g_u[o2]);
        }
    }
}

// ---------------------------------------------------------------------------
// LayerNorm over H (postnorm).  reads g_z, writes g_u fp32 + bf16 hi/lo.
// ---------------------------------------------------------------------------
__global__ void layernorm_kernel(const float* __restrict__ ln_g,
                                 const float* __restrict__ ln_b,
                                 int il)
{
    int idx = blockIdx.x * blockDim.x + threadIdx.x;
    int b = idx >> 12;
    int l = idx & (Lsz - 1);
    const float* zb = g_z + (size_t)b*Hsz*Lsz + l;
    float s = 0.f, s2 = 0.f;
    #pragma unroll 4
    for (int hh = 0; hh < Hsz; hh++) {
        float v = zb[(size_t)hh * Lsz];
        s += v; s2 = fmaf(v, v, s2);
    }
    const float invH = 1.0f / (float)Hsz;
    float mu = s * invH;
    float var = s2 * invH - mu*mu;
    float rstd = rsqrtf(var + 1e-5f);
    size_t base = (size_t)b*Hsz*Lsz + l;
    const float* gi = ln_g + il*Hsz;
    const float* bi = ln_b + il*Hsz;
    #pragma unroll 4
    for (int hh = 0; hh < Hsz; hh++) {
        float v = zb[(size_t)hh * Lsz];
        float o = fmaf((v - mu) * rstd, gi[hh], bi[hh]);
        size_t off = base + (size_t)hh * Lsz;
        g_u[off] = o;
        __nv_bfloat16 hi, lo;
        split_bf16(o, hi, lo);
        g_uhi[off] = hi;
        g_ulo[off] = lo;
    }
}

// ---------------------------------------------------------------------------
// Decoder: 256-block partial reduction + tiny finisher (deterministic).
// ---------------------------------------------------------------------------
__global__ void decoder_partial(const float* __restrict__ d1w,
                                const float* __restrict__ d2w)
{
    int blk = blockIdx.x;        // 0..255
    int b = blk >> 3, s = blk & 7;
    const float* hb = g_u + ((size_t)b*Hsz + s*32)*Lsz;
    const float* w2 = d2w + s*32;
    float acc = 0.f;
    for (int i = threadIdx.x; i < 32*Lsz; i += 256) {
        int hh = i >> 12;
        int l  = i & (Lsz - 1);
        acc = fmaf(hb[(size_t)hh*Lsz + l], d1w[l] * w2[hh], acc);
    }
    __shared__ float red[256];
    red[threadIdx.x] = acc;
    __syncthreads();
    for (int st = 128; st > 0; st >>= 1) {
        if (threadIdx.x < st) red[threadIdx.x] += red[threadIdx.x + st];
        __syncthreads();
    }
    if (threadIdx.x == 0) g_dec[blk] = red[0];
}

__global__ void decoder_final(const float* __restrict__ d1b,
                              const float* __restrict__ d2w,
                              const float* __restrict__ d2b,
                              float* __restrict__ out)
{
    int b = threadIdx.x;   // 32 threads
    if (b < Bsz) {
        float v = 0.f;
        #pragma unroll
        for (int s = 0; s < 8; s++) v += g_dec[b*8 + s];
        float sw = 0.f;
        for (int hh = 0; hh < Hsz; hh++) sw += d2w[hh];
        v += d1b[0]*sw + d2b[0];
        out[b] = 1.0f / (1.0f + expf(-v));
    }
}

// ---------------------------------------------------------------------------
// Launch
// ---------------------------------------------------------------------------
extern "C" void kernel_launch(void* const* d_in, const int* in_sizes, int n_in,
                              void* d_out, int out_size)
{
    const float* x          = (const float*)d_in[0];
    const float* enc_w      = (const float*)d_in[1];
    const float* enc_b      = (const float*)d_in[2];
    const float* log_dt     = (const float*)d_in[3];
    const float* log_A_real = (const float*)d_in[4];
    const float* A_imag     = (const float*)d_in[5];
    const float* C_re       = (const float*)d_in[6];
    const float* C_im       = (const float*)d_in[7];
    const float* Dv         = (const float*)d_in[8];
    const float* glu_w      = (const float*)d_in[9];
    const float* glu_b      = (const float*)d_in[10];
    const float* ln_g       = (const float*)d_in[11];
    const float* ln_b       = (const float*)d_in[12];
    const float* dec1_w     = (const float*)d_in[13];
    const float* dec1_b     = (const float*)d_in[14];
    const float* dec2_w     = (const float*)d_in[15];
    const float* dec2_b     = (const float*)d_in[16];
    float* out = (float*)d_out;

    // 1) Precompute tables + bf16 weight splits
    precompute_kernel<<<NLs*Hsz, 128>>>(log_dt, log_A_real, A_imag, C_re, C_im);
    wconvert_kernel<<<(NLs*H2sz*Hsz)/256, 256>>>(glu_w);

    // 2) Encoder
    {
        size_t total = (size_t)Bsz*Hsz*Lsz;
        encoder_kernel<<<(unsigned)(total/256), 256>>>(x, enc_w, enc_b);
    }

    // 3) Layers
    for (int il = 0; il < NLs; il++) {
        dim3 sgrid(BCt/128, Hsz);                   // (8, 256)
        s4d_state_mma<<<sgrid, 256>>>(il);
        dim3 ogrid(BCt/128, Hsz);                   // (8, 256)
        s4d_out_mma<<<ogrid, 256>>>(Dv, il);
        dim3 ggrid((Bsz*Lsz)/128, Hsz/64);          // (1024, 4)
        glu_mma_kernel<<<ggrid, 256>>>(glu_b, il);
        layernorm_kernel<<<(Bsz*Lsz)/256, 256>>>(ln_g, ln_b, il);
    }

    // 4) Decoder
    decoder_partial<<<256, 256>>>(dec1_w, dec2_w);
    decoder_final<<<1, 32>>>(dec1_b, dec2_w, dec2_b, out);
}

// round 16
// speedup vs baseline: 2.3903x; 1.0153x over previous
#include <cuda_runtime.h>
#include <cuda_bf16.h>
#include <math.h>
#include <stdint.h>

// Problem constants
#define Bsz 32
#define Lsz 4096
#define Hsz 256
#define H2sz 512
#define NLs 4
#define N2s 32
#define Tc  128   // chunk length
#define Cc  32    // chunks per sequence (Tc*Cc == Lsz)
#define Kt  192   // output GEMM K dim: 128 (u taps) + 64 (carry re/im)
#define BCt 1024  // B*Cc
#define PCH 24    // smem tile pitch in bf16 (16 data + 8 pad; 48B rows)
#define AP  136   // glu A-tile pitch in bf16 (128 data + 8 pad; 272B rows)

// ---------------------------------------------------------------------------
// Scratch (device globals; no runtime allocation allowed)
// ---------------------------------------------------------------------------
__device__ float  g_u [(size_t)Bsz*Hsz*Lsz];       // current hidden state h (B,H,L) fp32
__device__ float  g_z [(size_t)Bsz*Hsz*Lsz];       // GLU output + residual (pre-LN)
__device__ float2 g_rT[(size_t)NLs*Hsz*N2s];       // r^T per mode
__device__ float  g_dec[256];                      // decoder partials
// bf16 hi/lo operands
__device__ __align__(16) __nv_bfloat16 g_uhi[(size_t)Bsz*Hsz*Lsz];     // u bf16 hi (B,H,L)
__device__ __align__(16) __nv_bfloat16 g_ulo[(size_t)Bsz*Hsz*Lsz];     // u bf16 lo
__device__ __align__(16) __nv_bfloat16 g_yghi[(size_t)Bsz*Hsz*Lsz];    // post-gelu bf16 hi (B,H,L)
__device__ __align__(16) __nv_bfloat16 g_yglo[(size_t)Bsz*Hsz*Lsz];    // post-gelu bf16 lo
__device__ __align__(16) __nv_bfloat16 g_Qthi[(size_t)NLs*Hsz*64*Tc];  // Qt[il][h][2n(+1)][j]
__device__ __align__(16) __nv_bfloat16 g_Qtlo[(size_t)NLs*Hsz*64*Tc];
__device__ __align__(16) __nv_bfloat16 g_Mthi[(size_t)NLs*Hsz*Tc*Kt];  // Mt[il][h][j][k]
__device__ __align__(16) __nv_bfloat16 g_Mtlo[(size_t)NLs*Hsz*Tc*Kt];
__device__ __align__(16) __nv_bfloat16 g_Shi[(size_t)Hsz*BCt*64];      // carries [h][bc][k]
__device__ __align__(16) __nv_bfloat16 g_Slo[(size_t)Hsz*BCt*64];
__device__ __align__(16) __nv_bfloat16 g_whi[(size_t)NLs*H2sz*Hsz];
__device__ __align__(16) __nv_bfloat16 g_wlo[(size_t)NLs*H2sz*Hsz];

// ---------------------------------------------------------------------------
// Warp-level MMA + cp.async helpers (sm_80-era, legal on plain sm_103 target)
// ---------------------------------------------------------------------------
__device__ __forceinline__ uint32_t smem_u32(const void* p) {
    uint32_t a;
    asm("{ .reg .u64 t; cvta.to.shared.u64 t, %1; cvt.u32.u64 %0, t; }" : "=r"(a) : "l"(p));
    return a;
}
__device__ __forceinline__ void ldsm_x4(uint32_t* r, uint32_t addr) {
    asm volatile("ldmatrix.sync.aligned.m8n8.x4.shared.b16 {%0,%1,%2,%3}, [%4];"
        : "=r"(r[0]), "=r"(r[1]), "=r"(r[2]), "=r"(r[3]) : "r"(addr));
}
__device__ __forceinline__ void ldsm_x4_t(uint32_t* r, uint32_t addr) {
    asm volatile("ldmatrix.sync.aligned.m8n8.x4.trans.shared.b16 {%0,%1,%2,%3}, [%4];"
        : "=r"(r[0]), "=r"(r[1]), "=r"(r[2]), "=r"(r[3]) : "r"(addr));
}
__device__ __forceinline__ void mma_bf16(float* d, const uint32_t* a, const uint32_t* b) {
    asm volatile("mma.sync.aligned.m16n8k16.row.col.f32.bf16.bf16.f32 "
        "{%0,%1,%2,%3}, {%4,%5,%6,%7}, {%8,%9}, {%0,%1,%2,%3};"
        : "+f"(d[0]), "+f"(d[1]), "+f"(d[2]), "+f"(d[3])
        : "r"(a[0]), "r"(a[1]), "r"(a[2]), "r"(a[3]), "r"(b[0]), "r"(b[1]));
}
__device__ __forceinline__ void cp_async16(uint32_t dst, const void* src) {
    asm volatile("cp.async.cg.shared.global [%0], [%1], 16;" :: "r"(dst), "l"(src));
}
__device__ __forceinline__ void cp_commit() { asm volatile("cp.async.commit_group;" ::: "memory"); }
__device__ __forceinline__ void cp_wait1()  { asm volatile("cp.async.wait_group 1;" ::: "memory"); }
__device__ __forceinline__ void cp_wait0()  { asm volatile("cp.async.wait_group 0;" ::: "memory"); }
__device__ __forceinline__ void split_bf16(float x, __nv_bfloat16& hi, __nv_bfloat16& lo) {
    hi = __float2bfloat16(x);
    lo = __float2bfloat16(x - __bfloat162float(hi));
}

// ---------------------------------------------------------------------------
// Precompute tables per (layer, h).  grid = NL*H blocks, 128 threads.
// ---------------------------------------------------------------------------
__global__ void precompute_kernel(const float* __restrict__ log_dt,
                                  const float* __restrict__ log_A_real,
                                  const float* __restrict__ A_imag,
                                  const float* __restrict__ C_re,
                                  const float* __restrict__ C_im)
{
    int ilh = blockIdx.x;
    int il = ilh >> 8;
    int h  = ilh & 255;
    __shared__ float s_dre[N2s], s_dim[N2s], s_Ckr[N2s], s_Cki[N2s];
    __shared__ float s_kc[Tc];

    int tid = threadIdx.x;
    if (tid < N2s) {
        int n = tid;
        float dt = expf(log_dt[il*Hsz + h]);
        size_t idx = ((size_t)il*Hsz + h)*N2s + n;
        float Are = -expf(log_A_real[idx]);
        float Aim = A_imag[idx];
        float dre = Are * dt, dim = Aim * dt;
        float er = expf(dre);
        float sr, cr0; sincosf(dim, &sr, &cr0);
        float rr = er * cr0, ri = er * sr;
        float nr = rr - 1.0f, ni = ri;
        float den = Are*Are + Aim*Aim;
        float qr = (nr*Are + ni*Aim)/den;
        float qi = (ni*Are - nr*Aim)/den;
        float cre = C_re[idx], cim = C_im[idx];
        s_dre[n] = dre; s_dim[n] = dim;
        s_Ckr[n] = cre*qr - cim*qi;
        s_Cki[n] = cre*qi + cim*qr;
        float eT = expf(dre * (float)Tc);
        float sT, cT; sincosf(dim * (float)Tc, &sT, &cT);
        g_rT[((size_t)il*Hsz + h)*N2s + n] = make_float2(eT*cT, eT*sT);
    }
    __syncthreads();

    int j = tid;  // 0..127
    __nv_bfloat16* Qth = g_Qthi + ((size_t)il*Hsz + h)*64*Tc;
    __nv_bfloat16* Qtl = g_Qtlo + ((size_t)il*Hsz + h)*64*Tc;
    __nv_bfloat16* Mh = g_Mthi + (((size_t)il*Hsz + h)*Tc + j)*Kt;
    __nv_bfloat16* Ml = g_Mtlo + (((size_t)il*Hsz + h)*Tc + j)*Kt;
    float ksum = 0.f;
    #pragma unroll 4
    for (int n = 0; n < N2s; n++) {
        float dre = s_dre[n], dim = s_dim[n];
        float Ckr = s_Ckr[n], Cki = s_Cki[n];
        float m1 = (float)(Tc - 1 - j);
        float e1 = expf(dre*m1);
        float s1, c1; sincosf(dim*m1, &s1, &c1);
        __nv_bfloat16 hb, lb;
        split_bf16(e1*c1, hb, lb); Qth[(2*n    )*Tc + j] = hb; Qtl[(2*n    )*Tc + j] = lb;
        split_bf16(e1*s1, hb, lb); Qth[(2*n + 1)*Tc + j] = hb; Qtl[(2*n + 1)*Tc + j] = lb;
        float m2 = (float)(j + 1);
        float e2 = expf(dre*m2);
        float s2, c2; sincosf(dim*m2, &s2, &c2);
        float pr = e2*c2, pi = e2*s2;
        float wr = Ckr*pr - Cki*pi;
        float wi = Ckr*pi + Cki*pr;
        split_bf16( 2.f*wr, hb, lb); Mh[128 + 2*n    ] = hb; Ml[128 + 2*n    ] = lb;
        split_bf16(-2.f*wi, hb, lb); Mh[128 + 2*n + 1] = hb; Ml[128 + 2*n + 1] = lb;
        float m3 = (float)j;
        float e3 = expf(dre*m3);
        float s3, c3; sincosf(dim*m3, &s3, &c3);
        ksum += Ckr*(e3*c3) - Cki*(e3*s3);
    }
    s_kc[j] = 2.f*ksum;
    __syncthreads();

    for (int k = 0; k < Tc; k++) {
        float v = (k <= j) ? s_kc[j - k] : 0.f;
        __nv_bfloat16 hb, lb;
        split_bf16(v, hb, lb);
        Mh[k] = hb; Ml[k] = lb;
    }
}

// ---------------------------------------------------------------------------
// GLU weight hi/lo bf16 split (all layers at once).
// ---------------------------------------------------------------------------
__global__ void wconvert_kernel(const float* __restrict__ glu_w)
{
    int i = blockIdx.x * 256 + threadIdx.x;
    float x = glu_w[i];
    __nv_bfloat16 hi, lo;
    split_bf16(x, hi, lo);
    g_whi[i] = hi;
    g_wlo[i] = lo;
}

// ---------------------------------------------------------------------------
// Encoder: g_u[b][h][l] = x[b][l]*enc_w[h] + enc_b[h]  (+ bf16 hi/lo copies)
// ---------------------------------------------------------------------------
__global__ void encoder_kernel(const float* __restrict__ x,
                               const float* __restrict__ ew,
                               const float* __restrict__ eb)
{
    size_t i = (size_t)blockIdx.x * blockDim.x + threadIdx.x;
    int l = (int)(i & (Lsz - 1));
    size_t bh = i >> 12;
    int hh = (int)(bh & (Hsz - 1));
    int b  = (int)(bh >> 8);
    float v = x[(size_t)b*Lsz + l]*ew[hh] + eb[hh];
    g_u[i] = v;
    __nv_bfloat16 hi, lo;
    split_bf16(v, hi, lo);
    g_uhi[i] = hi;
    g_ulo[i] = lo;
}

// ---------------------------------------------------------------------------
// S4D states on mma.sync (cp.async pipelined), fused scan + carry write-out.
// ---------------------------------------------------------------------------
#define ST_ASZ (128*PCH*2)     // 6144 B
#define ST_BSZ (64*PCH*2)      // 3072 B
#define ST_STAGE (2*ST_ASZ + 2*ST_BSZ)   // 18432
#define SSC_P 132              // scan buffer pitch (floats)

__global__ __launch_bounds__(256) void s4d_state_mma(int il)
{
    __shared__ __align__(16) char smraw[2*ST_STAGE];   // 36864; scan buf aliases
    float* Ssc = (float*)smraw;                        // [64][SSC_P] = 33792

    int tid  = threadIdx.x;
    int lane = tid & 31;
    int wid  = tid >> 5;
    int wm   = wid & 3;
    int wn   = wid >> 2;
    int bc0  = blockIdx.x * 128;
    int h    = blockIdx.y;

    uint32_t sbase = smem_u32(smraw);
    uint32_t uA[2][2], uB[2][2];
    #pragma unroll
    for (int st = 0; st < 2; st++) {
        uA[st][0] = sbase + st*ST_STAGE;
        uA[st][1] = sbase + st*ST_STAGE + ST_ASZ;
        uB[st][0] = sbase + st*ST_STAGE + 2*ST_ASZ;
        uB[st][1] = sbase + st*ST_STAGE + 2*ST_ASZ + ST_BSZ;
    }

    float acc[2][4][4];
    #pragma unroll
    for (int mt = 0; mt < 2; mt++)
        #pragma unroll
        for (int nt = 0; nt < 4; nt++)
            #pragma unroll
            for (int q = 0; q < 4; q++) acc[mt][nt][q] = 0.f;

    int r = tid >> 1, i = tid & 1;
    int bcr = bc0 + r;
    int b2 = bcr >> 5, c2 = bcr & 31;
    const __nv_bfloat16* gAhi = g_uhi + ((size_t)b2*Hsz + h)*Lsz + c2*Tc + i*8;
    const __nv_bfloat16* gAlo = g_ulo + ((size_t)b2*Hsz + h)*Lsz + c2*Tc + i*8;
    const __nv_bfloat16* gBhi = g_Qthi + ((size_t)il*Hsz + h)*64*Tc + (size_t)r*Tc + i*8;
    const __nv_bfloat16* gBlo = g_Qtlo + ((size_t)il*Hsz + h)*64*Tc + (size_t)r*Tc + i*8;
    uint32_t doff = (uint32_t)(r*PCH + i*8)*2;

    auto load = [&](int c, int st) {
        int k0 = c*16;
        cp_async16(uA[st][0] + doff, gAhi + k0);
        cp_async16(uA[st][1] + doff, gAlo + k0);
        if (tid < 128) {
            cp_async16(uB[st][0] + doff, gBhi + k0);
            cp_async16(uB[st][1] + doff, gBlo + k0);
        }
        cp_commit();
    };
    auto compute = [&](int st) {
        int acol = ((lane >> 4) << 3);
        int arow0 = wm*32 + (lane & 15);
        int bn = wn*32 + (lane & 7) + (((lane >> 4) & 1) << 3);
        int bkk = ((lane >> 3) & 1) << 3;
        uint32_t ah[2][4], bhf[2][4];
        #pragma unroll
        for (int mt = 0; mt < 2; mt++)
            ldsm_x4(ah[mt], uA[st][0] + (uint32_t)(((arow0 + mt*16)*PCH + acol) * 2));
        #pragma unroll
        for (int p = 0; p < 2; p++)
            ldsm_x4(bhf[p], uB[st][0] + (uint32_t)(((bn + p*16)*PCH + bkk) * 2));
        #pragma unroll
        for (int mt = 0; mt < 2; mt++)
            #pragma unroll
            for (int nt = 0; nt < 4; nt++)
                mma_bf16(acc[mt][nt], ah[mt], &bhf[nt >> 1][(nt & 1) * 2]);
        {
            uint32_t al[4];
            #pragma unroll
            for (int mt = 0; mt < 2; mt++) {
                ldsm_x4(al, uA[st][1] + (uint32_t)(((arow0 + mt*16)*PCH + acol) * 2));
                #pragma unroll
                for (int nt = 0; nt < 4; nt++)
                    mma_bf16(acc[mt][nt], al, &bhf[nt >> 1][(nt & 1) * 2]);
            }
        }
        {
            uint32_t bl[4];
            #pragma unroll
            for (int p = 0; p < 2; p++) {
                ldsm_x4(bl, uB[st][1] + (uint32_t)(((bn + p*16)*PCH + bkk) * 2));
                #pragma unroll
                for (int mt = 0; mt < 2; mt++) {
                    mma_bf16(acc[mt][2*p    ], ah[mt], &bl[0]);
                    mma_bf16(acc[mt][2*p + 1], ah[mt], &bl[2]);
                }
            }
        }
    };

    load(0, 0); load(1, 1);
    #pragma unroll 1
    for (int c = 0; c < 8; c++) {
        if (c + 1 < 8) cp_wait1(); else cp_wait0();
        __syncthreads();
        compute(c & 1);
        __syncthreads();
        if (c + 2 < 8) load(c + 2, c & 1);
    }

    // ---- Dump accumulators to transposed scan buffer Ssc[col][bc_local]
    #pragma unroll
    for (int mt = 0; mt < 2; mt++) {
        #pragma unroll
        for (int half = 0; half < 2; half++) {
            int rr = wm*32 + (lane >> 2) + half*8 + mt*16;
            #pragma unroll
            for (int nt = 0; nt < 4; nt++) {
                int jc = wn*32 + nt*8 + (lane & 3)*2;
                Ssc[jc*SSC_P + rr]       = acc[mt][nt][half*2 + 0];
                Ssc[(jc + 1)*SSC_P + rr] = acc[mt][nt][half*2 + 1];
            }
        }
    }
    __syncthreads();

    // ---- Inter-chunk scan
    if (tid < 128) {
        int n = tid & 31;
        int bl = tid >> 5;
        float2 rt = g_rT[((size_t)il*Hsz + h)*N2s + n];
        float xr = 0.f, xi = 0.f;
        float* Sr = &Ssc[(2*n    )*SSC_P + bl*32];
        float* Si = &Ssc[(2*n + 1)*SSC_P + bl*32];
        #pragma unroll 4
        for (int c = 0; c < Cc; c++) {
            float sr = Sr[c];
            float si = Si[c];
            Sr[c] = xr;
            Si[c] = xi;
            float nxr = fmaf(rt.x, xr, fmaf(-rt.y, xi, sr));
            float nxi = fmaf(rt.x, xi, fmaf( rt.y, xr, si));
            xr = nxr; xi = nxi;
        }
    }
    __syncthreads();

    // ---- Write carries bf16 hi/lo to g_S [h][bc][k]
    {
        int rr   = tid >> 1;
        int half = tid & 1;
        __nv_bfloat16 vh[32], vl[32];
        #pragma unroll
        for (int i2 = 0; i2 < 32; i2++) {
            int k = half*32 + i2;
            split_bf16(Ssc[k*SSC_P + rr], vh[i2], vl[i2]);
        }
        size_t off = ((size_t)h*BCt + bc0 + rr)*64 + half*32;
        #pragma unroll
        for (int i2 = 0; i2 < 4; i2++) {
            *(uint4*)(g_Shi + off + i2*8) = ((uint4*)vh)[i2];
            *(uint4*)(g_Slo + off + i2*8) = ((uint4*)vl)[i2];
        }
    }
}

// ---------------------------------------------------------------------------
// S4D output GEMM on mma.sync (cp.async pipelined, bf16 hi/lo, fp32 accum).
// D[bc=128, j=128] = Xt[128,192] . Mt[128,192]^T, K in 12 chunks of 16.
// Epilogue: yv = acc + D[h]*u, exact GELU, write bf16 hi/lo g_yg [b][h][l].
// ---------------------------------------------------------------------------
#define TL_ASZ (128*PCH*2)             // 6144 B
#define TL_STAGE (4*TL_ASZ)            // 24576

__global__ __launch_bounds__(256) void s4d_out_mma(const float* __restrict__ Dvec, int il)
{
    __shared__ __align__(16) char smraw[2*TL_STAGE];   // 49152 = 48KB

    int tid  = threadIdx.x;
    int lane = tid & 31;
    int wid  = tid >> 5;
    int wm   = wid & 3;
    int wn   = wid >> 2;
    int bc0  = blockIdx.x * 128;
    int h    = blockIdx.y;

    uint32_t sbase = smem_u32(smraw);
    uint32_t uT[2][4];
    #pragma unroll
    for (int st = 0; st < 2; st++)
        #pragma unroll
        for (int a = 0; a < 4; a++)
            uT[st][a] = sbase + st*TL_STAGE + a*TL_ASZ;

    float acc[2][8][4];
    #pragma unroll
    for (int mt = 0; mt < 2; mt++)
        #pragma unroll
        for (int nt = 0; nt < 8; nt++)
            #pragma unroll
            for (int q = 0; q < 4; q++) acc[mt][nt][q] = 0.f;

    int r = tid >> 1, i = tid & 1;
    int bcr = bc0 + r;
    int b2 = bcr >> 5, c2 = bcr & 31;
    const __nv_bfloat16* gAhi_u = g_uhi + ((size_t)b2*Hsz + h)*Lsz + c2*Tc + i*8;
    const __nv_bfloat16* gAlo_u = g_ulo + ((size_t)b2*Hsz + h)*Lsz + c2*Tc + i*8;
    const __nv_bfloat16* gAhi_s = g_Shi + ((size_t)h*BCt + bcr)*64 + i*8;
    const __nv_bfloat16* gAlo_s = g_Slo + ((size_t)h*BCt + bcr)*64 + i*8;
    const __nv_bfloat16* gBhi = g_Mthi + ((size_t)il*Hsz + h)*Tc*Kt + (size_t)r*Kt + i*8;
    const __nv_bfloat16* gBlo = g_Mtlo + ((size_t)il*Hsz + h)*Tc*Kt + (size_t)r*Kt + i*8;
    uint32_t doff = (uint32_t)(r*PCH + i*8)*2;

    auto load = [&](int c, int st) {
        int k0 = c*16;
        if (k0 < 128) {
            cp_async16(uT[st][0] + doff, gAhi_u + k0);
            cp_async16(uT[st][1] + doff, gAlo_u + k0);
        } else {
            cp_async16(uT[st][0] + doff, gAhi_s + (k0 - 128));
            cp_async16(uT[st][1] + doff, gAlo_s + (k0 - 128));
        }
        cp_async16(uT[st][2] + doff, gBhi + k0);
        cp_async16(uT[st][3] + doff, gBlo + k0);
        cp_commit();
    };
    auto compute = [&](int st) {
        int acol = ((lane >> 4) << 3);
        int arow0 = wm*32 + (lane & 15);
        int bn = wn*64 + (lane & 7) + (((lane >> 4) & 1) << 3);
        int bkk = ((lane >> 3) & 1) << 3;
        uint32_t ah[2][4], bhf[4][4];
        #pragma unroll
        for (int mt = 0; mt < 2; mt++)
            ldsm_x4(ah[mt], uT[st][0] + (uint32_t)(((arow0 + mt*16)*PCH + acol) * 2));
        #pragma unroll
        for (int p = 0; p < 4; p++)
            ldsm_x4(bhf[p], uT[st][2] + (uint32_t)(((bn + p*16)*PCH + bkk) * 2));
        #pragma unroll
        for (int mt = 0; mt < 2; mt++)
            #pragma unroll
            for (int nt = 0; nt < 8; nt++)
                mma_bf16(acc[mt][nt], ah[mt], &bhf[nt >> 1][(nt & 1) * 2]);
        {
            uint32_t al[4];
            #pragma unroll
            for (int mt = 0; mt < 2; mt++) {
                ldsm_x4(al, uT[st][1] + (uint32_t)(((arow0 + mt*16)*PCH + acol) * 2));
                #pragma unroll
                for (int nt = 0; nt < 8; nt++)
                    mma_bf16(acc[mt][nt], al, &bhf[nt >> 1][(nt & 1) * 2]);
            }
        }
        {
            uint32_t bl[4];
            #pragma unroll
            for (int p = 0; p < 4; p++) {
                ldsm_x4(bl, uT[st][3] + (uint32_t)(((bn + p*16)*PCH + bkk) * 2));
                #pragma unroll
                for (int mt = 0; mt < 2; mt++) {
                    mma_bf16(acc[mt][2*p    ], ah[mt], &bl[0]);
                    mma_bf16(acc[mt][2*p + 1], ah[mt], &bl[2]);
                }
            }
        }
    };

    load(0, 0); load(1, 1);
    #pragma unroll 1
    for (int c = 0; c < 12; c++) {
        if (c + 1 < 12) cp_wait1(); else cp_wait0();
        __syncthreads();
        compute(c & 1);
        __syncthreads();
        if (c + 2 < 12) load(c + 2, c & 1);
    }

    float Dh = Dvec[il*Hsz + h];
    int r0 = wm*32 + (lane >> 2);
    #pragma unroll
    for (int mt = 0; mt < 2; mt++) {
        #pragma unroll
        for (int half = 0; half < 2; half++) {
            int bc = bc0 + r0 + mt*16 + half*8;
            int bb2 = bc >> 5, cc2 = bc & 31;
            size_t rowbase = ((size_t)bb2*Hsz + h)*Lsz + cc2*Tc;
            #pragma unroll
            for (int nt = 0; nt < 8; nt++) {
                int j = wn*64 + nt*8 + (lane & 3)*2;
                size_t o = rowbase + j;
                float2 uu = *(const float2*)(g_u + o);
                float y0 = fmaf(Dh, uu.x, acc[mt][nt][half*2 + 0]);
                float y1 = fmaf(Dh, uu.y, acc[mt][nt][half*2 + 1]);
                y0 = 0.5f * y0 * (1.0f + erff(y0 * 0.70710678118654752f));
                y1 = 0.5f * y1 * (1.0f + erff(y1 * 0.70710678118654752f));
                __nv_bfloat16 h0b, l0b, h1b, l1b;
                split_bf16(y0, h0b, l0b);
                split_bf16(y1, h1b, l1b);
                __nv_bfloat162 vh; vh.x = h0b; vh.y = h1b;
                __nv_bfloat162 vl; vl.x = l0b; vl.y = l1b;
                *(__nv_bfloat162*)(g_yghi + o) = vh;
                *(__nv_bfloat162*)(g_yglo + o) = vl;
            }
        }
    }
}

// ---------------------------------------------------------------------------
// GLU GEMM on mma.sync (cp.async pipelined, bf16 hi/lo split, fp32 accum).
// A consumed directly from g_yghi/lo [b][h][l] via ldmatrix.trans.
// GRID: x = h0-tile (4, fastest) , y = l-tile (1024) -> the 4 CTAs sharing an
// l-tile are consecutive block IDs, so the yg A-tiles hit L2 instead of DRAM.
// ---------------------------------------------------------------------------
#define GA_SZ (16*AP*2)                 // 4352 B
#define GB_SZ (128*PCH*2)               // 6144 B
#define G_STAGE (2*GA_SZ + 2*GB_SZ)     // 20992

__global__ __launch_bounds__(256) void glu_mma_kernel(const float* __restrict__ glu_b, int il)
{
    __shared__ __align__(16) char smraw[2*G_STAGE];   // 41984

    int tid  = threadIdx.x;
    int lane = tid & 31;
    int wid  = tid >> 5;
    int wm   = wid & 3;
    int wn   = wid >> 2;
    int lbase = blockIdx.y * 128;      // flat b*L + l
    int h0    = blockIdx.x * 64;
    int b     = lbase >> 12;
    int lb    = lbase & (Lsz - 1);

    uint32_t sbase = smem_u32(smraw);
    uint32_t uA[2][2], uB[2][2];
    #pragma unroll
    for (int st = 0; st < 2; st++) {
        uA[st][0] = sbase + st*G_STAGE;
        uA[st][1] = sbase + st*G_STAGE + GA_SZ;
        uB[st][0] = sbase + st*G_STAGE + 2*GA_SZ;
        uB[st][1] = sbase + st*G_STAGE + 2*GA_SZ + GB_SZ;
    }

    float acc[2][8][4];
    #pragma unroll
    for (int mt = 0; mt < 2; mt++)
        #pragma unroll
        for (int nt = 0; nt < 8; nt++)
            #pragma unroll
            for (int q = 0; q < 4; q++) acc[mt][nt][q] = 0.f;

    // A loads: row = h-in-chunk (tid>>4), cu = l-unit (tid&15)
    int arow = tid >> 4, acu = tid & 15;
    size_t gAbase = ((size_t)b*Hsz + arow)*Lsz + lb + acu*8;   // + k0*Lsz per chunk
    uint32_t doffA = (uint32_t)(arow*AP + acu*8)*2;
    // B loads: r = tid>>1 (W row within tile), i = tid&1
    int r = tid >> 1, i = tid & 1;
    int i2 = r >> 1;
    int h2row = (r & 1) ? (256 + h0 + i2) : (h0 + i2);
    const __nv_bfloat16* gBhi = g_whi + ((size_t)il*H2sz + h2row)*Hsz + i*8;
    const __nv_bfloat16* gBlo = g_wlo + ((size_t)il*H2sz + h2row)*Hsz + i*8;
    uint32_t doffB = (uint32_t)(r*PCH + i*8)*2;

    auto load = [&](int c, int st) {
        int k0 = c*16;
        size_t ga = gAbase + (size_t)k0*Lsz;
        cp_async16(uA[st][0] + doffA, g_yghi + ga);
        cp_async16(uA[st][1] + doffA, g_yglo + ga);
        cp_async16(uB[st][0] + doffB, gBhi + k0);
        cp_async16(uB[st][1] + doffB, gBlo + k0);
        cp_commit();
    };
    auto compute = [&](int st) {
        int atr = (lane & 7) + (((lane >> 4) & 1) << 3);
        int atc = ((lane >> 3) & 1) << 3;
        int bn = wn*64 + (lane & 7) + (((lane >> 4) & 1) << 3);
        int bkk = ((lane >> 3) & 1) << 3;
        uint32_t ah[2][4], bhf[4][4];
        #pragma unroll
        for (int mt = 0; mt < 2; mt++) {
            int m0 = wm*32 + mt*16;
            ldsm_x4_t(ah[mt], uA[st][0] + (uint32_t)((atr*AP + m0 + atc) * 2));
        }
        #pragma unroll
        for (int p = 0; p < 4; p++)
            ldsm_x4(bhf[p], uB[st][0] + (uint32_t)(((bn + p*16)*PCH + bkk) * 2));
        #pragma unroll
        for (int mt = 0; mt < 2; mt++)
            #pragma unroll
            for (int nt = 0; nt < 8; nt++)
                mma_bf16(acc[mt][nt], ah[mt], &bhf[nt >> 1][(nt & 1) * 2]);
        {
            uint32_t al[4];
            #pragma unroll
            for (int mt = 0; mt < 2; mt++) {
                int m0 = wm*32 + mt*16;
                ldsm_x4_t(al, uA[st][1] + (uint32_t)((atr*AP + m0 + atc) * 2));
                #pragma unroll
                for (int nt = 0; nt < 8; nt++)
                    mma_bf16(acc[mt][nt], al, &bhf[nt >> 1][(nt & 1) * 2]);
            }
        }
        {
            uint32_t bl[4];
            #pragma unroll
            for (int p = 0; p < 4; p++) {
                ldsm_x4(bl, uB[st][1] + (uint32_t)(((bn + p*16)*PCH + bkk) * 2));
                #pragma unroll
                for (int mt = 0; mt < 2; mt++) {
                    mma_bf16(acc[mt][2*p    ], ah[mt], &bl[0]);
                    mma_bf16(acc[mt][2*p + 1], ah[mt], &bl[2]);
                }
            }
        }
    };

    load(0, 0); load(1, 1);
    #pragma unroll 1
    for (int c = 0; c < 16; c++) {
        if (c + 1 < 16) cp_wait1(); else cp_wait0();
        __syncthreads();
        compute(c & 1);
        __syncthreads();
        if (c + 2 < 16) load(c + 2, c & 1);
    }

    const float* bb = glu_b + (size_t)il * H2sz;
    int lrow0 = lb + wm*32 + (lane >> 2);
    #pragma unroll
    for (int mt = 0; mt < 2; mt++) {
        int l1 = lrow0 + mt*16;
        #pragma unroll
        for (int nt = 0; nt < 8; nt++) {
            int h = h0 + wn*32 + nt*4 + (lane & 3);
            float ba = bb[h];
            float bg = bb[Hsz + h];
            size_t o1 = ((size_t)b*Hsz + h)*Lsz + l1;
            size_t o2 = o1 + 8;
            float a0 = acc[mt][nt][0] + ba;
            float g0 = acc[mt][nt][1] + bg;
            float a1 = acc[mt][nt][2] + ba;
            float g1 = acc[mt][nt][3] + bg;
            g_z[o1] = fmaf(a0, 1.0f/(1.0f + expf(-g0)), g_u[o1]);
            g_z[o2] = fmaf(a1, 1.0f/(1.0f + expf(-g1)), g_u[o2]);
        }
    }
}

// ---------------------------------------------------------------------------
// LayerNorm over H (postnorm), float2-vectorized over l.
// reads g_z, writes g_u fp32 + bf16 hi/lo.
// ---------------------------------------------------------------------------
__global__ void layernorm_kernel(const float* __restrict__ ln_g,
                                 const float* __restrict__ ln_b,
                                 int il)
{
    int idx = blockIdx.x * blockDim.x + threadIdx.x;   // over B*L/2
    int b = idx >> 11;
    int l = (idx & 2047) * 2;
    const float* zb = g_z + (size_t)b*Hsz*Lsz + l;
    float sx = 0.f, sy = 0.f, s2x = 0.f, s2y = 0.f;
    #pragma unroll 4
    for (int hh = 0; hh < Hsz; hh++) {
        float2 v = *(const float2*)(zb + (size_t)hh * Lsz);
        sx += v.x; sy += v.y;
        s2x = fmaf(v.x, v.x, s2x);
        s2y = fmaf(v.y, v.y, s2y);
    }
    const float invH = 1.0f / (float)Hsz;
    float mux = sx * invH, muy = sy * invH;
    float rstdx = rsqrtf(s2x * invH - mux*mux + 1e-5f);
    float rstdy = rsqrtf(s2y * invH - muy*muy + 1e-5f);
    size_t base = (size_t)b*Hsz*Lsz + l;
    const float* gi = ln_g + il*Hsz;
    const float* bi = ln_b + il*Hsz;
    #pragma unroll 4
    for (int hh = 0; hh < Hsz; hh++) {
        float2 v = *(const float2*)(zb + (size_t)hh * Lsz);
        float gg = gi[hh], bbx = bi[hh];
        float ox = fmaf((v.x - mux) * rstdx, gg, bbx);
        float oy = fmaf((v.y - muy) * rstdy, gg, bbx);
        size_t off = base + (size_t)hh * Lsz;
        *(float2*)(g_u + off) = make_float2(ox, oy);
        __nv_bfloat16 hx, lx, hy, ly;
        split_bf16(ox, hx, lx);
        split_bf16(oy, hy, ly);
        __nv_bfloat162 vh; vh.x = hx; vh.y = hy;
        __nv_bfloat162 vl; vl.x = lx; vl.y = ly;
        *(__nv_bfloat162*)(g_uhi + off) = vh;
        *(__nv_bfloat162*)(g_ulo + off) = vl;
    }
}

// ---------------------------------------------------------------------------
// Decoder: 256-block partial reduction + tiny finisher (deterministic).
// ---------------------------------------------------------------------------
__global__ void decoder_partial(const float* __restrict__ d1w,
                                const float* __restrict__ d2w)
{
    int blk = blockIdx.x;        // 0..255
    int b = blk >> 3, s = blk & 7;
    const float* hb = g_u + ((size_t)b*Hsz + s*32)*Lsz;
    const float* w2 = d2w + s*32;
    float acc = 0.f;
    for (int i = threadIdx.x; i < 32*Lsz; i += 256) {
        int hh = i >> 12;
        int l  = i & (Lsz - 1);
        acc = fmaf(hb[(size_t)hh*Lsz + l], d1w[l] * w2[hh], acc);
    }
    __shared__ float red[256];
    red[threadIdx.x] = acc;
    __syncthreads();
    for (int st = 128; st > 0; st >>= 1) {
        if (threadIdx.x < st) red[threadIdx.x] += red[threadIdx.x + st];
        __syncthreads();
    }
    if (threadIdx.x == 0) g_dec[blk] = red[0];
}

__global__ void decoder_final(const float* __restrict__ d1b,
                              const float* __restrict__ d2w,
                              const float* __restrict__ d2b,
                              float* __restrict__ out)
{
    int b = threadIdx.x;   // 32 threads
    if (b < Bsz) {
        float v = 0.f;
        #pragma unroll
        for (int s = 0; s < 8; s++) v += g_dec[b*8 + s];
        float sw = 0.f;
        for (int hh = 0; hh < Hsz; hh++) sw += d2w[hh];
        v += d1b[0]*sw + d2b[0];
        out[b] = 1.0f / (1.0f + expf(-v));
    }
}

// ---------------------------------------------------------------------------
// Launch
// ---------------------------------------------------------------------------
extern "C" void kernel_launch(void* const* d_in, const int* in_sizes, int n_in,
                              void* d_out, int out_size)
{
    const float* x          = (const float*)d_in[0];
    const float* enc_w      = (const float*)d_in[1];
    const float* enc_b      = (const float*)d_in[2];
    const float* log_dt     = (const float*)d_in[3];
    const float* log_A_real = (const float*)d_in[4];
    const float* A_imag     = (const float*)d_in[5];
    const float* C_re       = (const float*)d_in[6];
    const float* C_im       = (const float*)d_in[7];
    const float* Dv         = (const float*)d_in[8];
    const float* glu_w      = (const float*)d_in[9];
    const float* glu_b      = (const float*)d_in[10];
    const float* ln_g       = (const float*)d_in[11];
    const float* ln_b       = (const float*)d_in[12];
    const float* dec1_w     = (const float*)d_in[13];
    const float* dec1_b     = (const float*)d_in[14];
    const float* dec2_w     = (const float*)d_in[15];
    const float* dec2_b     = (const float*)d_in[16];
    float* out = (float*)d_out;

    // 1) Precompute tables + bf16 weight splits
    precompute_kernel<<<NLs*Hsz, 128>>>(log_dt, log_A_real, A_imag, C_re, C_im);
    wconvert_kernel<<<(NLs*H2sz*Hsz)/256, 256>>>(glu_w);

    // 2) Encoder
    {
        size_t total = (size_t)Bsz*Hsz*Lsz;
        encoder_kernel<<<(unsigned)(total/256), 256>>>(x, enc_w, enc_b);
    }

    // 3) Layers
    for (int il = 0; il < NLs; il++) {
        dim3 sgrid(BCt/128, Hsz);                   // (8, 256)
        s4d_state_mma<<<sgrid, 256>>>(il);
        dim3 ogrid(BCt/128, Hsz);                   // (8, 256)
        s4d_out_mma<<<ogrid, 256>>>(Dv, il);
        dim3 ggrid(Hsz/64, (Bsz*Lsz)/128);          // (4, 1024): h0 fastest -> L2 reuse of yg
        glu_mma_kernel<<<ggrid, 256>>>(glu_b, il);
        layernorm_kernel<<<(Bsz*Lsz/2)/256, 256>>>(ln_g, ln_b, il);
    }

    // 4) Decoder
    decoder_partial<<<256, 256>>>(dec1_w, dec2_w);
    decoder_final<<<1, 32>>>(dec1_b, dec2_w, dec2_b, out);
}

// round 17
// speedup vs baseline: 2.3924x; 1.0009x over previous
#include <cuda_runtime.h>
#include <cuda_bf16.h>
#include <math.h>
#include <stdint.h>

// Problem constants
#define Bsz 32
#define Lsz 4096
#define Hsz 256
#define H2sz 512
#define NLs 4
#define N2s 32
#define Tc  128   // chunk length
#define Cc  32    // chunks per sequence (Tc*Cc == Lsz)
#define Kt  192   // output GEMM K dim: 128 (u taps) + 64 (carry re/im)
#define BCt 1024  // B*Cc
#define PCH 24    // smem tile pitch in bf16 (16 data + 8 pad; 48B rows)
#define GAP 72    // glu A-tile pitch in bf16 (64 data + 8 pad; 144B rows)

// ---------------------------------------------------------------------------
// Scratch (device globals; no runtime allocation allowed)
// ---------------------------------------------------------------------------
__device__ float  g_u [(size_t)Bsz*Hsz*Lsz];       // current hidden state h (B,H,L) fp32
__device__ float2 g_rT[(size_t)NLs*Hsz*N2s];       // r^T per mode
__device__ float  g_dec[256];                      // decoder partials
// bf16 hi/lo operands
__device__ __align__(16) __nv_bfloat16 g_uhi[(size_t)Bsz*Hsz*Lsz];     // u bf16 hi (B,H,L)
__device__ __align__(16) __nv_bfloat16 g_ulo[(size_t)Bsz*Hsz*Lsz];     // u bf16 lo
__device__ __align__(16) __nv_bfloat16 g_yghi[(size_t)Bsz*Hsz*Lsz];    // post-gelu bf16 hi (B,H,L)
__device__ __align__(16) __nv_bfloat16 g_yglo[(size_t)Bsz*Hsz*Lsz];    // post-gelu bf16 lo
__device__ __align__(16) __nv_bfloat16 g_Qthi[(size_t)NLs*Hsz*64*Tc];  // Qt[il][h][2n(+1)][j]
__device__ __align__(16) __nv_bfloat16 g_Qtlo[(size_t)NLs*Hsz*64*Tc];
__device__ __align__(16) __nv_bfloat16 g_Mthi[(size_t)NLs*Hsz*Tc*Kt];  // Mt[il][h][j][k]
__device__ __align__(16) __nv_bfloat16 g_Mtlo[(size_t)NLs*Hsz*Tc*Kt];
__device__ __align__(16) __nv_bfloat16 g_Shi[(size_t)Hsz*BCt*64];      // carries [h][bc][k]
__device__ __align__(16) __nv_bfloat16 g_Slo[(size_t)Hsz*BCt*64];
__device__ __align__(16) __nv_bfloat16 g_whi[(size_t)NLs*H2sz*Hsz];
__device__ __align__(16) __nv_bfloat16 g_wlo[(size_t)NLs*H2sz*Hsz];

// ---------------------------------------------------------------------------
// Warp-level MMA + cp.async helpers (sm_80-era, legal on plain sm_103 target)
// ---------------------------------------------------------------------------
__device__ __forceinline__ uint32_t smem_u32(const void* p) {
    uint32_t a;
    asm("{ .reg .u64 t; cvta.to.shared.u64 t, %1; cvt.u32.u64 %0, t; }" : "=r"(a) : "l"(p));
    return a;
}
__device__ __forceinline__ void ldsm_x4(uint32_t* r, uint32_t addr) {
    asm volatile("ldmatrix.sync.aligned.m8n8.x4.shared.b16 {%0,%1,%2,%3}, [%4];"
        : "=r"(r[0]), "=r"(r[1]), "=r"(r[2]), "=r"(r[3]) : "r"(addr));
}
__device__ __forceinline__ void ldsm_x4_t(uint32_t* r, uint32_t addr) {
    asm volatile("ldmatrix.sync.aligned.m8n8.x4.trans.shared.b16 {%0,%1,%2,%3}, [%4];"
        : "=r"(r[0]), "=r"(r[1]), "=r"(r[2]), "=r"(r[3]) : "r"(addr));
}
__device__ __forceinline__ void mma_bf16(float* d, const uint32_t* a, const uint32_t* b) {
    asm volatile("mma.sync.aligned.m16n8k16.row.col.f32.bf16.bf16.f32 "
        "{%0,%1,%2,%3}, {%4,%5,%6,%7}, {%8,%9}, {%0,%1,%2,%3};"
        : "+f"(d[0]), "+f"(d[1]), "+f"(d[2]), "+f"(d[3])
        : "r"(a[0]), "r"(a[1]), "r"(a[2]), "r"(a[3]), "r"(b[0]), "r"(b[1]));
}
__device__ __forceinline__ void cp_async16(uint32_t dst, const void* src) {
    asm volatile("cp.async.cg.shared.global [%0], [%1], 16;" :: "r"(dst), "l"(src));
}
__device__ __forceinline__ void cp_commit() { asm volatile("cp.async.commit_group;" ::: "memory"); }
__device__ __forceinline__ void cp_wait1()  { asm volatile("cp.async.wait_group 1;" ::: "memory"); }
__device__ __forceinline__ void cp_wait0()  { asm volatile("cp.async.wait_group 0;" ::: "memory"); }
__device__ __forceinline__ void split_bf16(float x, __nv_bfloat16& hi, __nv_bfloat16& lo) {
    hi = __float2bfloat16(x);
    lo = __float2bfloat16(x - __bfloat162float(hi));
}

// ---------------------------------------------------------------------------
// Precompute tables per (layer, h).  grid = NL*H blocks, 128 threads.
// ---------------------------------------------------------------------------
__global__ void precompute_kernel(const float* __restrict__ log_dt,
                                  const float* __restrict__ log_A_real,
                                  const float* __restrict__ A_imag,
                                  const float* __restrict__ C_re,
                                  const float* __restrict__ C_im)
{
    int ilh = blockIdx.x;
    int il = ilh >> 8;
    int h  = ilh & 255;
    __shared__ float s_dre[N2s], s_dim[N2s], s_Ckr[N2s], s_Cki[N2s];
    __shared__ float s_kc[Tc];

    int tid = threadIdx.x;
    if (tid < N2s) {
        int n = tid;
        float dt = expf(log_dt[il*Hsz + h]);
        size_t idx = ((size_t)il*Hsz + h)*N2s + n;
        float Are = -expf(log_A_real[idx]);
        float Aim = A_imag[idx];
        float dre = Are * dt, dim = Aim * dt;
        float er = expf(dre);
        float sr, cr0; sincosf(dim, &sr, &cr0);
        float rr = er * cr0, ri = er * sr;
        float nr = rr - 1.0f, ni = ri;
        float den = Are*Are + Aim*Aim;
        float qr = (nr*Are + ni*Aim)/den;
        float qi = (ni*Are - nr*Aim)/den;
        float cre = C_re[idx], cim = C_im[idx];
        s_dre[n] = dre; s_dim[n] = dim;
        s_Ckr[n] = cre*qr - cim*qi;
        s_Cki[n] = cre*qi + cim*qr;
        float eT = expf(dre * (float)Tc);
        float sT, cT; sincosf(dim * (float)Tc, &sT, &cT);
        g_rT[((size_t)il*Hsz + h)*N2s + n] = make_float2(eT*cT, eT*sT);
    }
    __syncthreads();

    int j = tid;  // 0..127
    __nv_bfloat16* Qth = g_Qthi + ((size_t)il*Hsz + h)*64*Tc;
    __nv_bfloat16* Qtl = g_Qtlo + ((size_t)il*Hsz + h)*64*Tc;
    __nv_bfloat16* Mh = g_Mthi + (((size_t)il*Hsz + h)*Tc + j)*Kt;
    __nv_bfloat16* Ml = g_Mtlo + (((size_t)il*Hsz + h)*Tc + j)*Kt;
    float ksum = 0.f;
    #pragma unroll 4
    for (int n = 0; n < N2s; n++) {
        float dre = s_dre[n], dim = s_dim[n];
        float Ckr = s_Ckr[n], Cki = s_Cki[n];
        float m1 = (float)(Tc - 1 - j);
        float e1 = expf(dre*m1);
        float s1, c1; sincosf(dim*m1, &s1, &c1);
        __nv_bfloat16 hb, lb;
        split_bf16(e1*c1, hb, lb); Qth[(2*n    )*Tc + j] = hb; Qtl[(2*n    )*Tc + j] = lb;
        split_bf16(e1*s1, hb, lb); Qth[(2*n + 1)*Tc + j] = hb; Qtl[(2*n + 1)*Tc + j] = lb;
        float m2 = (float)(j + 1);
        float e2 = expf(dre*m2);
        float s2, c2; sincosf(dim*m2, &s2, &c2);
        float pr = e2*c2, pi = e2*s2;
        float wr = Ckr*pr - Cki*pi;
        float wi = Ckr*pi + Cki*pr;
        split_bf16( 2.f*wr, hb, lb); Mh[128 + 2*n    ] = hb; Ml[128 + 2*n    ] = lb;
        split_bf16(-2.f*wi, hb, lb); Mh[128 + 2*n + 1] = hb; Ml[128 + 2*n + 1] = lb;
        float m3 = (float)j;
        float e3 = expf(dre*m3);
        float s3, c3; sincosf(dim*m3, &s3, &c3);
        ksum += Ckr*(e3*c3) - Cki*(e3*s3);
    }
    s_kc[j] = 2.f*ksum;
    __syncthreads();

    for (int k = 0; k < Tc; k++) {
        float v = (k <= j) ? s_kc[j - k] : 0.f;
        __nv_bfloat16 hb, lb;
        split_bf16(v, hb, lb);
        Mh[k] = hb; Ml[k] = lb;
    }
}

// ---------------------------------------------------------------------------
// GLU weight hi/lo bf16 split (all layers at once).
// ---------------------------------------------------------------------------
__global__ void wconvert_kernel(const float* __restrict__ glu_w)
{
    int i = blockIdx.x * 256 + threadIdx.x;
    float x = glu_w[i];
    __nv_bfloat16 hi, lo;
    split_bf16(x, hi, lo);
    g_whi[i] = hi;
    g_wlo[i] = lo;
}

// ---------------------------------------------------------------------------
// Encoder: g_u[b][h][l] = x[b][l]*enc_w[h] + enc_b[h]  (+ bf16 hi/lo copies)
// ---------------------------------------------------------------------------
__global__ void encoder_kernel(const float* __restrict__ x,
                               const float* __restrict__ ew,
                               const float* __restrict__ eb)
{
    size_t i = (size_t)blockIdx.x * blockDim.x + threadIdx.x;
    int l = (int)(i & (Lsz - 1));
    size_t bh = i >> 12;
    int hh = (int)(bh & (Hsz - 1));
    int b  = (int)(bh >> 8);
    float v = x[(size_t)b*Lsz + l]*ew[hh] + eb[hh];
    g_u[i] = v;
    __nv_bfloat16 hi, lo;
    split_bf16(v, hi, lo);
    g_uhi[i] = hi;
    g_ulo[i] = lo;
}

// ---------------------------------------------------------------------------
// S4D states on mma.sync (cp.async pipelined), fused scan + carry write-out.
// ---------------------------------------------------------------------------
#define ST_ASZ (128*PCH*2)     // 6144 B
#define ST_BSZ (64*PCH*2)      // 3072 B
#define ST_STAGE (2*ST_ASZ + 2*ST_BSZ)   // 18432
#define SSC_P 132              // scan buffer pitch (floats)

__global__ __launch_bounds__(256) void s4d_state_mma(int il)
{
    __shared__ __align__(16) char smraw[2*ST_STAGE];   // 36864; scan buf aliases
    float* Ssc = (float*)smraw;                        // [64][SSC_P] = 33792

    int tid  = threadIdx.x;
    int lane = tid & 31;
    int wid  = tid >> 5;
    int wm   = wid & 3;
    int wn   = wid >> 2;
    int bc0  = blockIdx.x * 128;
    int h    = blockIdx.y;

    uint32_t sbase = smem_u32(smraw);
    uint32_t uA[2][2], uB[2][2];
    #pragma unroll
    for (int st = 0; st < 2; st++) {
        uA[st][0] = sbase + st*ST_STAGE;
        uA[st][1] = sbase + st*ST_STAGE + ST_ASZ;
        uB[st][0] = sbase + st*ST_STAGE + 2*ST_ASZ;
        uB[st][1] = sbase + st*ST_STAGE + 2*ST_ASZ + ST_BSZ;
    }

    float acc[2][4][4];
    #pragma unroll
    for (int mt = 0; mt < 2; mt++)
        #pragma unroll
        for (int nt = 0; nt < 4; nt++)
            #pragma unroll
            for (int q = 0; q < 4; q++) acc[mt][nt][q] = 0.f;

    int r = tid >> 1, i = tid & 1;
    int bcr = bc0 + r;
    int b2 = bcr >> 5, c2 = bcr & 31;
    const __nv_bfloat16* gAhi = g_uhi + ((size_t)b2*Hsz + h)*Lsz + c2*Tc + i*8;
    const __nv_bfloat16* gAlo = g_ulo + ((size_t)b2*Hsz + h)*Lsz + c2*Tc + i*8;
    const __nv_bfloat16* gBhi = g_Qthi + ((size_t)il*Hsz + h)*64*Tc + (size_t)r*Tc + i*8;
    const __nv_bfloat16* gBlo = g_Qtlo + ((size_t)il*Hsz + h)*64*Tc + (size_t)r*Tc + i*8;
    uint32_t doff = (uint32_t)(r*PCH + i*8)*2;

    auto load = [&](int c, int st) {
        int k0 = c*16;
        cp_async16(uA[st][0] + doff, gAhi + k0);
        cp_async16(uA[st][1] + doff, gAlo + k0);
        if (tid < 128) {
            cp_async16(uB[st][0] + doff, gBhi + k0);
            cp_async16(uB[st][1] + doff, gBlo + k0);
        }
        cp_commit();
    };
    auto compute = [&](int st) {
        int acol = ((lane >> 4) << 3);
        int arow0 = wm*32 + (lane & 15);
        int bn = wn*32 + (lane & 7) + (((lane >> 4) & 1) << 3);
        int bkk = ((lane >> 3) & 1) << 3;
        uint32_t ah[2][4], bhf[2][4];
        #pragma unroll
        for (int mt = 0; mt < 2; mt++)
            ldsm_x4(ah[mt], uA[st][0] + (uint32_t)(((arow0 + mt*16)*PCH + acol) * 2));
        #pragma unroll
        for (int p = 0; p < 2; p++)
            ldsm_x4(bhf[p], uB[st][0] + (uint32_t)(((bn + p*16)*PCH + bkk) * 2));
        #pragma unroll
        for (int mt = 0; mt < 2; mt++)
            #pragma unroll
            for (int nt = 0; nt < 4; nt++)
                mma_bf16(acc[mt][nt], ah[mt], &bhf[nt >> 1][(nt & 1) * 2]);
        {
            uint32_t al[4];
            #pragma unroll
            for (int mt = 0; mt < 2; mt++) {
                ldsm_x4(al, uA[st][1] + (uint32_t)(((arow0 + mt*16)*PCH + acol) * 2));
                #pragma unroll
                for (int nt = 0; nt < 4; nt++)
                    mma_bf16(acc[mt][nt], al, &bhf[nt >> 1][(nt & 1) * 2]);
            }
        }
        {
            uint32_t bl[4];
            #pragma unroll
            for (int p = 0; p < 2; p++) {
                ldsm_x4(bl, uB[st][1] + (uint32_t)(((bn + p*16)*PCH + bkk) * 2));
                #pragma unroll
                for (int mt = 0; mt < 2; mt++) {
                    mma_bf16(acc[mt][2*p    ], ah[mt], &bl[0]);
                    mma_bf16(acc[mt][2*p + 1], ah[mt], &bl[2]);
                }
            }
        }
    };

    load(0, 0); load(1, 1);
    #pragma unroll 1
    for (int c = 0; c < 8; c++) {
        if (c + 1 < 8) cp_wait1(); else cp_wait0();
        __syncthreads();
        compute(c & 1);
        __syncthreads();
        if (c + 2 < 8) load(c + 2, c & 1);
    }

    // ---- Dump accumulators to transposed scan buffer Ssc[col][bc_local]
    #pragma unroll
    for (int mt = 0; mt < 2; mt++) {
        #pragma unroll
        for (int half = 0; half < 2; half++) {
            int rr = wm*32 + (lane >> 2) + half*8 + mt*16;
            #pragma unroll
            for (int nt = 0; nt < 4; nt++) {
                int jc = wn*32 + nt*8 + (lane & 3)*2;
                Ssc[jc*SSC_P + rr]       = acc[mt][nt][half*2 + 0];
                Ssc[(jc + 1)*SSC_P + rr] = acc[mt][nt][half*2 + 1];
            }
        }
    }
    __syncthreads();

    // ---- Inter-chunk scan
    if (tid < 128) {
        int n = tid & 31;
        int bl = tid >> 5;
        float2 rt = g_rT[((size_t)il*Hsz + h)*N2s + n];
        float xr = 0.f, xi = 0.f;
        float* Sr = &Ssc[(2*n    )*SSC_P + bl*32];
        float* Si = &Ssc[(2*n + 1)*SSC_P + bl*32];
        #pragma unroll 4
        for (int c = 0; c < Cc; c++) {
            float sr = Sr[c];
            float si = Si[c];
            Sr[c] = xr;
            Si[c] = xi;
            float nxr = fmaf(rt.x, xr, fmaf(-rt.y, xi, sr));
            float nxi = fmaf(rt.x, xi, fmaf( rt.y, xr, si));
            xr = nxr; xi = nxi;
        }
    }
    __syncthreads();

    // ---- Write carries bf16 hi/lo to g_S [h][bc][k]
    {
        int rr   = tid >> 1;
        int half = tid & 1;
        __nv_bfloat16 vh[32], vl[32];
        #pragma unroll
        for (int i2 = 0; i2 < 32; i2++) {
            int k = half*32 + i2;
            split_bf16(Ssc[k*SSC_P + rr], vh[i2], vl[i2]);
        }
        size_t off = ((size_t)h*BCt + bc0 + rr)*64 + half*32;
        #pragma unroll
        for (int i2 = 0; i2 < 4; i2++) {
            *(uint4*)(g_Shi + off + i2*8) = ((uint4*)vh)[i2];
            *(uint4*)(g_Slo + off + i2*8) = ((uint4*)vl)[i2];
        }
    }
}

// ---------------------------------------------------------------------------
// S4D output GEMM on mma.sync (cp.async pipelined, bf16 hi/lo, fp32 accum).
// D[bc=128, j=128] = Xt[128,192] . Mt[128,192]^T, K in 12 chunks of 16.
// Epilogue: yv = acc + D[h]*u, exact GELU, write bf16 hi/lo g_yg [b][h][l].
// ---------------------------------------------------------------------------
#define TL_ASZ (128*PCH*2)             // 6144 B
#define TL_STAGE (4*TL_ASZ)            // 24576

__global__ __launch_bounds__(256) void s4d_out_mma(const float* __restrict__ Dvec, int il)
{
    __shared__ __align__(16) char smraw[2*TL_STAGE];   // 49152 = 48KB

    int tid  = threadIdx.x;
    int lane = tid & 31;
    int wid  = tid >> 5;
    int wm   = wid & 3;
    int wn   = wid >> 2;
    int bc0  = blockIdx.x * 128;
    int h    = blockIdx.y;

    uint32_t sbase = smem_u32(smraw);
    uint32_t uT[2][4];
    #pragma unroll
    for (int st = 0; st < 2; st++)
        #pragma unroll
        for (int a = 0; a < 4; a++)
            uT[st][a] = sbase + st*TL_STAGE + a*TL_ASZ;

    float acc[2][8][4];
    #pragma unroll
    for (int mt = 0; mt < 2; mt++)
        #pragma unroll
        for (int nt = 0; nt < 8; nt++)
            #pragma unroll
            for (int q = 0; q < 4; q++) acc[mt][nt][q] = 0.f;

    int r = tid >> 1, i = tid & 1;
    int bcr = bc0 + r;
    int b2 = bcr >> 5, c2 = bcr & 31;
    const __nv_bfloat16* gAhi_u = g_uhi + ((size_t)b2*Hsz + h)*Lsz + c2*Tc + i*8;
    const __nv_bfloat16* gAlo_u = g_ulo + ((size_t)b2*Hsz + h)*Lsz + c2*Tc + i*8;
    const __nv_bfloat16* gAhi_s = g_Shi + ((size_t)h*BCt + bcr)*64 + i*8;
    const __nv_bfloat16* gAlo_s = g_Slo + ((size_t)h*BCt + bcr)*64 + i*8;
    const __nv_bfloat16* gBhi = g_Mthi + ((size_t)il*Hsz + h)*Tc*Kt + (size_t)r*Kt + i*8;
    const __nv_bfloat16* gBlo = g_Mtlo + ((size_t)il*Hsz + h)*Tc*Kt + (size_t)r*Kt + i*8;
    uint32_t doff = (uint32_t)(r*PCH + i*8)*2;

    auto load = [&](int c, int st) {
        int k0 = c*16;
        if (k0 < 128) {
            cp_async16(uT[st][0] + doff, gAhi_u + k0);
            cp_async16(uT[st][1] + doff, gAlo_u + k0);
        } else {
            cp_async16(uT[st][0] + doff, gAhi_s + (k0 - 128));
            cp_async16(uT[st][1] + doff, gAlo_s + (k0 - 128));
        }
        cp_async16(uT[st][2] + doff, gBhi + k0);
        cp_async16(uT[st][3] + doff, gBlo + k0);
        cp_commit();
    };
    auto compute = [&](int st) {
        int acol = ((lane >> 4) << 3);
        int arow0 = wm*32 + (lane & 15);
        int bn = wn*64 + (lane & 7) + (((lane >> 4) & 1) << 3);
        int bkk = ((lane >> 3) & 1) << 3;
        uint32_t ah[2][4], bhf[4][4];
        #pragma unroll
        for (int mt = 0; mt < 2; mt++)
            ldsm_x4(ah[mt], uT[st][0] + (uint32_t)(((arow0 + mt*16)*PCH + acol) * 2));
        #pragma unroll
        for (int p = 0; p < 4; p++)
            ldsm_x4(bhf[p], uT[st][2] + (uint32_t)(((bn + p*16)*PCH + bkk) * 2));
        #pragma unroll
        for (int mt = 0; mt < 2; mt++)
            #pragma unroll
            for (int nt = 0; nt < 8; nt++)
                mma_bf16(acc[mt][nt], ah[mt], &bhf[nt >> 1][(nt & 1) * 2]);
        {
            uint32_t al[4];
            #pragma unroll
            for (int mt = 0; mt < 2; mt++) {
                ldsm_x4(al, uT[st][1] + (uint32_t)(((arow0 + mt*16)*PCH + acol) * 2));
                #pragma unroll
                for (int nt = 0; nt < 8; nt++)
                    mma_bf16(acc[mt][nt], al, &bhf[nt >> 1][(nt & 1) * 2]);
            }
        }
        {
            uint32_t bl[4];
            #pragma unroll
            for (int p = 0; p < 4; p++) {
                ldsm_x4(bl, uT[st][3] + (uint32_t)(((bn + p*16)*PCH + bkk) * 2));
                #pragma unroll
                for (int mt = 0; mt < 2; mt++) {
                    mma_bf16(acc[mt][2*p    ], ah[mt], &bl[0]);
                    mma_bf16(acc[mt][2*p + 1], ah[mt], &bl[2]);
                }
            }
        }
    };

    load(0, 0); load(1, 1);
    #pragma unroll 1
    for (int c = 0; c < 12; c++) {
        if (c + 1 < 12) cp_wait1(); else cp_wait0();
        __syncthreads();
        compute(c & 1);
        __syncthreads();
        if (c + 2 < 12) load(c + 2, c & 1);
    }

    float Dh = Dvec[il*Hsz + h];
    int r0 = wm*32 + (lane >> 2);
    #pragma unroll
    for (int mt = 0; mt < 2; mt++) {
        #pragma unroll
        for (int half = 0; half < 2; half++) {
            int bc = bc0 + r0 + mt*16 + half*8;
            int bb2 = bc >> 5, cc2 = bc & 31;
            size_t rowbase = ((size_t)bb2*Hsz + h)*Lsz + cc2*Tc;
            #pragma unroll
            for (int nt = 0; nt < 8; nt++) {
                int j = wn*64 + nt*8 + (lane & 3)*2;
                size_t o = rowbase + j;
                float2 uu = *(const float2*)(g_u + o);
                float y0 = fmaf(Dh, uu.x, acc[mt][nt][half*2 + 0]);
                float y1 = fmaf(Dh, uu.y, acc[mt][nt][half*2 + 1]);
                y0 = 0.5f * y0 * (1.0f + erff(y0 * 0.70710678118654752f));
                y1 = 0.5f * y1 * (1.0f + erff(y1 * 0.70710678118654752f));
                __nv_bfloat16 h0b, l0b, h1b, l1b;
                split_bf16(y0, h0b, l0b);
                split_bf16(y1, h1b, l1b);
                __nv_bfloat162 vh; vh.x = h0b; vh.y = h1b;
                __nv_bfloat162 vl; vl.x = l0b; vl.y = l1b;
                *(__nv_bfloat162*)(g_yghi + o) = vh;
                *(__nv_bfloat162*)(g_yglo + o) = vl;
            }
        }
    }
}

// ---------------------------------------------------------------------------
// GLU GEMM + fused residual + LayerNorm (one CTA owns full H for 64 l-rows).
// CTA: M=64 (l), N=512 (=256 h, a/g interleaved), K=256 in 16 chunks of 16.
// 512 threads = 16 warps as 4(M:16 l) x 4(N:128).
// Epilogue: stage a*sigmoid(g) into smem [h][l] (aliases pipeline buffers),
// add residual u (coalesced), LN stats, normalize, write u fp32+bf16 hi/lo.
// ---------------------------------------------------------------------------
#define GA_SZ (16*GAP*2)                  // 2304 B
#define GB_SZ (512*PCH*2)                 // 24576 B
#define G_STAGE (2*GA_SZ + 2*GB_SZ)       // 53760
#define G_SMEM  (2*G_STAGE)               // 107520
#define ZP 65                             // z staging pitch (floats)

__global__ __launch_bounds__(512) void glu_ln_kernel(const float* __restrict__ glu_b,
                                                     const float* __restrict__ ln_g,
                                                     const float* __restrict__ ln_b,
                                                     int il)
{
    extern __shared__ __align__(16) char smraw[];
    float* zst = (float*)smraw;            // [256][ZP] = 66560 B (aliases stages, used post-GEMM)
    __shared__ float redS[8][64], redQ[8][64], s_mu[64], s_rs[64];

    int tid  = threadIdx.x;
    int lane = tid & 31;
    int wid  = tid >> 5;
    int wm   = wid & 3;         // M: 16 l each
    int wn   = wid >> 2;        // N: 128 each
    int lbase = blockIdx.x * 64;      // flat b*L + l
    int b     = lbase >> 12;
    int lb    = lbase & (Lsz - 1);

    uint32_t sbase = smem_u32(smraw);
    uint32_t uA[2][2], uB[2][2];
    #pragma unroll
    for (int st = 0; st < 2; st++) {
        uA[st][0] = sbase + st*G_STAGE;
        uA[st][1] = sbase + st*G_STAGE + GA_SZ;
        uB[st][0] = sbase + st*G_STAGE + 2*GA_SZ;
        uB[st][1] = sbase + st*G_STAGE + 2*GA_SZ + GB_SZ;
    }

    float acc[16][4];
    #pragma unroll
    for (int nt = 0; nt < 16; nt++)
        #pragma unroll
        for (int q = 0; q < 4; q++) acc[nt][q] = 0.f;

    // A loads (t<128): r = k-row (16), cu = l-unit (8 of 8)
    int arow = tid >> 3, acu = tid & 7;     // valid for tid<128
    size_t gAbase = ((size_t)b*Hsz + arow)*Lsz + lb + acu*8;   // + k0*Lsz per chunk
    uint32_t doffA = (uint32_t)(arow*GAP + acu*8)*2;
    // B loads: 1024 units over 512 threads x2
    uint32_t doffB[2];
    const __nv_bfloat16 *gBhi[2], *gBlo[2];
    #pragma unroll
    for (int s = 0; s < 2; s++) {
        int idx = tid + s*512;
        int r = idx >> 1, i = idx & 1;
        int i2 = r >> 1;
        int h2row = (r & 1) ? (256 + i2) : i2;
        gBhi[s] = g_whi + ((size_t)il*H2sz + h2row)*Hsz + i*8;
        gBlo[s] = g_wlo + ((size_t)il*H2sz + h2row)*Hsz + i*8;
        doffB[s] = (uint32_t)(r*PCH + i*8)*2;
    }

    auto load = [&](int c, int st) {
        int k0 = c*16;
        if (tid < 128) {
            size_t ga = gAbase + (size_t)k0*Lsz;
            cp_async16(uA[st][0] + doffA, g_yghi + ga);
            cp_async16(uA[st][1] + doffA, g_yglo + ga);
        }
        #pragma unroll
        for (int s = 0; s < 2; s++) {
            cp_async16(uB[st][0] + doffB[s], gBhi[s] + k0);
            cp_async16(uB[st][1] + doffB[s], gBlo[s] + k0);
        }
        cp_commit();
    };
    auto compute = [&](int st) {
        int atr = (lane & 7) + (((lane >> 4) & 1) << 3);  // k
        int atc = ((lane >> 3) & 1) << 3;                 // m offset
        int m0 = wm*16;
        int bn0 = wn*128 + (lane & 7) + (((lane >> 4) & 1) << 3);
        int bkk = ((lane >> 3) & 1) << 3;
        uint32_t ah[4], al[4];
        ldsm_x4_t(ah, uA[st][0] + (uint32_t)((atr*GAP + m0 + atc) * 2));
        ldsm_x4_t(al, uA[st][1] + (uint32_t)((atr*GAP + m0 + atc) * 2));
        // process N in two halves of 64 to cap register use
        #pragma unroll
        for (int half = 0; half < 2; half++) {
            uint32_t bhf[4][4];
            #pragma unroll
            for (int p = 0; p < 4; p++)
                ldsm_x4(bhf[p], uB[st][0] + (uint32_t)(((bn0 + half*64 + p*16)*PCH + bkk) * 2));
            #pragma unroll
            for (int nt = 0; nt < 8; nt++) {
                mma_bf16(acc[half*8 + nt], ah, &bhf[nt >> 1][(nt & 1) * 2]);
                mma_bf16(acc[half*8 + nt], al, &bhf[nt >> 1][(nt & 1) * 2]);
            }
            uint32_t bl[4];
            #pragma unroll
            for (int p = 0; p < 4; p++) {
                ldsm_x4(bl, uB[st][1] + (uint32_t)(((bn0 + half*64 + p*16)*PCH + bkk) * 2));
                mma_bf16(acc[half*8 + 2*p    ], ah, &bl[0]);
                mma_bf16(acc[half*8 + 2*p + 1], ah, &bl[2]);
            }
        }
    };

    load(0, 0); load(1, 1);
    #pragma unroll 1
    for (int c = 0; c < 16; c++) {
        if (c + 1 < 16) cp_wait1(); else cp_wait0();
        __syncthreads();
        compute(c & 1);
        __syncthreads();
        if (c + 2 < 16) load(c + 2, c & 1);
    }

    // ---- Stage a*sigmoid(g) into zst[h][l_local]
    {
        const float* bb = glu_b + (size_t)il * H2sz;
        int l0 = wm*16 + (lane >> 2);
        #pragma unroll
        for (int nt = 0; nt < 16; nt++) {
            int h = wn*64 + nt*4 + (lane & 3);
            float ba = bb[h];
            float bg = bb[Hsz + h];
            float a0 = acc[nt][0] + ba;
            float g0 = acc[nt][1] + bg;
            float a1 = acc[nt][2] + ba;
            float g1 = acc[nt][3] + bg;
            zst[h*ZP + l0]     = a0 * (1.0f/(1.0f + expf(-g0)));
            zst[h*ZP + l0 + 8] = a1 * (1.0f/(1.0f + expf(-g1)));
        }
    }
    __syncthreads();

    // ---- Pass 1: add residual u (coalesced), accumulate LN stats
    {
        int l = tid & 63;
        int hg = tid >> 6;      // 0..7, 32 h each
        float s = 0.f, q = 0.f;
        #pragma unroll 4
        for (int h = hg*32; h < hg*32 + 32; h++) {
            float v = zst[h*ZP + l] + g_u[((size_t)b*Hsz + h)*Lsz + lb + l];
            zst[h*ZP + l] = v;
            s += v; q = fmaf(v, v, q);
        }
        redS[hg][l] = s;
        redQ[hg][l] = q;
    }
    __syncthreads();
    if (tid < 64) {
        float s = 0.f, q = 0.f;
        #pragma unroll
        for (int g = 0; g < 8; g++) { s += redS[g][tid]; q += redQ[g][tid]; }
        float mu = s * (1.0f/(float)Hsz);
        s_mu[tid] = mu;
        s_rs[tid] = rsqrtf(q * (1.0f/(float)Hsz) - mu*mu + 1e-5f);
    }
    __syncthreads();

    // ---- Pass 2: normalize, write u fp32 + bf16 hi/lo (coalesced)
    {
        int l = tid & 63;
        int hg = tid >> 6;
        float mu = s_mu[l], rs = s_rs[l];
        const float* gi = ln_g + il*Hsz;
        const float* bi = ln_b + il*Hsz;
        #pragma unroll 4
        for (int h = hg*32; h < hg*32 + 32; h++) {
            float o = fmaf((zst[h*ZP + l] - mu) * rs, __ldg(gi + h), __ldg(bi + h));
            size_t off = ((size_t)b*Hsz + h)*Lsz + lb + l;
            g_u[off] = o;
            __nv_bfloat16 hi, lo;
            split_bf16(o, hi, lo);
            g_uhi[off] = hi;
            g_ulo[off] = lo;
        }
    }
}

// ---------------------------------------------------------------------------
// Decoder: 256-block partial reduction + tiny finisher (deterministic).
// ---------------------------------------------------------------------------
__global__ void decoder_partial(const float* __restrict__ d1w,
                                const float* __restrict__ d2w)
{
    int blk = blockIdx.x;        // 0..255
    int b = blk >> 3, s = blk & 7;
    const float* hb = g_u + ((size_t)b*Hsz + s*32)*Lsz;
    const float* w2 = d2w + s*32;
    float acc = 0.f;
    for (int i = threadIdx.x; i < 32*Lsz; i += 256) {
        int hh = i >> 12;
        int l  = i & (Lsz - 1);
        acc = fmaf(hb[(size_t)hh*Lsz + l], d1w[l] * w2[hh], acc);
    }
    __shared__ float red[256];
    red[threadIdx.x] = acc;
    __syncthreads();
    for (int st = 128; st > 0; st >>= 1) {
        if (threadIdx.x < st) red[threadIdx.x] += red[threadIdx.x + st];
        __syncthreads();
    }
    if (threadIdx.x == 0) g_dec[blk] = red[0];
}

__global__ void decoder_final(const float* __restrict__ d1b,
                              const float* __restrict__ d2w,
                              const float* __restrict__ d2b,
                              float* __restrict__ out)
{
    int b = threadIdx.x;   // 32 threads
    if (b < Bsz) {
        float v = 0.f;
        #pragma unroll
        for (int s = 0; s < 8; s++) v += g_dec[b*8 + s];
        float sw = 0.f;
        for (int hh = 0; hh < Hsz; hh++) sw += d2w[hh];
        v += d1b[0]*sw + d2b[0];
        out[b] = 1.0f / (1.0f + expf(-v));
    }
}

// ---------------------------------------------------------------------------
// Launch
// ---------------------------------------------------------------------------
extern "C" void kernel_launch(void* const* d_in, const int* in_sizes, int n_in,
                              void* d_out, int out_size)
{
    const float* x          = (const float*)d_in[0];
    const float* enc_w      = (const float*)d_in[1];
    const float* enc_b      = (const float*)d_in[2];
    const float* log_dt     = (const float*)d_in[3];
    const float* log_A_real = (const float*)d_in[4];
    const float* A_imag     = (const float*)d_in[5];
    const float* C_re       = (const float*)d_in[6];
    const float* C_im       = (const float*)d_in[7];
    const float* Dv         = (const float*)d_in[8];
    const float* glu_w      = (const float*)d_in[9];
    const float* glu_b      = (const float*)d_in[10];
    const float* ln_g       = (const float*)d_in[11];
    const float* ln_b       = (const float*)d_in[12];
    const float* dec1_w     = (const float*)d_in[13];
    const float* dec1_b     = (const float*)d_in[14];
    const float* dec2_w     = (const float*)d_in[15];
    const float* dec2_b     = (const float*)d_in[16];
    float* out = (float*)d_out;

    // idempotent attribute set (host-side, no allocation, graph-safe)
    cudaFuncSetAttribute(glu_ln_kernel, cudaFuncAttributeMaxDynamicSharedMemorySize, G_SMEM);

    // 1) Precompute tables + bf16 weight splits
    precompute_kernel<<<NLs*Hsz, 128>>>(log_dt, log_A_real, A_imag, C_re, C_im);
    wconvert_kernel<<<(NLs*H2sz*Hsz)/256, 256>>>(glu_w);

    // 2) Encoder
    {
        size_t total = (size_t)Bsz*Hsz*Lsz;
        encoder_kernel<<<(unsigned)(total/256), 256>>>(x, enc_w, enc_b);
    }

    // 3) Layers
    for (int il = 0; il < NLs; il++) {
        dim3 sgrid(BCt/128, Hsz);                   // (8, 256)
        s4d_state_mma<<<sgrid, 256>>>(il);
        dim3 ogrid(BCt/128, Hsz);                   // (8, 256)
        s4d_out_mma<<<ogrid, 256>>>(Dv, il);
        glu_ln_kernel<<<(Bsz*Lsz)/64, 512, G_SMEM>>>(glu_b, ln_g, ln_b, il);
    }

    // 4) Decoder
    decoder_partial<<<256, 256>>>(dec1_w, dec2_w);
    decoder_final<<<1, 32>>>(dec1_b, dec2_w, dec2_b, out);
}